// round 12
// baseline (speedup 1.0000x reference)
#include <cuda_runtime.h>
#include <cuda_bf16.h>
#include <cstdint>

#define D   512
#define SEQ 1024
#define BB  4
#define NH  8
#define NL  6
#define FFD 2048
#define VOC 512
#define TOK (BB*SEQ)   // 4096
#define DD  (D*D)

// weight scratch offsets (element counts into g_wh/g_wl)
#define OFF_QKV 0                          // per layer: [wq; wk; wv] = 3*DD
#define OFF_WO  (18*DD)
#define OFF_W1  (24*DD)
#define OFF_W2  (OFF_W1 + 6*FFD*D)
#define OFF_LM  (OFF_W2 + 6*D*FFD)
#define W_TOTAL (OFF_LM + VOC*D)

// ---------------- device scratch (no allocations allowed) ----------------
__device__ float g_x[TOK*D];               // residual stream (fp32)
__device__ float g_t[TOK*D];               // gemm temp (fp32)
__device__ float g_bcat[NL*3*D];           // concat qkv bias
__device__ __nv_bfloat16 g_xh[TOK*D],  g_xl[TOK*D];    // residual hi/lo
__device__ __nv_bfloat16 g_qh[TOK*D],  g_ql[TOK*D];    // Q hi/lo
__device__ __nv_bfloat16 g_kh[TOK*D],  g_kl[TOK*D];    // K hi/lo
__device__ __nv_bfloat16 g_vh[TOK*D],  g_vl[TOK*D];    // V hi/lo
__device__ __nv_bfloat16 g_oh[TOK*D],  g_ol[TOK*D];    // attn out hi/lo
__device__ __nv_bfloat16 g_fh[TOK*FFD], g_fl[TOK*FFD]; // ffn hidden hi/lo
__device__ __nv_bfloat16 g_wh[W_TOTAL], g_wl[W_TOTAL]; // weights hi/lo
__device__ int g_idmode;

// ---------------- helpers ----------------
__device__ __forceinline__ uint32_t smem_u32(const void* p) {
    uint32_t a;
    asm("{ .reg .u64 t; cvta.to.shared.u64 t, %1; cvt.u32.u64 %0, t; }"
        : "=r"(a) : "l"(p));
    return a;
}
__device__ __forceinline__ void ldsm4(uint32_t* r, uint32_t addr) {
    asm volatile("ldmatrix.sync.aligned.m8n8.x4.shared.b16 {%0,%1,%2,%3}, [%4];"
                 : "=r"(r[0]), "=r"(r[1]), "=r"(r[2]), "=r"(r[3]) : "r"(addr));
}
__device__ __forceinline__ void ldsm4t(uint32_t* r, uint32_t addr) {
    asm volatile("ldmatrix.sync.aligned.m8n8.x4.trans.shared.b16 {%0,%1,%2,%3}, [%4];"
                 : "=r"(r[0]), "=r"(r[1]), "=r"(r[2]), "=r"(r[3]) : "r"(addr));
}
__device__ __forceinline__ void mma_bf16(float* d, const uint32_t* a,
                                         const uint32_t* b) {
    asm volatile("mma.sync.aligned.m16n8k16.row.col.f32.bf16.bf16.f32 "
                 "{%0,%1,%2,%3}, {%4,%5,%6,%7}, {%8,%9}, {%0,%1,%2,%3};"
                 : "+f"(d[0]), "+f"(d[1]), "+f"(d[2]), "+f"(d[3])
                 : "r"(a[0]), "r"(a[1]), "r"(a[2]), "r"(a[3]),
                   "r"(b[0]), "r"(b[1]));
}
#define CPA(dst, src) \
    asm volatile("cp.async.ca.shared.global [%0], [%1], 16;" :: "r"(dst), "l"(src))
#define CPC()  asm volatile("cp.async.commit_group;" ::: "memory")
#define CPW0() asm volatile("cp.async.wait_group 0;" ::: "memory")

__device__ __forceinline__ uint32_t pack_hi(float a, float b) {
    return (uint32_t)__bfloat16_as_ushort(__float2bfloat16(a)) |
           ((uint32_t)__bfloat16_as_ushort(__float2bfloat16(b)) << 16);
}
__device__ __forceinline__ uint32_t pack_lo(float a, float b) {
    float ra = a - __bfloat162float(__float2bfloat16(a));
    float rb = b - __bfloat162float(__float2bfloat16(b));
    return (uint32_t)__bfloat16_as_ushort(__float2bfloat16(ra)) |
           ((uint32_t)__bfloat16_as_ushort(__float2bfloat16(rb)) << 16);
}
// fast exp: 2^(x*log2e) via 5-FMA poly + exponent bit-stuff (no MUFU)
__device__ __forceinline__ float fexp(float x) {
    x = fmaxf(x, -80.0f);
    float t = x * 1.4426950408889634f;
    float fi = rintf(t);
    float f = t - fi;
    float p =              1.3333558146e-3f;
    p = fmaf(p, f, 9.6180209764e-3f);
    p = fmaf(p, f, 5.5504108664e-2f);
    p = fmaf(p, f, 2.4022650695e-1f);
    p = fmaf(p, f, 6.9314718056e-1f);
    p = fmaf(p, f, 1.0f);
    return __int_as_float(((int)fi + 127) << 23) * p;
}

// ---- single fused weight conversion: all 7 tensors, one launch ----------
__global__ void conv_all(const float* __restrict__ wq, const float* __restrict__ wk,
                         const float* __restrict__ wv, const float* __restrict__ wo,
                         const float* __restrict__ w1, const float* __restrict__ w2,
                         const float* __restrict__ lmw)
{
    long i = ((long)blockIdx.x * 256 + threadIdx.x) * 4;
    const float* src;
    size_t d;
    if (i < 6L*DD) {
        long j = i;  long l = j / DD, r = j - l * DD;
        src = wq + j;  d = (size_t)l * 3 * DD + r;
    } else if (i < 12L*DD) {
        long j = i - 6L*DD;  long l = j / DD, r = j - l * DD;
        src = wk + j;  d = (size_t)l * 3 * DD + DD + r;
    } else if (i < 18L*DD) {
        long j = i - 12L*DD;  long l = j / DD, r = j - l * DD;
        src = wv + j;  d = (size_t)l * 3 * DD + 2 * DD + r;
    } else if (i < 24L*DD) {
        long j = i - 18L*DD;  src = wo + j;  d = OFF_WO + j;
    } else if (i < 24L*DD + 6L*FFD*D) {
        long j = i - 24L*DD;  src = w1 + j;  d = OFF_W1 + j;
    } else if (i < 24L*DD + 12L*FFD*D) {
        long j = i - (24L*DD + 6L*FFD*D);  src = w2 + j;  d = OFF_W2 + j;
    } else {
        long j = i - (24L*DD + 12L*FFD*D);  src = lmw + j;  d = OFF_LM + j;
    }
    float4 v = *(const float4*)src;
    *(uint32_t*)&g_wh[d]     = pack_hi(v.x, v.y);
    *(uint32_t*)&g_wh[d + 2] = pack_hi(v.z, v.w);
    *(uint32_t*)&g_wl[d]     = pack_lo(v.x, v.y);
    *(uint32_t*)&g_wl[d + 2] = pack_lo(v.z, v.w);
}

// concat qkv biases into g_bcat[l][1536]
__global__ void bcat_kernel(const float* __restrict__ bq,
                            const float* __restrict__ bk,
                            const float* __restrict__ bv)
{
    int i = blockIdx.x * 256 + threadIdx.x;
    if (i >= NL * 3 * D) return;
    int l = i / (3 * D), r = i % (3 * D);
    int part = r >> 9, d = r & 511;
    const float* s = part == 0 ? bq : part == 1 ? bk : bv;
    g_bcat[i] = s[l * D + d];
}

// ---------------- input_ids dtype detection ----------------
__global__ void detect_ids_kernel(const int* __restrict__ p) {
    __shared__ int any;
    if (threadIdx.x == 0) any = 0;
    __syncthreads();
    int loc = 0;
    for (int i = threadIdx.x; i < 2048; i += blockDim.x) loc |= p[2*i + 1];
    if (loc) atomicOr(&any, 1);
    __syncthreads();
    if (threadIdx.x == 0) g_idmode = any ? 1 : 0;
}

// ---------------- embedding + positional encoding (fp32 + hi/lo) -------
__global__ void embed_kernel(const int* __restrict__ ids,
                             const float* __restrict__ emb) {
    int bs = blockIdx.x;
    int s  = bs & (SEQ - 1);
    int id = g_idmode ? ids[bs] : ids[2*bs];
    const float* e = emb + (size_t)id * D;
    const float c = -9.210340371976184f / 512.0f;
    const int d0 = threadIdx.x * 4;
    float v[4];
    #pragma unroll
    for (int j = 0; j < 4; j++) {
        int d = d0 + j;
        float ang = (float)s * expf(c * (float)(d & ~1));
        float pe  = (d & 1) ? cosf(ang) : sinf(ang);
        v[j] = e[d] * 22.627416997969522f + pe;
    }
    const size_t off = (size_t)bs * D + d0;
    *(float4*)&g_x[off] = make_float4(v[0], v[1], v[2], v[3]);
    *(uint32_t*)&g_xh[off]     = pack_hi(v[0], v[1]);
    *(uint32_t*)&g_xh[off + 2] = pack_hi(v[2], v[3]);
    *(uint32_t*)&g_xl[off]     = pack_lo(v[0], v[1]);
    *(uint32_t*)&g_xl[off + 2] = pack_lo(v[2], v[3]);
}

// =====================================================================
// bf16 tensor-core GEMM 128x128 (R9 baseline; N=512 shapes).
// =====================================================================
__device__ __forceinline__ void load_chunk128(
    uint32_t sbuf,
    const __nv_bfloat16* __restrict__ Ah, const __nv_bfloat16* __restrict__ Al,
    const __nv_bfloat16* __restrict__ Wh, const __nv_bfloat16* __restrict__ Wl,
    int m0, int n0, int K, int kc, int tid)
{
    #pragma unroll
    for (int t = 0; t < 4; t++) {
        int s = tid + t * 256;
        int reg = s >> 9;
        int row = (s >> 2) & 127;
        int seg = s & 3;
        uint32_t dst = sbuf + reg * 10240 + row * 80 + seg * 16;
        const __nv_bfloat16* src = (reg ? Al : Ah) + (size_t)(m0 + row) * K + kc + seg * 8;
        CPA(dst, src);
    }
    #pragma unroll
    for (int t = 0; t < 4; t++) {
        int s = tid + t * 256;
        int reg = s >> 9;
        int row = (s >> 2) & 127;
        int seg = s & 3;
        uint32_t dst = sbuf + 20480 + reg * 10240 + row * 80 + seg * 16;
        const __nv_bfloat16* src = (reg ? Wl : Wh) + (size_t)(n0 + row) * K + kc + seg * 8;
        CPA(dst, src);
    }
}

__global__ void __launch_bounds__(256, 2) gemm_bf(
    const __nv_bfloat16* __restrict__ Ah, const __nv_bfloat16* __restrict__ Al,
    const __nv_bfloat16* __restrict__ Wh, const __nv_bfloat16* __restrict__ Wl,
    const float* __restrict__ bias, float* __restrict__ C,
    __nv_bfloat16* __restrict__ Ch, __nv_bfloat16* __restrict__ Cl,
    int M, int N, int K, int relu)
{
    extern __shared__ char sm[];
    const uint32_t smb = smem_u32(sm);
    constexpr int BUFSZ = 40960;
    const int tid = threadIdx.x, wid = tid >> 5, lane = tid & 31;
    const int wm = wid >> 2;
    const int wn = wid & 3;
    const int m0 = blockIdx.y << 7;
    const int n0 = blockIdx.x << 7;
    const int a_row = lane & 15,  a_kb = lane & 16;
    const int b_row = ((lane >> 4) << 3) + (lane & 7), b_kb = ((lane >> 3) & 1) << 4;

    float acc[4][4][4];
    #pragma unroll
    for (int i = 0; i < 4; i++)
        #pragma unroll
        for (int j = 0; j < 4; j++)
            #pragma unroll
            for (int t = 0; t < 4; t++) acc[i][j][t] = 0.0f;

    const int nch = K >> 5;
    load_chunk128(smb, Ah, Al, Wh, Wl, m0, n0, K, 0, tid);
    CPC();
    for (int c = 0; c < nch; c++) {
        CPW0();
        __syncthreads();
        if (c + 1 < nch) {
            load_chunk128(smb + ((c + 1) & 1) * BUFSZ, Ah, Al, Wh, Wl,
                          m0, n0, K, (c + 1) << 5, tid);
            CPC();
        }
        const uint32_t ab = smb + (c & 1) * BUFSZ;
        const uint32_t wb = ab + 20480;
        #pragma unroll
        for (int ks = 0; ks < 2; ks++) {
            const int kbyte = ks * 32;
            uint32_t Bh[2][4], Bl[2][4];
            #pragma unroll
            for (int ng = 0; ng < 2; ng++) {
                const uint32_t roff = (wn*32 + ng*16 + b_row) * 80 + kbyte + b_kb;
                ldsm4(Bh[ng], wb + roff);
                ldsm4(Bl[ng], wb + 10240 + roff);
            }
            #pragma unroll
            for (int mt = 0; mt < 4; mt++) {
                uint32_t Af[4], Alf[4];
                const uint32_t aoff = (wm*64 + mt*16 + a_row) * 80 + kbyte + a_kb;
                ldsm4(Af,  ab + aoff);
                ldsm4(Alf, ab + 10240 + aoff);
                #pragma unroll
                for (int ng = 0; ng < 2; ng++)
                    #pragma unroll
                    for (int hf = 0; hf < 2; hf++) {
                        float* d = acc[mt][ng*2 + hf];
                        mma_bf16(d, Af,  Bh[ng] + hf*2);
                        mma_bf16(d, Alf, Bh[ng] + hf*2);
                        mma_bf16(d, Af,  Bl[ng] + hf*2);
                    }
            }
        }
        __syncthreads();
    }

    const int g = lane >> 2, tg = lane & 3;
    #pragma unroll
    for (int mt = 0; mt < 4; mt++) {
        #pragma unroll
        for (int nt = 0; nt < 4; nt++) {
            const int row = m0 + wm*64 + mt*16 + g;
            const int col = n0 + wn*32 + nt*8 + tg*2;
            float b0 = bias ? bias[col]     : 0.0f;
            float b1 = bias ? bias[col + 1] : 0.0f;
            float v0 = acc[mt][nt][0] + b0, v1 = acc[mt][nt][1] + b1;
            float v2 = acc[mt][nt][2] + b0, v3 = acc[mt][nt][3] + b1;
            if (relu) {
                v0 = fmaxf(v0, 0.f); v1 = fmaxf(v1, 0.f);
                v2 = fmaxf(v2, 0.f); v3 = fmaxf(v3, 0.f);
            }
            const size_t o0 = (size_t)row * N + col;
            const size_t o1 = (size_t)(row + 8) * N + col;
            if (C) {
                *(float2*)&C[o0] = make_float2(v0, v1);
                *(float2*)&C[o1] = make_float2(v2, v3);
            }
            if (Ch) {
                *(uint32_t*)&Ch[o0] = pack_hi(v0, v1);
                *(uint32_t*)&Ch[o1] = pack_hi(v2, v3);
                *(uint32_t*)&Cl[o0] = pack_lo(v0, v1);
                *(uint32_t*)&Cl[o1] = pack_lo(v2, v3);
            }
        }
    }
}

// =====================================================================
// bf16 tensor-core GEMM 128x256, 512 threads (big-N shapes: QKV, FFN1).
// Traffic factor 3/256 (vs 4/256 at 128x128) -> compute-bound.
// QKV mode: KH!=null -> per-CTA output select, store stride 512.
// smem: stage = A 2x10240 + W 2x20480 = 61440; 2 stages = 122880 (1 CTA/SM).
// =====================================================================
__device__ __forceinline__ void load_chunk256(
    uint32_t sbuf,
    const __nv_bfloat16* __restrict__ Ah, const __nv_bfloat16* __restrict__ Al,
    const __nv_bfloat16* __restrict__ Wh, const __nv_bfloat16* __restrict__ Wl,
    int m0, int n0, int K, int kc, int tid)
{
    #pragma unroll
    for (int t = 0; t < 2; t++) {                  // A: 2 x 128 x 4
        int s = tid + t * 512;
        int reg = s >> 9;
        int row = (s >> 2) & 127;
        int seg = s & 3;
        uint32_t dst = sbuf + reg * 10240 + row * 80 + seg * 16;
        const __nv_bfloat16* src = (reg ? Al : Ah) + (size_t)(m0 + row) * K + kc + seg * 8;
        CPA(dst, src);
    }
    #pragma unroll
    for (int t = 0; t < 4; t++) {                  // W: 2 x 256 x 4
        int s = tid + t * 512;
        int reg = s >> 10;
        int row = (s >> 2) & 255;
        int seg = s & 3;
        uint32_t dst = sbuf + 20480 + reg * 20480 + row * 80 + seg * 16;
        const __nv_bfloat16* src = (reg ? Wl : Wh) + (size_t)(n0 + row) * K + kc + seg * 8;
        CPA(dst, src);
    }
}

__global__ void __launch_bounds__(512, 1) gemm_wide(
    const __nv_bfloat16* __restrict__ Ah, const __nv_bfloat16* __restrict__ Al,
    const __nv_bfloat16* __restrict__ Wh, const __nv_bfloat16* __restrict__ Wl,
    const float* __restrict__ bias, float* __restrict__ C,
    __nv_bfloat16* __restrict__ Ch, __nv_bfloat16* __restrict__ Cl,
    __nv_bfloat16* __restrict__ KH, __nv_bfloat16* __restrict__ KL,
    __nv_bfloat16* __restrict__ VH, __nv_bfloat16* __restrict__ VL,
    int M, int N, int K, int relu)
{
    extern __shared__ char sm[];
    const uint32_t smb = smem_u32(sm);
    constexpr int BUFSZ = 61440;
    const int tid = threadIdx.x, wid = tid >> 5, lane = tid & 31;
    const int wm = wid >> 3;          // 0..1 -> m offset 64*wm
    const int wn = wid & 7;           // 0..7 -> n offset 32*wn
    const int m0 = blockIdx.y << 7;
    const int n0 = blockIdx.x << 8;
    const int a_row = lane & 15,  a_kb = lane & 16;
    const int b_row = ((lane >> 4) << 3) + (lane & 7), b_kb = ((lane >> 3) & 1) << 4;

    float acc[4][4][4];
    #pragma unroll
    for (int i = 0; i < 4; i++)
        #pragma unroll
        for (int j = 0; j < 4; j++)
            #pragma unroll
            for (int t = 0; t < 4; t++) acc[i][j][t] = 0.0f;

    const int nch = K >> 5;
    load_chunk256(smb, Ah, Al, Wh, Wl, m0, n0, K, 0, tid);
    CPC();
    for (int c = 0; c < nch; c++) {
        CPW0();
        __syncthreads();
        if (c + 1 < nch) {
            load_chunk256(smb + ((c + 1) & 1) * BUFSZ, Ah, Al, Wh, Wl,
                          m0, n0, K, (c + 1) << 5, tid);
            CPC();
        }
        const uint32_t ab = smb + (c & 1) * BUFSZ;
        const uint32_t wb = ab + 20480;
        #pragma unroll
        for (int ks = 0; ks < 2; ks++) {
            const int kbyte = ks * 32;
            uint32_t Bh[2][4], Bl[2][4];
            #pragma unroll
            for (int ng = 0; ng < 2; ng++) {
                const uint32_t roff = (wn*32 + ng*16 + b_row) * 80 + kbyte + b_kb;
                ldsm4(Bh[ng], wb + roff);
                ldsm4(Bl[ng], wb + 20480 + roff);
            }
            #pragma unroll
            for (int mt = 0; mt < 4; mt++) {
                uint32_t Af[4], Alf[4];
                const uint32_t aoff = (wm*64 + mt*16 + a_row) * 80 + kbyte + a_kb;
                ldsm4(Af,  ab + aoff);
                ldsm4(Alf, ab + 10240 + aoff);
                #pragma unroll
                for (int ng = 0; ng < 2; ng++)
                    #pragma unroll
                    for (int hf = 0; hf < 2; hf++) {
                        float* d = acc[mt][ng*2 + hf];
                        mma_bf16(d, Af,  Bh[ng] + hf*2);
                        mma_bf16(d, Alf, Bh[ng] + hf*2);
                        mma_bf16(d, Af,  Bl[ng] + hf*2);
                    }
            }
        }
        __syncthreads();
    }

    // epilogue (per-CTA output select for fused QKV)
    __nv_bfloat16 *oh_ = Ch, *ol_ = Cl;
    int nst = N, nbase = n0;
    if (KH) {
        const int part = n0 >> 9;
        if (part == 1)      { oh_ = KH; ol_ = KL; }
        else if (part == 2) { oh_ = VH; ol_ = VL; }
        nbase = n0 & 511;
        nst = 512;
    }
    const int g = lane >> 2, tg = lane & 3;
    #pragma unroll
    for (int mt = 0; mt < 4; mt++) {
        #pragma unroll
        for (int nt = 0; nt < 4; nt++) {
            const int row  = m0 + wm*64 + mt*16 + g;
            const int colb = n0 + wn*32 + nt*8 + tg*2;
            const int cols = nbase + wn*32 + nt*8 + tg*2;
            float b0 = bias ? bias[colb]     : 0.0f;
            float b1 = bias ? bias[colb + 1] : 0.0f;
            float v0 = acc[mt][nt][0] + b0, v1 = acc[mt][nt][1] + b1;
            float v2 = acc[mt][nt][2] + b0, v3 = acc[mt][nt][3] + b1;
            if (relu) {
                v0 = fmaxf(v0, 0.f); v1 = fmaxf(v1, 0.f);
                v2 = fmaxf(v2, 0.f); v3 = fmaxf(v3, 0.f);
            }
            const size_t o0 = (size_t)row * nst + cols;
            const size_t o1 = (size_t)(row + 8) * nst + cols;
            if (C) {
                *(float2*)&C[o0] = make_float2(v0, v1);
                *(float2*)&C[o1] = make_float2(v2, v3);
            }
            if (oh_) {
                *(uint32_t*)&oh_[o0] = pack_hi(v0, v1);
                *(uint32_t*)&oh_[o1] = pack_hi(v2, v3);
                *(uint32_t*)&ol_[o0] = pack_lo(v0, v1);
                *(uint32_t*)&ol_[o1] = pack_lo(v2, v3);
            }
        }
    }
}

// =====================================================================
// Tensor-core flash attention (causal), double-buffered K/V pipeline.
// =====================================================================
#define KVB(i) ((i) * 36864)
#define AAM    73728
#define ASME   (AAM + 512)

__global__ void __launch_bounds__(256) attn_tc(
    const __nv_bfloat16* __restrict__ Qh, const __nv_bfloat16* __restrict__ Ql,
    const __nv_bfloat16* __restrict__ Kh, const __nv_bfloat16* __restrict__ Kl,
    const __nv_bfloat16* __restrict__ Vh, const __nv_bfloat16* __restrict__ Vl,
    const int* __restrict__ amask,
    __nv_bfloat16* __restrict__ Oh, __nv_bfloat16* __restrict__ Ol)
{
    extern __shared__ char sm[];
    const uint32_t smb = smem_u32(sm);
    int* am_s = (int*)(sm + AAM);              // [2][64]
    const int qt = blockIdx.x, bh = blockIdx.y;
    const int b = bh >> 3, h = bh & 7;
    const int tid = threadIdx.x, wid = tid >> 5, lane = tid & 31;
    const int g = lane >> 2, tg = lane & 3;
    const size_t base = (size_t)b * SEQ * D + h * 64;
    const int q0 = qt * 128;
    const int a_row = lane & 15, a_kb = lane & 16;
    const int b_row = ((lane >> 4) << 3) + (lane & 7), b_kb = ((lane >> 3) & 1) << 4;
    const int v_row = (((lane >> 3) & 1) << 3) + (lane & 7), v_byte = (lane >> 4) << 4;

    #pragma unroll
    for (int t = 0; t < 8; t++) {
        int s = tid + t * 256;
        int reg = s >> 10, row = (s >> 3) & 127, seg = s & 7;
        uint32_t dst = smb + KVB(1) + reg * 18432 + row * 144 + seg * 16;
        const __nv_bfloat16* src = (reg ? Ql : Qh) + base + (size_t)(q0 + row) * D + seg * 8;
        CPA(dst, src);
    }
    CPC(); CPW0();
    __syncthreads();
    uint32_t qhf[4][4], qlf[4][4];
    #pragma unroll
    for (int ks = 0; ks < 4; ks++) {
        const uint32_t off = (wid*16 + a_row) * 144 + ks*32 + a_kb;
        ldsm4(qhf[ks], smb + KVB(1) + off);
        ldsm4(qlf[ks], smb + KVB(1) + 18432 + off);
    }

    float m_i[2] = {-1e30f, -1e30f}, l_i[2] = {0.f, 0.f};
    float o_acc[8][4];
    #pragma unroll
    for (int i = 0; i < 8; i++)
        #pragma unroll
        for (int j = 0; j < 4; j++) o_acc[i][j] = 0.f;

    const int row0 = q0 + wid*16 + g;
    const int ktmax = 2*qt + 1;

    {
        const uint32_t kv = smb + KVB(0);
        #pragma unroll
        for (int t = 0; t < 4; t++) {
            int s = tid + t * 256;
            int reg = s >> 9, row = (s >> 3) & 63, seg = s & 7;
            CPA(kv + reg * 9216 + row * 144 + seg * 16,
                (reg ? Kl : Kh) + base + (size_t)row * D + seg * 8);
        }
        #pragma unroll
        for (int t = 0; t < 4; t++) {
            int s = tid + t * 256;
            int reg = s >> 9, row = (s >> 3) & 63, seg = s & 7;
            CPA(kv + 18432 + reg * 9216 + row * 144 + seg * 16,
                (reg ? Vl : Vh) + base + (size_t)row * D + seg * 8);
        }
        if (tid < 64) am_s[tid] = amask[b * SEQ + tid];
        CPC();
    }

    for (int kt = 0; kt <= ktmax; kt++) {
        CPW0();
        __syncthreads();
        if (kt + 1 <= ktmax) {
            const uint32_t kv = smb + KVB((kt + 1) & 1);
            const size_t kb = base + (size_t)((kt + 1) * 64) * D;
            #pragma unroll
            for (int t = 0; t < 4; t++) {
                int s = tid + t * 256;
                int reg = s >> 9, row = (s >> 3) & 63, seg = s & 7;
                CPA(kv + reg * 9216 + row * 144 + seg * 16,
                    (reg ? Kl : Kh) + kb + (size_t)row * D + seg * 8);
            }
            #pragma unroll
            for (int t = 0; t < 4; t++) {
                int s = tid + t * 256;
                int reg = s >> 9, row = (s >> 3) & 63, seg = s & 7;
                CPA(kv + 18432 + reg * 9216 + row * 144 + seg * 16,
                    (reg ? Vl : Vh) + kb + (size_t)row * D + seg * 8);
            }
            if (tid < 64) am_s[((kt + 1) & 1) * 64 + tid] = amask[b * SEQ + (kt + 1) * 64 + tid];
            CPC();
        }
        const uint32_t kbuf = smb + KVB(kt & 1);
        const uint32_t vbuf = kbuf + 18432;
        const int* am = am_s + (kt & 1) * 64;

        float sc[8][4];
        #pragma unroll
        for (int i = 0; i < 8; i++)
            #pragma unroll
            for (int j = 0; j < 4; j++) sc[i][j] = 0.f;
        #pragma unroll
        for (int ks = 0; ks < 4; ks++) {
            #pragma unroll
            for (int ng = 0; ng < 4; ng++) {
                uint32_t Bh[4], Bl[4];
                const uint32_t roff = (ng*16 + b_row) * 144 + ks*32 + b_kb;
                ldsm4(Bh, kbuf + roff);
                ldsm4(Bl, kbuf + 9216 + roff);
                #pragma unroll
                for (int hf = 0; hf < 2; hf++) {
                    float* d = sc[ng*2 + hf];
                    mma_bf16(d, qhf[ks], Bh + hf*2);
                    mma_bf16(d, qlf[ks], Bh + hf*2);
                    mma_bf16(d, qhf[ks], Bl + hf*2);
                }
            }
        }
        float mx0 = -1e30f, mx1 = -1e30f;
        #pragma unroll
        for (int nt = 0; nt < 8; nt++) {
            const int c0 = nt*8 + tg*2, c1 = c0 + 1;
            const int col0 = kt*64 + c0, col1 = col0 + 1;
            const int ok0 = am[c0], ok1 = am[c1];
            float s0 = sc[nt][0] * 0.125f, s1 = sc[nt][1] * 0.125f;
            float s2 = sc[nt][2] * 0.125f, s3 = sc[nt][3] * 0.125f;
            if (col0 > row0     || !ok0) s0 = -1e9f;
            if (col1 > row0     || !ok1) s1 = -1e9f;
            if (col0 > row0 + 8 || !ok0) s2 = -1e9f;
            if (col1 > row0 + 8 || !ok1) s3 = -1e9f;
            sc[nt][0] = s0; sc[nt][1] = s1; sc[nt][2] = s2; sc[nt][3] = s3;
            mx0 = fmaxf(mx0, fmaxf(s0, s1));
            mx1 = fmaxf(mx1, fmaxf(s2, s3));
        }
        mx0 = fmaxf(mx0, __shfl_xor_sync(0xffffffffu, mx0, 1));
        mx0 = fmaxf(mx0, __shfl_xor_sync(0xffffffffu, mx0, 2));
        mx1 = fmaxf(mx1, __shfl_xor_sync(0xffffffffu, mx1, 1));
        mx1 = fmaxf(mx1, __shfl_xor_sync(0xffffffffu, mx1, 2));
        const float mn0 = fmaxf(m_i[0], mx0), mn1 = fmaxf(m_i[1], mx1);
        const float al0 = fexp(m_i[0] - mn0), al1 = fexp(m_i[1] - mn1);
        float rs0 = 0.f, rs1 = 0.f;
        #pragma unroll
        for (int nt = 0; nt < 8; nt++) {
            float p0 = fexp(sc[nt][0] - mn0), p1 = fexp(sc[nt][1] - mn0);
            float p2 = fexp(sc[nt][2] - mn1), p3 = fexp(sc[nt][3] - mn1);
            sc[nt][0] = p0; sc[nt][1] = p1; sc[nt][2] = p2; sc[nt][3] = p3;
            rs0 += p0 + p1; rs1 += p2 + p3;
        }
        rs0 += __shfl_xor_sync(0xffffffffu, rs0, 1);
        rs0 += __shfl_xor_sync(0xffffffffu, rs0, 2);
        rs1 += __shfl_xor_sync(0xffffffffu, rs1, 1);
        rs1 += __shfl_xor_sync(0xffffffffu, rs1, 2);
        l_i[0] = l_i[0] * al0 + rs0;  m_i[0] = mn0;
        l_i[1] = l_i[1] * al1 + rs1;  m_i[1] = mn1;
        #pragma unroll
        for (int dt = 0; dt < 8; dt++) {
            o_acc[dt][0] *= al0; o_acc[dt][1] *= al0;
            o_acc[dt][2] *= al1; o_acc[dt][3] *= al1;
        }
        #pragma unroll
        for (int ks = 0; ks < 4; ks++) {
            uint32_t ph[4], pl[4];
            const int n0t = 2*ks, n1t = 2*ks + 1;
            ph[0] = pack_hi(sc[n0t][0], sc[n0t][1]); ph[1] = pack_hi(sc[n0t][2], sc[n0t][3]);
            ph[2] = pack_hi(sc[n1t][0], sc[n1t][1]); ph[3] = pack_hi(sc[n1t][2], sc[n1t][3]);
            pl[0] = pack_lo(sc[n0t][0], sc[n0t][1]); pl[1] = pack_lo(sc[n0t][2], sc[n0t][3]);
            pl[2] = pack_lo(sc[n1t][0], sc[n1t][1]); pl[3] = pack_lo(sc[n1t][2], sc[n1t][3]);
            #pragma unroll
            for (int dg = 0; dg < 4; dg++) {
                uint32_t Vhf[4], Vlf[4];
                const uint32_t voff = (ks*16 + v_row) * 144 + dg*32 + v_byte;
                ldsm4t(Vhf, vbuf + voff);
                ldsm4t(Vlf, vbuf + 9216 + voff);
                #pragma unroll
                for (int hf = 0; hf < 2; hf++) {
                    float* d = o_acc[dg*2 + hf];
                    mma_bf16(d, ph, Vhf + hf*2);
                    mma_bf16(d, pl, Vhf + hf*2);
                    mma_bf16(d, ph, Vlf + hf*2);
                }
            }
        }
    }
    const float inv0 = 1.0f / l_i[0], inv1 = 1.0f / l_i[1];
    #pragma unroll
    for (int dt = 0; dt < 8; dt++) {
        const int col = dt*8 + tg*2;
        const size_t o0 = base + (size_t)row0 * D + col;
        const size_t o1 = base + (size_t)(row0 + 8) * D + col;
        float v0 = o_acc[dt][0]*inv0, v1 = o_acc[dt][1]*inv0;
        float v2 = o_acc[dt][2]*inv1, v3 = o_acc[dt][3]*inv1;
        *(uint32_t*)&Oh[o0] = pack_hi(v0, v1);
        *(uint32_t*)&Oh[o1] = pack_hi(v2, v3);
        *(uint32_t*)&Ol[o0] = pack_lo(v0, v1);
        *(uint32_t*)&Ol[o1] = pack_lo(v2, v3);
    }
}

// ---------------- fused (residual add +) LayerNorm + bf16 split --------
__global__ void add_ln_kernel(float* __restrict__ X, const float* __restrict__ R,
                              const float* __restrict__ g, const float* __restrict__ b,
                              __nv_bfloat16* __restrict__ Xh,
                              __nv_bfloat16* __restrict__ Xl)
{
    const int row = blockIdx.x;
    __shared__ float sh[4];
    const int c = threadIdx.x * 4;
    float4 v = *(const float4*)&X[(size_t)row*D + c];
    if (R) {
        float4 r = *(const float4*)&R[(size_t)row*D + c];
        v.x += r.x; v.y += r.y; v.z += r.z; v.w += r.w;
    }
    float s = v.x + v.y + v.z + v.w;
    #pragma unroll
    for (int o = 16; o; o >>= 1) s += __shfl_xor_sync(0xffffffffu, s, o);
    if ((threadIdx.x & 31) == 0) sh[threadIdx.x >> 5] = s;
    __syncthreads();
    float mu = (sh[0] + sh[1] + sh[2] + sh[3]) * (1.0f / D);
    float dx = v.x - mu, dy = v.y - mu, dz = v.z - mu, dw = v.w - mu;
    float sq = dx*dx + dy*dy + dz*dz + dw*dw;
    #pragma unroll
    for (int o = 16; o; o >>= 1) sq += __shfl_xor_sync(0xffffffffu, sq, o);
    __syncthreads();
    if ((threadIdx.x & 31) == 0) sh[threadIdx.x >> 5] = sq;
    __syncthreads();
    float var = (sh[0] + sh[1] + sh[2] + sh[3]) * (1.0f / D);
    float inv = rsqrtf(var + 1e-5f);
    float4 gg = *(const float4*)&g[c];
    float4 bb = *(const float4*)&b[c];
    float o0 = dx*inv*gg.x + bb.x, o1 = dy*inv*gg.y + bb.y;
    float o2 = dz*inv*gg.z + bb.z, o3 = dw*inv*gg.w + bb.w;
    const size_t off = (size_t)row*D + c;
    *(float4*)&X[off] = make_float4(o0, o1, o2, o3);
    *(uint32_t*)&Xh[off]     = pack_hi(o0, o1);
    *(uint32_t*)&Xh[off + 2] = pack_hi(o2, o3);
    *(uint32_t*)&Xl[off]     = pack_lo(o0, o1);
    *(uint32_t*)&Xl[off + 2] = pack_lo(o2, o3);
}

// ---------------- host orchestration ----------------
extern "C" void kernel_launch(void* const* d_in, const int* in_sizes, int n_in,
                              void* d_out, int out_size)
{
    const int*   ids  = (const int*)  d_in[0];
    const int*   am   = (const int*)  d_in[1];
    const float* emb  = (const float*)d_in[2];
    const float* wq   = (const float*)d_in[3];  const float* bq = (const float*)d_in[4];
    const float* wk   = (const float*)d_in[5];  const float* bk = (const float*)d_in[6];
    const float* wv   = (const float*)d_in[7];  const float* bv = (const float*)d_in[8];
    const float* wo   = (const float*)d_in[9];  const float* bo = (const float*)d_in[10];
    const float* ln1g = (const float*)d_in[11]; const float* ln1b = (const float*)d_in[12];
    const float* w1   = (const float*)d_in[13]; const float* b1 = (const float*)d_in[14];
    const float* w2   = (const float*)d_in[15]; const float* b2 = (const float*)d_in[16];
    const float* ln2g = (const float*)d_in[17]; const float* ln2b = (const float*)d_in[18];
    const float* lnfg = (const float*)d_in[19]; const float* lnfb = (const float*)d_in[20];
    const float* lmw  = (const float*)d_in[21];
    float* out = (float*)d_out;

    static float *xp = nullptr, *tp, *bcat;
    static __nv_bfloat16 *xh, *xl, *qh, *ql, *kh, *kl, *vh, *vl, *oh, *ol, *fh, *fl, *wh, *wl;
    if (!xp) {
        cudaGetSymbolAddress((void**)&xp, g_x);
        cudaGetSymbolAddress((void**)&tp, g_t);
        cudaGetSymbolAddress((void**)&bcat, g_bcat);
        cudaGetSymbolAddress((void**)&xh, g_xh);
        cudaGetSymbolAddress((void**)&xl, g_xl);
        cudaGetSymbolAddress((void**)&qh, g_qh);
        cudaGetSymbolAddress((void**)&ql, g_ql);
        cudaGetSymbolAddress((void**)&kh, g_kh);
        cudaGetSymbolAddress((void**)&kl, g_kl);
        cudaGetSymbolAddress((void**)&vh, g_vh);
        cudaGetSymbolAddress((void**)&vl, g_vl);
        cudaGetSymbolAddress((void**)&oh, g_oh);
        cudaGetSymbolAddress((void**)&ol, g_ol);
        cudaGetSymbolAddress((void**)&fh, g_fh);
        cudaGetSymbolAddress((void**)&fl, g_fl);
        cudaGetSymbolAddress((void**)&wh, g_wh);
        cudaGetSymbolAddress((void**)&wl, g_wl);
        cudaFuncSetAttribute(attn_tc, cudaFuncAttributeMaxDynamicSharedMemorySize, ASME);
        cudaFuncSetAttribute(gemm_bf,   cudaFuncAttributeMaxDynamicSharedMemorySize, 81920);
        cudaFuncSetAttribute(gemm_wide, cudaFuncAttributeMaxDynamicSharedMemorySize, 122880);
    }

    conv_all<<<W_TOTAL/1024, 256>>>(wq, wk, wv, wo, w1, w2, lmw);
    bcat_kernel<<<(NL*3*D + 255)/256, 256>>>(bq, bk, bv);
    detect_ids_kernel<<<1, 256>>>(ids);
    embed_kernel<<<TOK, 128>>>(ids, emb);

    const dim3 gQKV(1536/256, TOK/128); // (6, 32) 512 threads
    const dim3 gD(D/128,  TOK/128);     // (4, 32) 256 threads
    const dim3 gF(FFD/256, TOK/128);    // (8, 32) 512 threads
    for (int l = 0; l < NL; l++) {
        gemm_wide<<<gQKV, 512, 122880>>>(xh, xl,
            wh + OFF_QKV + (size_t)l*3*DD, wl + OFF_QKV + (size_t)l*3*DD,
            bcat + l*1536, nullptr, qh, ql, kh, kl, vh, vl, TOK, 1536, D, 0);
        attn_tc<<<dim3(SEQ/128, BB*NH), 256, ASME>>>(qh, ql, kh, kl, vh, vl, am, oh, ol);
        gemm_bf<<<gD, 256, 81920>>>(oh, ol,
            wh + OFF_WO + (size_t)l*DD, wl + OFF_WO + (size_t)l*DD,
            bo + l*D, tp, nullptr, nullptr, TOK, D, D, 0);
        add_ln_kernel<<<TOK, 128>>>(xp, tp, ln1g + l*D, ln1b + l*D, xh, xl);
        gemm_wide<<<gF, 512, 122880>>>(xh, xl,
            wh + OFF_W1 + (size_t)l*FFD*D, wl + OFF_W1 + (size_t)l*FFD*D,
            b1 + l*FFD, nullptr, fh, fl, nullptr, nullptr, nullptr, nullptr,
            TOK, FFD, D, 1);
        gemm_bf<<<gD, 256, 81920>>>(fh, fl,
            wh + OFF_W2 + (size_t)l*D*FFD, wl + OFF_W2 + (size_t)l*D*FFD,
            b2 + l*D, tp, nullptr, nullptr, TOK, D, FFD, 0);
        add_ln_kernel<<<TOK, 128>>>(xp, tp, ln2g + l*D, ln2b + l*D, xh, xl);
    }
    add_ln_kernel<<<TOK, 128>>>(xp, nullptr, lnfg, lnfb, xh, xl);
    gemm_bf<<<gD, 256, 81920>>>(xh, xl, wh + OFF_LM, wl + OFF_LM,
        nullptr, out, nullptr, nullptr, TOK, VOC, D, 0);
}

// round 13
// speedup vs baseline: 1.0820x; 1.0820x over previous
#include <cuda_runtime.h>
#include <cuda_bf16.h>
#include <cstdint>

#define D   512
#define SEQ 1024
#define BB  4
#define NH  8
#define NL  6
#define FFD 2048
#define VOC 512
#define TOK (BB*SEQ)   // 4096
#define DD  (D*D)

// weight scratch offsets (element counts into g_wh/g_wl)
#define OFF_QKV 0                          // per layer: [wq; wk; wv] = 3*DD
#define OFF_WO  (18*DD)
#define OFF_W1  (24*DD)
#define OFF_W2  (OFF_W1 + 6*FFD*D)
#define OFF_LM  (OFF_W2 + 6*D*FFD)
#define W_TOTAL (OFF_LM + VOC*D)

// ---------------- device scratch (no allocations allowed) ----------------
__device__ float g_x[TOK*D];               // residual stream (fp32)
__device__ float g_t[TOK*D];               // gemm temp (split-K partial 0)
__device__ float g_t2[TOK*D];              // gemm temp (split-K partial 1)
__device__ float g_bcat[NL*3*D];           // concat qkv bias
__device__ __nv_bfloat16 g_xh[TOK*D],  g_xl[TOK*D];    // residual hi/lo
__device__ __nv_bfloat16 g_qh[TOK*D],  g_ql[TOK*D];    // Q hi/lo
__device__ __nv_bfloat16 g_kh[TOK*D],  g_kl[TOK*D];    // K hi/lo
__device__ __nv_bfloat16 g_vh[TOK*D],  g_vl[TOK*D];    // V hi/lo
__device__ __nv_bfloat16 g_oh[TOK*D],  g_ol[TOK*D];    // attn out hi/lo
__device__ __nv_bfloat16 g_fh[TOK*FFD], g_fl[TOK*FFD]; // ffn hidden hi/lo
__device__ __nv_bfloat16 g_wh[W_TOTAL], g_wl[W_TOTAL]; // weights hi/lo
__device__ int g_idmode;

// ---------------- helpers ----------------
__device__ __forceinline__ uint32_t smem_u32(const void* p) {
    uint32_t a;
    asm("{ .reg .u64 t; cvta.to.shared.u64 t, %1; cvt.u32.u64 %0, t; }"
        : "=r"(a) : "l"(p));
    return a;
}
__device__ __forceinline__ void ldsm4(uint32_t* r, uint32_t addr) {
    asm volatile("ldmatrix.sync.aligned.m8n8.x4.shared.b16 {%0,%1,%2,%3}, [%4];"
                 : "=r"(r[0]), "=r"(r[1]), "=r"(r[2]), "=r"(r[3]) : "r"(addr));
}
__device__ __forceinline__ void ldsm4t(uint32_t* r, uint32_t addr) {
    asm volatile("ldmatrix.sync.aligned.m8n8.x4.trans.shared.b16 {%0,%1,%2,%3}, [%4];"
                 : "=r"(r[0]), "=r"(r[1]), "=r"(r[2]), "=r"(r[3]) : "r"(addr));
}
__device__ __forceinline__ void mma_bf16(float* d, const uint32_t* a,
                                         const uint32_t* b) {
    asm volatile("mma.sync.aligned.m16n8k16.row.col.f32.bf16.bf16.f32 "
                 "{%0,%1,%2,%3}, {%4,%5,%6,%7}, {%8,%9}, {%0,%1,%2,%3};"
                 : "+f"(d[0]), "+f"(d[1]), "+f"(d[2]), "+f"(d[3])
                 : "r"(a[0]), "r"(a[1]), "r"(a[2]), "r"(a[3]),
                   "r"(b[0]), "r"(b[1]));
}
#define CPA(dst, src) \
    asm volatile("cp.async.ca.shared.global [%0], [%1], 16;" :: "r"(dst), "l"(src))
#define CPC()  asm volatile("cp.async.commit_group;" ::: "memory")
#define CPW0() asm volatile("cp.async.wait_group 0;" ::: "memory")

__device__ __forceinline__ uint32_t pack_hi(float a, float b) {
    return (uint32_t)__bfloat16_as_ushort(__float2bfloat16(a)) |
           ((uint32_t)__bfloat16_as_ushort(__float2bfloat16(b)) << 16);
}
__device__ __forceinline__ uint32_t pack_lo(float a, float b) {
    float ra = a - __bfloat162float(__float2bfloat16(a));
    float rb = b - __bfloat162float(__float2bfloat16(b));
    return (uint32_t)__bfloat16_as_ushort(__float2bfloat16(ra)) |
           ((uint32_t)__bfloat16_as_ushort(__float2bfloat16(rb)) << 16);
}
// fast exp: 2^(x*log2e) via 5-FMA poly + exponent bit-stuff (no MUFU)
__device__ __forceinline__ float fexp(float x) {
    x = fmaxf(x, -80.0f);
    float t = x * 1.4426950408889634f;
    float fi = rintf(t);
    float f = t - fi;
    float p =              1.3333558146e-3f;
    p = fmaf(p, f, 9.6180209764e-3f);
    p = fmaf(p, f, 5.5504108664e-2f);
    p = fmaf(p, f, 2.4022650695e-1f);
    p = fmaf(p, f, 6.9314718056e-1f);
    p = fmaf(p, f, 1.0f);
    return __int_as_float(((int)fi + 127) << 23) * p;
}

// ---- single fused weight conversion: all 7 tensors, one launch ----------
__global__ void conv_all(const float* __restrict__ wq, const float* __restrict__ wk,
                         const float* __restrict__ wv, const float* __restrict__ wo,
                         const float* __restrict__ w1, const float* __restrict__ w2,
                         const float* __restrict__ lmw)
{
    long i = ((long)blockIdx.x * 256 + threadIdx.x) * 4;
    const float* src;
    size_t d;
    if (i < 6L*DD) {
        long j = i;  long l = j / DD, r = j - l * DD;
        src = wq + j;  d = (size_t)l * 3 * DD + r;
    } else if (i < 12L*DD) {
        long j = i - 6L*DD;  long l = j / DD, r = j - l * DD;
        src = wk + j;  d = (size_t)l * 3 * DD + DD + r;
    } else if (i < 18L*DD) {
        long j = i - 12L*DD;  long l = j / DD, r = j - l * DD;
        src = wv + j;  d = (size_t)l * 3 * DD + 2 * DD + r;
    } else if (i < 24L*DD) {
        long j = i - 18L*DD;  src = wo + j;  d = OFF_WO + j;
    } else if (i < 24L*DD + 6L*FFD*D) {
        long j = i - 24L*DD;  src = w1 + j;  d = OFF_W1 + j;
    } else if (i < 24L*DD + 12L*FFD*D) {
        long j = i - (24L*DD + 6L*FFD*D);  src = w2 + j;  d = OFF_W2 + j;
    } else {
        long j = i - (24L*DD + 12L*FFD*D);  src = lmw + j;  d = OFF_LM + j;
    }
    float4 v = *(const float4*)src;
    *(uint32_t*)&g_wh[d]     = pack_hi(v.x, v.y);
    *(uint32_t*)&g_wh[d + 2] = pack_hi(v.z, v.w);
    *(uint32_t*)&g_wl[d]     = pack_lo(v.x, v.y);
    *(uint32_t*)&g_wl[d + 2] = pack_lo(v.z, v.w);
}

// concat qkv biases into g_bcat[l][1536]
__global__ void bcat_kernel(const float* __restrict__ bq,
                            const float* __restrict__ bk,
                            const float* __restrict__ bv)
{
    int i = blockIdx.x * 256 + threadIdx.x;
    if (i >= NL * 3 * D) return;
    int l = i / (3 * D), r = i % (3 * D);
    int part = r >> 9, d = r & 511;
    const float* s = part == 0 ? bq : part == 1 ? bk : bv;
    g_bcat[i] = s[l * D + d];
}

// ---------------- input_ids dtype detection ----------------
__global__ void detect_ids_kernel(const int* __restrict__ p) {
    __shared__ int any;
    if (threadIdx.x == 0) any = 0;
    __syncthreads();
    int loc = 0;
    for (int i = threadIdx.x; i < 2048; i += blockDim.x) loc |= p[2*i + 1];
    if (loc) atomicOr(&any, 1);
    __syncthreads();
    if (threadIdx.x == 0) g_idmode = any ? 1 : 0;
}

// ---------------- embedding + positional encoding (fp32 + hi/lo) -------
__global__ void embed_kernel(const int* __restrict__ ids,
                             const float* __restrict__ emb) {
    int bs = blockIdx.x;
    int s  = bs & (SEQ - 1);
    int id = g_idmode ? ids[bs] : ids[2*bs];
    const float* e = emb + (size_t)id * D;
    const float c = -9.210340371976184f / 512.0f;
    const int d0 = threadIdx.x * 4;
    float v[4];
    #pragma unroll
    for (int j = 0; j < 4; j++) {
        int d = d0 + j;
        float ang = (float)s * expf(c * (float)(d & ~1));
        float pe  = (d & 1) ? cosf(ang) : sinf(ang);
        v[j] = e[d] * 22.627416997969522f + pe;
    }
    const size_t off = (size_t)bs * D + d0;
    *(float4*)&g_x[off] = make_float4(v[0], v[1], v[2], v[3]);
    *(uint32_t*)&g_xh[off]     = pack_hi(v[0], v[1]);
    *(uint32_t*)&g_xh[off + 2] = pack_hi(v[2], v[3]);
    *(uint32_t*)&g_xl[off]     = pack_lo(v[0], v[1]);
    *(uint32_t*)&g_xl[off + 2] = pack_lo(v[2], v[3]);
}

// =====================================================================
// bf16 tensor-core GEMM 128x128, 2-stage cp.async (R9 baseline).
// Split-K: gridDim.z CTAs partition K; z=0 writes C(+bias), z=1 -> C2.
// QKV mode: KH!=null -> per-CTA output select, store stride 512.
// =====================================================================
__device__ __forceinline__ void load_chunk128(
    uint32_t sbuf,
    const __nv_bfloat16* __restrict__ Ah, const __nv_bfloat16* __restrict__ Al,
    const __nv_bfloat16* __restrict__ Wh, const __nv_bfloat16* __restrict__ Wl,
    int m0, int n0, int K, int kc, int tid)
{
    #pragma unroll
    for (int t = 0; t < 4; t++) {
        int s = tid + t * 256;
        int reg = s >> 9;
        int row = (s >> 2) & 127;
        int seg = s & 3;
        uint32_t dst = sbuf + reg * 10240 + row * 80 + seg * 16;
        const __nv_bfloat16* src = (reg ? Al : Ah) + (size_t)(m0 + row) * K + kc + seg * 8;
        CPA(dst, src);
    }
    #pragma unroll
    for (int t = 0; t < 4; t++) {
        int s = tid + t * 256;
        int reg = s >> 9;
        int row = (s >> 2) & 127;
        int seg = s & 3;
        uint32_t dst = sbuf + 20480 + reg * 10240 + row * 80 + seg * 16;
        const __nv_bfloat16* src = (reg ? Wl : Wh) + (size_t)(n0 + row) * K + kc + seg * 8;
        CPA(dst, src);
    }
}

__global__ void __launch_bounds__(256, 2) gemm_bf(
    const __nv_bfloat16* __restrict__ Ah, const __nv_bfloat16* __restrict__ Al,
    const __nv_bfloat16* __restrict__ Wh, const __nv_bfloat16* __restrict__ Wl,
    const float* __restrict__ bias, float* __restrict__ C,
    float* __restrict__ C2,
    __nv_bfloat16* __restrict__ Ch, __nv_bfloat16* __restrict__ Cl,
    __nv_bfloat16* __restrict__ KH, __nv_bfloat16* __restrict__ KL,
    __nv_bfloat16* __restrict__ VH, __nv_bfloat16* __restrict__ VL,
    int M, int N, int K, int relu)
{
    extern __shared__ char sm[];
    const uint32_t smb = smem_u32(sm);
    constexpr int BUFSZ = 40960;
    const int tid = threadIdx.x, wid = tid >> 5, lane = tid & 31;
    const int wm = wid >> 2;
    const int wn = wid & 3;
    const int m0 = blockIdx.y << 7;
    const int n0 = blockIdx.x << 7;
    const int zz = blockIdx.z;
    const int kslice = K / gridDim.z;
    const int kbase0 = zz * kslice;
    const int a_row = lane & 15,  a_kb = lane & 16;
    const int b_row = ((lane >> 4) << 3) + (lane & 7), b_kb = ((lane >> 3) & 1) << 4;

    float acc[4][4][4];
    #pragma unroll
    for (int i = 0; i < 4; i++)
        #pragma unroll
        for (int j = 0; j < 4; j++)
            #pragma unroll
            for (int t = 0; t < 4; t++) acc[i][j][t] = 0.0f;

    const int nch = kslice >> 5;
    load_chunk128(smb, Ah, Al, Wh, Wl, m0, n0, K, kbase0, tid);
    CPC();
    for (int c = 0; c < nch; c++) {
        CPW0();
        __syncthreads();
        if (c + 1 < nch) {
            load_chunk128(smb + ((c + 1) & 1) * BUFSZ, Ah, Al, Wh, Wl,
                          m0, n0, K, kbase0 + ((c + 1) << 5), tid);
            CPC();
        }
        const uint32_t ab = smb + (c & 1) * BUFSZ;
        const uint32_t wb = ab + 20480;
        #pragma unroll
        for (int ks = 0; ks < 2; ks++) {
            const int kbyte = ks * 32;
            uint32_t Bh[2][4], Bl[2][4];
            #pragma unroll
            for (int ng = 0; ng < 2; ng++) {
                const uint32_t roff = (wn*32 + ng*16 + b_row) * 80 + kbyte + b_kb;
                ldsm4(Bh[ng], wb + roff);
                ldsm4(Bl[ng], wb + 10240 + roff);
            }
            #pragma unroll
            for (int mt = 0; mt < 4; mt++) {
                uint32_t Af[4], Alf[4];
                const uint32_t aoff = (wm*64 + mt*16 + a_row) * 80 + kbyte + a_kb;
                ldsm4(Af,  ab + aoff);
                ldsm4(Alf, ab + 10240 + aoff);
                #pragma unroll
                for (int ng = 0; ng < 2; ng++)
                    #pragma unroll
                    for (int hf = 0; hf < 2; hf++) {
                        float* d = acc[mt][ng*2 + hf];
                        mma_bf16(d, Af,  Bh[ng] + hf*2);
                        mma_bf16(d, Alf, Bh[ng] + hf*2);
                        mma_bf16(d, Af,  Bl[ng] + hf*2);
                    }
            }
        }
        __syncthreads();
    }

    // epilogue (per-CTA output select for fused QKV; split-K buffer select)
    __nv_bfloat16 *oh_ = Ch, *ol_ = Cl;
    float* Cout = (zz == 0) ? C : C2;
    const float* bia = (zz == 0) ? bias : nullptr;
    int nst = N, nbase = n0;
    if (KH) {
        const int part = n0 >> 9;
        if (part == 1)      { oh_ = KH; ol_ = KL; }
        else if (part == 2) { oh_ = VH; ol_ = VL; }
        nbase = n0 & 511;
        nst = 512;
    }
    const int g = lane >> 2, tg = lane & 3;
    #pragma unroll
    for (int mt = 0; mt < 4; mt++) {
        #pragma unroll
        for (int nt = 0; nt < 4; nt++) {
            const int row  = m0 + wm*64 + mt*16 + g;
            const int colb = n0 + wn*32 + nt*8 + tg*2;
            const int cols = nbase + wn*32 + nt*8 + tg*2;
            float b0 = bia ? bia[colb]     : 0.0f;
            float b1 = bia ? bia[colb + 1] : 0.0f;
            float v0 = acc[mt][nt][0] + b0, v1 = acc[mt][nt][1] + b1;
            float v2 = acc[mt][nt][2] + b0, v3 = acc[mt][nt][3] + b1;
            if (relu) {
                v0 = fmaxf(v0, 0.f); v1 = fmaxf(v1, 0.f);
                v2 = fmaxf(v2, 0.f); v3 = fmaxf(v3, 0.f);
            }
            const size_t o0 = (size_t)row * nst + cols;
            const size_t o1 = (size_t)(row + 8) * nst + cols;
            if (Cout) {
                *(float2*)&Cout[o0] = make_float2(v0, v1);
                *(float2*)&Cout[o1] = make_float2(v2, v3);
            }
            if (oh_) {
                *(uint32_t*)&oh_[o0] = pack_hi(v0, v1);
                *(uint32_t*)&oh_[o1] = pack_hi(v2, v3);
                *(uint32_t*)&ol_[o0] = pack_lo(v0, v1);
                *(uint32_t*)&ol_[o1] = pack_lo(v2, v3);
            }
        }
    }
}

// =====================================================================
// Tensor-core flash attention (causal), double-buffered K/V pipeline.
// =====================================================================
#define KVB(i) ((i) * 36864)
#define AAM    73728
#define ASME   (AAM + 512)

__global__ void __launch_bounds__(256) attn_tc(
    const __nv_bfloat16* __restrict__ Qh, const __nv_bfloat16* __restrict__ Ql,
    const __nv_bfloat16* __restrict__ Kh, const __nv_bfloat16* __restrict__ Kl,
    const __nv_bfloat16* __restrict__ Vh, const __nv_bfloat16* __restrict__ Vl,
    const int* __restrict__ amask,
    __nv_bfloat16* __restrict__ Oh, __nv_bfloat16* __restrict__ Ol)
{
    extern __shared__ char sm[];
    const uint32_t smb = smem_u32(sm);
    int* am_s = (int*)(sm + AAM);              // [2][64]
    const int qt = blockIdx.x, bh = blockIdx.y;
    const int b = bh >> 3, h = bh & 7;
    const int tid = threadIdx.x, wid = tid >> 5, lane = tid & 31;
    const int g = lane >> 2, tg = lane & 3;
    const size_t base = (size_t)b * SEQ * D + h * 64;
    const int q0 = qt * 128;
    const int a_row = lane & 15, a_kb = lane & 16;
    const int b_row = ((lane >> 4) << 3) + (lane & 7), b_kb = ((lane >> 3) & 1) << 4;
    const int v_row = (((lane >> 3) & 1) << 3) + (lane & 7), v_byte = (lane >> 4) << 4;

    #pragma unroll
    for (int t = 0; t < 8; t++) {
        int s = tid + t * 256;
        int reg = s >> 10, row = (s >> 3) & 127, seg = s & 7;
        uint32_t dst = smb + KVB(1) + reg * 18432 + row * 144 + seg * 16;
        const __nv_bfloat16* src = (reg ? Ql : Qh) + base + (size_t)(q0 + row) * D + seg * 8;
        CPA(dst, src);
    }
    CPC(); CPW0();
    __syncthreads();
    uint32_t qhf[4][4], qlf[4][4];
    #pragma unroll
    for (int ks = 0; ks < 4; ks++) {
        const uint32_t off = (wid*16 + a_row) * 144 + ks*32 + a_kb;
        ldsm4(qhf[ks], smb + KVB(1) + off);
        ldsm4(qlf[ks], smb + KVB(1) + 18432 + off);
    }

    float m_i[2] = {-1e30f, -1e30f}, l_i[2] = {0.f, 0.f};
    float o_acc[8][4];
    #pragma unroll
    for (int i = 0; i < 8; i++)
        #pragma unroll
        for (int j = 0; j < 4; j++) o_acc[i][j] = 0.f;

    const int row0 = q0 + wid*16 + g;
    const int ktmax = 2*qt + 1;

    {
        const uint32_t kv = smb + KVB(0);
        #pragma unroll
        for (int t = 0; t < 4; t++) {
            int s = tid + t * 256;
            int reg = s >> 9, row = (s >> 3) & 63, seg = s & 7;
            CPA(kv + reg * 9216 + row * 144 + seg * 16,
                (reg ? Kl : Kh) + base + (size_t)row * D + seg * 8);
        }
        #pragma unroll
        for (int t = 0; t < 4; t++) {
            int s = tid + t * 256;
            int reg = s >> 9, row = (s >> 3) & 63, seg = s & 7;
            CPA(kv + 18432 + reg * 9216 + row * 144 + seg * 16,
                (reg ? Vl : Vh) + base + (size_t)row * D + seg * 8);
        }
        if (tid < 64) am_s[tid] = amask[b * SEQ + tid];
        CPC();
    }

    for (int kt = 0; kt <= ktmax; kt++) {
        CPW0();
        __syncthreads();
        if (kt + 1 <= ktmax) {
            const uint32_t kv = smb + KVB((kt + 1) & 1);
            const size_t kb = base + (size_t)((kt + 1) * 64) * D;
            #pragma unroll
            for (int t = 0; t < 4; t++) {
                int s = tid + t * 256;
                int reg = s >> 9, row = (s >> 3) & 63, seg = s & 7;
                CPA(kv + reg * 9216 + row * 144 + seg * 16,
                    (reg ? Kl : Kh) + kb + (size_t)row * D + seg * 8);
            }
            #pragma unroll
            for (int t = 0; t < 4; t++) {
                int s = tid + t * 256;
                int reg = s >> 9, row = (s >> 3) & 63, seg = s & 7;
                CPA(kv + 18432 + reg * 9216 + row * 144 + seg * 16,
                    (reg ? Vl : Vh) + kb + (size_t)row * D + seg * 8);
            }
            if (tid < 64) am_s[((kt + 1) & 1) * 64 + tid] = amask[b * SEQ + (kt + 1) * 64 + tid];
            CPC();
        }
        const uint32_t kbuf = smb + KVB(kt & 1);
        const uint32_t vbuf = kbuf + 18432;
        const int* am = am_s + (kt & 1) * 64;

        float sc[8][4];
        #pragma unroll
        for (int i = 0; i < 8; i++)
            #pragma unroll
            for (int j = 0; j < 4; j++) sc[i][j] = 0.f;
        #pragma unroll
        for (int ks = 0; ks < 4; ks++) {
            #pragma unroll
            for (int ng = 0; ng < 4; ng++) {
                uint32_t Bh[4], Bl[4];
                const uint32_t roff = (ng*16 + b_row) * 144 + ks*32 + b_kb;
                ldsm4(Bh, kbuf + roff);
                ldsm4(Bl, kbuf + 9216 + roff);
                #pragma unroll
                for (int hf = 0; hf < 2; hf++) {
                    float* d = sc[ng*2 + hf];
                    mma_bf16(d, qhf[ks], Bh + hf*2);
                    mma_bf16(d, qlf[ks], Bh + hf*2);
                    mma_bf16(d, qhf[ks], Bl + hf*2);
                }
            }
        }
        float mx0 = -1e30f, mx1 = -1e30f;
        #pragma unroll
        for (int nt = 0; nt < 8; nt++) {
            const int c0 = nt*8 + tg*2, c1 = c0 + 1;
            const int col0 = kt*64 + c0, col1 = col0 + 1;
            const int ok0 = am[c0], ok1 = am[c1];
            float s0 = sc[nt][0] * 0.125f, s1 = sc[nt][1] * 0.125f;
            float s2 = sc[nt][2] * 0.125f, s3 = sc[nt][3] * 0.125f;
            if (col0 > row0     || !ok0) s0 = -1e9f;
            if (col1 > row0     || !ok1) s1 = -1e9f;
            if (col0 > row0 + 8 || !ok0) s2 = -1e9f;
            if (col1 > row0 + 8 || !ok1) s3 = -1e9f;
            sc[nt][0] = s0; sc[nt][1] = s1; sc[nt][2] = s2; sc[nt][3] = s3;
            mx0 = fmaxf(mx0, fmaxf(s0, s1));
            mx1 = fmaxf(mx1, fmaxf(s2, s3));
        }
        mx0 = fmaxf(mx0, __shfl_xor_sync(0xffffffffu, mx0, 1));
        mx0 = fmaxf(mx0, __shfl_xor_sync(0xffffffffu, mx0, 2));
        mx1 = fmaxf(mx1, __shfl_xor_sync(0xffffffffu, mx1, 1));
        mx1 = fmaxf(mx1, __shfl_xor_sync(0xffffffffu, mx1, 2));
        const float mn0 = fmaxf(m_i[0], mx0), mn1 = fmaxf(m_i[1], mx1);
        const float al0 = fexp(m_i[0] - mn0), al1 = fexp(m_i[1] - mn1);
        float rs0 = 0.f, rs1 = 0.f;
        #pragma unroll
        for (int nt = 0; nt < 8; nt++) {
            float p0 = fexp(sc[nt][0] - mn0), p1 = fexp(sc[nt][1] - mn0);
            float p2 = fexp(sc[nt][2] - mn1), p3 = fexp(sc[nt][3] - mn1);
            sc[nt][0] = p0; sc[nt][1] = p1; sc[nt][2] = p2; sc[nt][3] = p3;
            rs0 += p0 + p1; rs1 += p2 + p3;
        }
        rs0 += __shfl_xor_sync(0xffffffffu, rs0, 1);
        rs0 += __shfl_xor_sync(0xffffffffu, rs0, 2);
        rs1 += __shfl_xor_sync(0xffffffffu, rs1, 1);
        rs1 += __shfl_xor_sync(0xffffffffu, rs1, 2);
        l_i[0] = l_i[0] * al0 + rs0;  m_i[0] = mn0;
        l_i[1] = l_i[1] * al1 + rs1;  m_i[1] = mn1;
        #pragma unroll
        for (int dt = 0; dt < 8; dt++) {
            o_acc[dt][0] *= al0; o_acc[dt][1] *= al0;
            o_acc[dt][2] *= al1; o_acc[dt][3] *= al1;
        }
        #pragma unroll
        for (int ks = 0; ks < 4; ks++) {
            uint32_t ph[4], pl[4];
            const int n0t = 2*ks, n1t = 2*ks + 1;
            ph[0] = pack_hi(sc[n0t][0], sc[n0t][1]); ph[1] = pack_hi(sc[n0t][2], sc[n0t][3]);
            ph[2] = pack_hi(sc[n1t][0], sc[n1t][1]); ph[3] = pack_hi(sc[n1t][2], sc[n1t][3]);
            pl[0] = pack_lo(sc[n0t][0], sc[n0t][1]); pl[1] = pack_lo(sc[n0t][2], sc[n0t][3]);
            pl[2] = pack_lo(sc[n1t][0], sc[n1t][1]); pl[3] = pack_lo(sc[n1t][2], sc[n1t][3]);
            #pragma unroll
            for (int dg = 0; dg < 4; dg++) {
                uint32_t Vhf[4], Vlf[4];
                const uint32_t voff = (ks*16 + v_row) * 144 + dg*32 + v_byte;
                ldsm4t(Vhf, vbuf + voff);
                ldsm4t(Vlf, vbuf + 9216 + voff);
                #pragma unroll
                for (int hf = 0; hf < 2; hf++) {
                    float* d = o_acc[dg*2 + hf];
                    mma_bf16(d, ph, Vhf + hf*2);
                    mma_bf16(d, pl, Vhf + hf*2);
                    mma_bf16(d, ph, Vlf + hf*2);
                }
            }
        }
    }
    const float inv0 = 1.0f / l_i[0], inv1 = 1.0f / l_i[1];
    #pragma unroll
    for (int dt = 0; dt < 8; dt++) {
        const int col = dt*8 + tg*2;
        const size_t o0 = base + (size_t)row0 * D + col;
        const size_t o1 = base + (size_t)(row0 + 8) * D + col;
        float v0 = o_acc[dt][0]*inv0, v1 = o_acc[dt][1]*inv0;
        float v2 = o_acc[dt][2]*inv1, v3 = o_acc[dt][3]*inv1;
        *(uint32_t*)&Oh[o0] = pack_hi(v0, v1);
        *(uint32_t*)&Oh[o1] = pack_hi(v2, v3);
        *(uint32_t*)&Ol[o0] = pack_lo(v0, v1);
        *(uint32_t*)&Ol[o1] = pack_lo(v2, v3);
    }
}

// -------- fused (residual add + split-K partial add +) LayerNorm --------
__global__ void add_ln_kernel(float* __restrict__ X, const float* __restrict__ R,
                              const float* __restrict__ R2,
                              const float* __restrict__ g, const float* __restrict__ b,
                              __nv_bfloat16* __restrict__ Xh,
                              __nv_bfloat16* __restrict__ Xl)
{
    const int row = blockIdx.x;
    __shared__ float sh[4];
    const int c = threadIdx.x * 4;
    float4 v = *(const float4*)&X[(size_t)row*D + c];
    if (R) {
        float4 r = *(const float4*)&R[(size_t)row*D + c];
        v.x += r.x; v.y += r.y; v.z += r.z; v.w += r.w;
    }
    if (R2) {
        float4 r = *(const float4*)&R2[(size_t)row*D + c];
        v.x += r.x; v.y += r.y; v.z += r.z; v.w += r.w;
    }
    float s = v.x + v.y + v.z + v.w;
    #pragma unroll
    for (int o = 16; o; o >>= 1) s += __shfl_xor_sync(0xffffffffu, s, o);
    if ((threadIdx.x & 31) == 0) sh[threadIdx.x >> 5] = s;
    __syncthreads();
    float mu = (sh[0] + sh[1] + sh[2] + sh[3]) * (1.0f / D);
    float dx = v.x - mu, dy = v.y - mu, dz = v.z - mu, dw = v.w - mu;
    float sq = dx*dx + dy*dy + dz*dz + dw*dw;
    #pragma unroll
    for (int o = 16; o; o >>= 1) sq += __shfl_xor_sync(0xffffffffu, sq, o);
    __syncthreads();
    if ((threadIdx.x & 31) == 0) sh[threadIdx.x >> 5] = sq;
    __syncthreads();
    float var = (sh[0] + sh[1] + sh[2] + sh[3]) * (1.0f / D);
    float inv = rsqrtf(var + 1e-5f);
    float4 gg = *(const float4*)&g[c];
    float4 bb = *(const float4*)&b[c];
    float o0 = dx*inv*gg.x + bb.x, o1 = dy*inv*gg.y + bb.y;
    float o2 = dz*inv*gg.z + bb.z, o3 = dw*inv*gg.w + bb.w;
    const size_t off = (size_t)row*D + c;
    *(float4*)&X[off] = make_float4(o0, o1, o2, o3);
    *(uint32_t*)&Xh[off]     = pack_hi(o0, o1);
    *(uint32_t*)&Xh[off + 2] = pack_hi(o2, o3);
    *(uint32_t*)&Xl[off]     = pack_lo(o0, o1);
    *(uint32_t*)&Xl[off + 2] = pack_lo(o2, o3);
}

// ---------------- host orchestration ----------------
extern "C" void kernel_launch(void* const* d_in, const int* in_sizes, int n_in,
                              void* d_out, int out_size)
{
    const int*   ids  = (const int*)  d_in[0];
    const int*   am   = (const int*)  d_in[1];
    const float* emb  = (const float*)d_in[2];
    const float* wq   = (const float*)d_in[3];  const float* bq = (const float*)d_in[4];
    const float* wk   = (const float*)d_in[5];  const float* bk = (const float*)d_in[6];
    const float* wv   = (const float*)d_in[7];  const float* bv = (const float*)d_in[8];
    const float* wo   = (const float*)d_in[9];  const float* bo = (const float*)d_in[10];
    const float* ln1g = (const float*)d_in[11]; const float* ln1b = (const float*)d_in[12];
    const float* w1   = (const float*)d_in[13]; const float* b1 = (const float*)d_in[14];
    const float* w2   = (const float*)d_in[15]; const float* b2 = (const float*)d_in[16];
    const float* ln2g = (const float*)d_in[17]; const float* ln2b = (const float*)d_in[18];
    const float* lnfg = (const float*)d_in[19]; const float* lnfb = (const float*)d_in[20];
    const float* lmw  = (const float*)d_in[21];
    float* out = (float*)d_out;

    static float *xp = nullptr, *tp, *t2, *bcat;
    static __nv_bfloat16 *xh, *xl, *qh, *ql, *kh, *kl, *vh, *vl, *oh, *ol, *fh, *fl, *wh, *wl;
    if (!xp) {
        cudaGetSymbolAddress((void**)&xp, g_x);
        cudaGetSymbolAddress((void**)&tp, g_t);
        cudaGetSymbolAddress((void**)&t2, g_t2);
        cudaGetSymbolAddress((void**)&bcat, g_bcat);
        cudaGetSymbolAddress((void**)&xh, g_xh);
        cudaGetSymbolAddress((void**)&xl, g_xl);
        cudaGetSymbolAddress((void**)&qh, g_qh);
        cudaGetSymbolAddress((void**)&ql, g_ql);
        cudaGetSymbolAddress((void**)&kh, g_kh);
        cudaGetSymbolAddress((void**)&kl, g_kl);
        cudaGetSymbolAddress((void**)&vh, g_vh);
        cudaGetSymbolAddress((void**)&vl, g_vl);
        cudaGetSymbolAddress((void**)&oh, g_oh);
        cudaGetSymbolAddress((void**)&ol, g_ol);
        cudaGetSymbolAddress((void**)&fh, g_fh);
        cudaGetSymbolAddress((void**)&fl, g_fl);
        cudaGetSymbolAddress((void**)&wh, g_wh);
        cudaGetSymbolAddress((void**)&wl, g_wl);
        cudaFuncSetAttribute(attn_tc, cudaFuncAttributeMaxDynamicSharedMemorySize, ASME);
        cudaFuncSetAttribute(gemm_bf, cudaFuncAttributeMaxDynamicSharedMemorySize, 81920);
    }

    conv_all<<<W_TOTAL/1024, 256>>>(wq, wk, wv, wo, w1, w2, lmw);
    bcat_kernel<<<(NL*3*D + 255)/256, 256>>>(bq, bk, bv);
    detect_ids_kernel<<<1, 256>>>(ids);
    embed_kernel<<<TOK, 128>>>(ids, emb);

    const dim3 gQKV(1536/128, TOK/128);    // (12, 32)
    const dim3 gDs(D/128, TOK/128, 2);     // (4, 32, 2) split-K
    const dim3 gD(D/128, TOK/128);         // (4, 32)
    const dim3 gF(FFD/128, TOK/128);       // (16, 32)
    for (int l = 0; l < NL; l++) {
        gemm_bf<<<gQKV, 256, 81920>>>(xh, xl,
            wh + OFF_QKV + (size_t)l*3*DD, wl + OFF_QKV + (size_t)l*3*DD,
            bcat + l*1536, nullptr, nullptr, qh, ql, kh, kl, vh, vl, TOK, 1536, D, 0);
        attn_tc<<<dim3(SEQ/128, BB*NH), 256, ASME>>>(qh, ql, kh, kl, vh, vl, am, oh, ol);
        gemm_bf<<<gDs, 256, 81920>>>(oh, ol,
            wh + OFF_WO + (size_t)l*DD, wl + OFF_WO + (size_t)l*DD,
            bo + l*D, tp, t2, nullptr, nullptr, nullptr, nullptr, nullptr, nullptr,
            TOK, D, D, 0);
        add_ln_kernel<<<TOK, 128>>>(xp, tp, t2, ln1g + l*D, ln1b + l*D, xh, xl);
        gemm_bf<<<gF, 256, 81920>>>(xh, xl,
            wh + OFF_W1 + (size_t)l*FFD*D, wl + OFF_W1 + (size_t)l*FFD*D,
            b1 + l*FFD, nullptr, nullptr, fh, fl, nullptr, nullptr, nullptr, nullptr,
            TOK, FFD, D, 1);
        gemm_bf<<<gDs, 256, 81920>>>(fh, fl,
            wh + OFF_W2 + (size_t)l*D*FFD, wl + OFF_W2 + (size_t)l*D*FFD,
            b2 + l*D, tp, t2, nullptr, nullptr, nullptr, nullptr, nullptr, nullptr,
            TOK, D, FFD, 0);
        add_ln_kernel<<<TOK, 128>>>(xp, tp, t2, ln2g + l*D, ln2b + l*D, xh, xl);
    }
    add_ln_kernel<<<TOK, 128>>>(xp, nullptr, nullptr, lnfg, lnfb, xh, xl);
    gemm_bf<<<gD, 256, 81920>>>(xh, xl, wh + OFF_LM, wl + OFF_LM,
        nullptr, out, nullptr, nullptr, nullptr, nullptr, nullptr, nullptr, nullptr,
        TOK, VOC, D, 0);
}

// round 14
// speedup vs baseline: 1.0890x; 1.0065x over previous
#include <cuda_runtime.h>
#include <cuda_bf16.h>
#include <cstdint>

#define D   512
#define SEQ 1024
#define BB  4
#define NH  8
#define NL  6
#define FFD 2048
#define VOC 512
#define TOK (BB*SEQ)   // 4096
#define DD  (D*D)

// weight scratch offsets (element counts into g_wh/g_wl)
#define OFF_QKV 0                          // per layer: [wq; wk; wv] = 3*DD
#define OFF_WO  (18*DD)
#define OFF_W1  (24*DD)
#define OFF_W2  (OFF_W1 + 6*FFD*D)
#define OFF_LM  (OFF_W2 + 6*D*FFD)
#define W_TOTAL (OFF_LM + VOC*D)

// ---------------- device scratch (no allocations allowed) ----------------
__device__ float g_x[TOK*D];               // residual stream (fp32)
__device__ float g_t[TOK*D];               // gemm temp (split-K partial 0)
__device__ float g_t2[TOK*D];              // gemm temp (split-K partial 1)
__device__ float g_bcat[NL*3*D];           // concat qkv bias
__device__ __nv_bfloat16 g_xh[TOK*D],  g_xl[TOK*D];    // residual hi/lo
__device__ __nv_bfloat16 g_qh[TOK*D],  g_ql[TOK*D];    // Q hi/lo
__device__ __nv_bfloat16 g_kh[TOK*D],  g_kl[TOK*D];    // K hi/lo
__device__ __nv_bfloat16 g_vh[TOK*D],  g_vl[TOK*D];    // V hi/lo
__device__ __nv_bfloat16 g_oh[TOK*D],  g_ol[TOK*D];    // attn out hi/lo
__device__ __nv_bfloat16 g_fh[TOK*FFD], g_fl[TOK*FFD]; // ffn hidden hi/lo
__device__ __nv_bfloat16 g_wh[W_TOTAL], g_wl[W_TOTAL]; // weights hi/lo
__device__ int g_idmode;

// ---------------- helpers ----------------
__device__ __forceinline__ uint32_t smem_u32(const void* p) {
    uint32_t a;
    asm("{ .reg .u64 t; cvta.to.shared.u64 t, %1; cvt.u32.u64 %0, t; }"
        : "=r"(a) : "l"(p));
    return a;
}
__device__ __forceinline__ void ldsm4(uint32_t* r, uint32_t addr) {
    asm volatile("ldmatrix.sync.aligned.m8n8.x4.shared.b16 {%0,%1,%2,%3}, [%4];"
                 : "=r"(r[0]), "=r"(r[1]), "=r"(r[2]), "=r"(r[3]) : "r"(addr));
}
__device__ __forceinline__ void ldsm4t(uint32_t* r, uint32_t addr) {
    asm volatile("ldmatrix.sync.aligned.m8n8.x4.trans.shared.b16 {%0,%1,%2,%3}, [%4];"
                 : "=r"(r[0]), "=r"(r[1]), "=r"(r[2]), "=r"(r[3]) : "r"(addr));
}
__device__ __forceinline__ void mma_bf16(float* d, const uint32_t* a,
                                         const uint32_t* b) {
    asm volatile("mma.sync.aligned.m16n8k16.row.col.f32.bf16.bf16.f32 "
                 "{%0,%1,%2,%3}, {%4,%5,%6,%7}, {%8,%9}, {%0,%1,%2,%3};"
                 : "+f"(d[0]), "+f"(d[1]), "+f"(d[2]), "+f"(d[3])
                 : "r"(a[0]), "r"(a[1]), "r"(a[2]), "r"(a[3]),
                   "r"(b[0]), "r"(b[1]));
}
#define CPA(dst, src) \
    asm volatile("cp.async.ca.shared.global [%0], [%1], 16;" :: "r"(dst), "l"(src))
#define CPC()  asm volatile("cp.async.commit_group;" ::: "memory")
#define CPW0() asm volatile("cp.async.wait_group 0;" ::: "memory")

__device__ __forceinline__ uint32_t pack_hi(float a, float b) {
    return (uint32_t)__bfloat16_as_ushort(__float2bfloat16(a)) |
           ((uint32_t)__bfloat16_as_ushort(__float2bfloat16(b)) << 16);
}
__device__ __forceinline__ uint32_t pack_lo(float a, float b) {
    float ra = a - __bfloat162float(__float2bfloat16(a));
    float rb = b - __bfloat162float(__float2bfloat16(b));
    return (uint32_t)__bfloat16_as_ushort(__float2bfloat16(ra)) |
           ((uint32_t)__bfloat16_as_ushort(__float2bfloat16(rb)) << 16);
}
// fast exp: 2^(x*log2e) via 5-FMA poly + exponent bit-stuff (no MUFU)
__device__ __forceinline__ float fexp(float x) {
    x = fmaxf(x, -80.0f);
    float t = x * 1.4426950408889634f;
    float fi = rintf(t);
    float f = t - fi;
    float p =              1.3333558146e-3f;
    p = fmaf(p, f, 9.6180209764e-3f);
    p = fmaf(p, f, 5.5504108664e-2f);
    p = fmaf(p, f, 2.4022650695e-1f);
    p = fmaf(p, f, 6.9314718056e-1f);
    p = fmaf(p, f, 1.0f);
    return __int_as_float(((int)fi + 127) << 23) * p;
}

// ---- single fused weight conversion: all 7 tensors, one launch ----------
__global__ void conv_all(const float* __restrict__ wq, const float* __restrict__ wk,
                         const float* __restrict__ wv, const float* __restrict__ wo,
                         const float* __restrict__ w1, const float* __restrict__ w2,
                         const float* __restrict__ lmw)
{
    long i = ((long)blockIdx.x * 256 + threadIdx.x) * 4;
    const float* src;
    size_t d;
    if (i < 6L*DD) {
        long j = i;  long l = j / DD, r = j - l * DD;
        src = wq + j;  d = (size_t)l * 3 * DD + r;
    } else if (i < 12L*DD) {
        long j = i - 6L*DD;  long l = j / DD, r = j - l * DD;
        src = wk + j;  d = (size_t)l * 3 * DD + DD + r;
    } else if (i < 18L*DD) {
        long j = i - 12L*DD;  long l = j / DD, r = j - l * DD;
        src = wv + j;  d = (size_t)l * 3 * DD + 2 * DD + r;
    } else if (i < 24L*DD) {
        long j = i - 18L*DD;  src = wo + j;  d = OFF_WO + j;
    } else if (i < 24L*DD + 6L*FFD*D) {
        long j = i - 24L*DD;  src = w1 + j;  d = OFF_W1 + j;
    } else if (i < 24L*DD + 12L*FFD*D) {
        long j = i - (24L*DD + 6L*FFD*D);  src = w2 + j;  d = OFF_W2 + j;
    } else {
        long j = i - (24L*DD + 12L*FFD*D);  src = lmw + j;  d = OFF_LM + j;
    }
    float4 v = *(const float4*)src;
    *(uint32_t*)&g_wh[d]     = pack_hi(v.x, v.y);
    *(uint32_t*)&g_wh[d + 2] = pack_hi(v.z, v.w);
    *(uint32_t*)&g_wl[d]     = pack_lo(v.x, v.y);
    *(uint32_t*)&g_wl[d + 2] = pack_lo(v.z, v.w);
}

// concat qkv biases into g_bcat[l][1536]
__global__ void bcat_kernel(const float* __restrict__ bq,
                            const float* __restrict__ bk,
                            const float* __restrict__ bv)
{
    int i = blockIdx.x * 256 + threadIdx.x;
    if (i >= NL * 3 * D) return;
    int l = i / (3 * D), r = i % (3 * D);
    int part = r >> 9, d = r & 511;
    const float* s = part == 0 ? bq : part == 1 ? bk : bv;
    g_bcat[i] = s[l * D + d];
}

// split-K final combine: out = a + b
__global__ void addout_kernel(const float* __restrict__ a,
                              const float* __restrict__ b,
                              float* __restrict__ o)
{
    int i = (blockIdx.x * 256 + threadIdx.x) * 4;
    float4 x = *(const float4*)&a[i];
    float4 y = *(const float4*)&b[i];
    *(float4*)&o[i] = make_float4(x.x + y.x, x.y + y.y, x.z + y.z, x.w + y.w);
}

// ---------------- input_ids dtype detection ----------------
__global__ void detect_ids_kernel(const int* __restrict__ p) {
    __shared__ int any;
    if (threadIdx.x == 0) any = 0;
    __syncthreads();
    int loc = 0;
    for (int i = threadIdx.x; i < 2048; i += blockDim.x) loc |= p[2*i + 1];
    if (loc) atomicOr(&any, 1);
    __syncthreads();
    if (threadIdx.x == 0) g_idmode = any ? 1 : 0;
}

// ---------------- embedding + positional encoding (fp32 + hi/lo) -------
__global__ void embed_kernel(const int* __restrict__ ids,
                             const float* __restrict__ emb) {
    int bs = blockIdx.x;
    int s  = bs & (SEQ - 1);
    int id = g_idmode ? ids[bs] : ids[2*bs];
    const float* e = emb + (size_t)id * D;
    const float c = -9.210340371976184f / 512.0f;
    const int d0 = threadIdx.x * 4;
    float v[4];
    #pragma unroll
    for (int j = 0; j < 4; j++) {
        int d = d0 + j;
        float ang = (float)s * expf(c * (float)(d & ~1));
        float pe  = (d & 1) ? cosf(ang) : sinf(ang);
        v[j] = e[d] * 22.627416997969522f + pe;
    }
    const size_t off = (size_t)bs * D + d0;
    *(float4*)&g_x[off] = make_float4(v[0], v[1], v[2], v[3]);
    *(uint32_t*)&g_xh[off]     = pack_hi(v[0], v[1]);
    *(uint32_t*)&g_xh[off + 2] = pack_hi(v[2], v[3]);
    *(uint32_t*)&g_xl[off]     = pack_lo(v[0], v[1]);
    *(uint32_t*)&g_xl[off + 2] = pack_lo(v[2], v[3]);
}

// =====================================================================
// bf16 tensor-core GEMM 128x128, 2-stage cp.async (R9 baseline).
// Split-K: gridDim.z CTAs partition K; z=0 writes C(+bias), z=1 -> C2.
// QKV mode: KH!=null -> per-CTA output select, store stride 512.
// =====================================================================
__device__ __forceinline__ void load_chunk128(
    uint32_t sbuf,
    const __nv_bfloat16* __restrict__ Ah, const __nv_bfloat16* __restrict__ Al,
    const __nv_bfloat16* __restrict__ Wh, const __nv_bfloat16* __restrict__ Wl,
    int m0, int n0, int K, int kc, int tid)
{
    #pragma unroll
    for (int t = 0; t < 4; t++) {
        int s = tid + t * 256;
        int reg = s >> 9;
        int row = (s >> 2) & 127;
        int seg = s & 3;
        uint32_t dst = sbuf + reg * 10240 + row * 80 + seg * 16;
        const __nv_bfloat16* src = (reg ? Al : Ah) + (size_t)(m0 + row) * K + kc + seg * 8;
        CPA(dst, src);
    }
    #pragma unroll
    for (int t = 0; t < 4; t++) {
        int s = tid + t * 256;
        int reg = s >> 9;
        int row = (s >> 2) & 127;
        int seg = s & 3;
        uint32_t dst = sbuf + 20480 + reg * 10240 + row * 80 + seg * 16;
        const __nv_bfloat16* src = (reg ? Wl : Wh) + (size_t)(n0 + row) * K + kc + seg * 8;
        CPA(dst, src);
    }
}

__global__ void __launch_bounds__(256, 2) gemm_bf(
    const __nv_bfloat16* __restrict__ Ah, const __nv_bfloat16* __restrict__ Al,
    const __nv_bfloat16* __restrict__ Wh, const __nv_bfloat16* __restrict__ Wl,
    const float* __restrict__ bias, float* __restrict__ C,
    float* __restrict__ C2,
    __nv_bfloat16* __restrict__ Ch, __nv_bfloat16* __restrict__ Cl,
    __nv_bfloat16* __restrict__ KH, __nv_bfloat16* __restrict__ KL,
    __nv_bfloat16* __restrict__ VH, __nv_bfloat16* __restrict__ VL,
    int M, int N, int K, int relu)
{
    extern __shared__ char sm[];
    const uint32_t smb = smem_u32(sm);
    constexpr int BUFSZ = 40960;
    const int tid = threadIdx.x, wid = tid >> 5, lane = tid & 31;
    const int wm = wid >> 2;
    const int wn = wid & 3;
    const int m0 = blockIdx.y << 7;
    const int n0 = blockIdx.x << 7;
    const int zz = blockIdx.z;
    const int kslice = K / gridDim.z;
    const int kbase0 = zz * kslice;
    const int a_row = lane & 15,  a_kb = lane & 16;
    const int b_row = ((lane >> 4) << 3) + (lane & 7), b_kb = ((lane >> 3) & 1) << 4;

    float acc[4][4][4];
    #pragma unroll
    for (int i = 0; i < 4; i++)
        #pragma unroll
        for (int j = 0; j < 4; j++)
            #pragma unroll
            for (int t = 0; t < 4; t++) acc[i][j][t] = 0.0f;

    const int nch = kslice >> 5;
    load_chunk128(smb, Ah, Al, Wh, Wl, m0, n0, K, kbase0, tid);
    CPC();
    for (int c = 0; c < nch; c++) {
        CPW0();
        __syncthreads();
        if (c + 1 < nch) {
            load_chunk128(smb + ((c + 1) & 1) * BUFSZ, Ah, Al, Wh, Wl,
                          m0, n0, K, kbase0 + ((c + 1) << 5), tid);
            CPC();
        }
        const uint32_t ab = smb + (c & 1) * BUFSZ;
        const uint32_t wb = ab + 20480;
        #pragma unroll
        for (int ks = 0; ks < 2; ks++) {
            const int kbyte = ks * 32;
            uint32_t Bh[2][4], Bl[2][4];
            #pragma unroll
            for (int ng = 0; ng < 2; ng++) {
                const uint32_t roff = (wn*32 + ng*16 + b_row) * 80 + kbyte + b_kb;
                ldsm4(Bh[ng], wb + roff);
                ldsm4(Bl[ng], wb + 10240 + roff);
            }
            #pragma unroll
            for (int mt = 0; mt < 4; mt++) {
                uint32_t Af[4], Alf[4];
                const uint32_t aoff = (wm*64 + mt*16 + a_row) * 80 + kbyte + a_kb;
                ldsm4(Af,  ab + aoff);
                ldsm4(Alf, ab + 10240 + aoff);
                #pragma unroll
                for (int ng = 0; ng < 2; ng++)
                    #pragma unroll
                    for (int hf = 0; hf < 2; hf++) {
                        float* d = acc[mt][ng*2 + hf];
                        mma_bf16(d, Af,  Bh[ng] + hf*2);
                        mma_bf16(d, Alf, Bh[ng] + hf*2);
                        mma_bf16(d, Af,  Bl[ng] + hf*2);
                    }
            }
        }
        __syncthreads();
    }

    // epilogue (per-CTA output select for fused QKV; split-K buffer select)
    __nv_bfloat16 *oh_ = Ch, *ol_ = Cl;
    float* Cout = (zz == 0) ? C : C2;
    const float* bia = (zz == 0) ? bias : nullptr;
    int nst = N, nbase = n0;
    if (KH) {
        const int part = n0 >> 9;
        if (part == 1)      { oh_ = KH; ol_ = KL; }
        else if (part == 2) { oh_ = VH; ol_ = VL; }
        nbase = n0 & 511;
        nst = 512;
    }
    const int g = lane >> 2, tg = lane & 3;
    #pragma unroll
    for (int mt = 0; mt < 4; mt++) {
        #pragma unroll
        for (int nt = 0; nt < 4; nt++) {
            const int row  = m0 + wm*64 + mt*16 + g;
            const int colb = n0 + wn*32 + nt*8 + tg*2;
            const int cols = nbase + wn*32 + nt*8 + tg*2;
            float b0 = bia ? bia[colb]     : 0.0f;
            float b1 = bia ? bia[colb + 1] : 0.0f;
            float v0 = acc[mt][nt][0] + b0, v1 = acc[mt][nt][1] + b1;
            float v2 = acc[mt][nt][2] + b0, v3 = acc[mt][nt][3] + b1;
            if (relu) {
                v0 = fmaxf(v0, 0.f); v1 = fmaxf(v1, 0.f);
                v2 = fmaxf(v2, 0.f); v3 = fmaxf(v3, 0.f);
            }
            const size_t o0 = (size_t)row * nst + cols;
            const size_t o1 = (size_t)(row + 8) * nst + cols;
            if (Cout) {
                *(float2*)&Cout[o0] = make_float2(v0, v1);
                *(float2*)&Cout[o1] = make_float2(v2, v3);
            }
            if (oh_) {
                *(uint32_t*)&oh_[o0] = pack_hi(v0, v1);
                *(uint32_t*)&oh_[o1] = pack_hi(v2, v3);
                *(uint32_t*)&ol_[o0] = pack_lo(v0, v1);
                *(uint32_t*)&ol_[o1] = pack_lo(v2, v3);
            }
        }
    }
}

// =====================================================================
// Tensor-core flash attention (causal), double-buffered K/V pipeline.
// qt remapped so co-resident CTA pairs (bid, bid+148) have equal work:
// perm = [0,1,2,3,7,6,5,4] -> every SM's pair sums to 18 tile-units.
// =====================================================================
#define KVB(i) ((i) * 36864)
#define AAM    73728
#define ASME   (AAM + 512)

__global__ void __launch_bounds__(256) attn_tc(
    const __nv_bfloat16* __restrict__ Qh, const __nv_bfloat16* __restrict__ Ql,
    const __nv_bfloat16* __restrict__ Kh, const __nv_bfloat16* __restrict__ Kl,
    const __nv_bfloat16* __restrict__ Vh, const __nv_bfloat16* __restrict__ Vl,
    const int* __restrict__ amask,
    __nv_bfloat16* __restrict__ Oh, __nv_bfloat16* __restrict__ Ol)
{
    extern __shared__ char sm[];
    const uint32_t smb = smem_u32(sm);
    int* am_s = (int*)(sm + AAM);              // [2][64]
    const int qtx = blockIdx.x, bh = blockIdx.y;
    const int qt = (qtx < 4) ? qtx : 11 - qtx; // work-balance permutation
    const int b = bh >> 3, h = bh & 7;
    const int tid = threadIdx.x, wid = tid >> 5, lane = tid & 31;
    const int g = lane >> 2, tg = lane & 3;
    const size_t base = (size_t)b * SEQ * D + h * 64;
    const int q0 = qt * 128;
    const int a_row = lane & 15, a_kb = lane & 16;
    const int b_row = ((lane >> 4) << 3) + (lane & 7), b_kb = ((lane >> 3) & 1) << 4;
    const int v_row = (((lane >> 3) & 1) << 3) + (lane & 7), v_byte = (lane >> 4) << 4;

    #pragma unroll
    for (int t = 0; t < 8; t++) {
        int s = tid + t * 256;
        int reg = s >> 10, row = (s >> 3) & 127, seg = s & 7;
        uint32_t dst = smb + KVB(1) + reg * 18432 + row * 144 + seg * 16;
        const __nv_bfloat16* src = (reg ? Ql : Qh) + base + (size_t)(q0 + row) * D + seg * 8;
        CPA(dst, src);
    }
    CPC(); CPW0();
    __syncthreads();
    uint32_t qhf[4][4], qlf[4][4];
    #pragma unroll
    for (int ks = 0; ks < 4; ks++) {
        const uint32_t off = (wid*16 + a_row) * 144 + ks*32 + a_kb;
        ldsm4(qhf[ks], smb + KVB(1) + off);
        ldsm4(qlf[ks], smb + KVB(1) + 18432 + off);
    }

    float m_i[2] = {-1e30f, -1e30f}, l_i[2] = {0.f, 0.f};
    float o_acc[8][4];
    #pragma unroll
    for (int i = 0; i < 8; i++)
        #pragma unroll
        for (int j = 0; j < 4; j++) o_acc[i][j] = 0.f;

    const int row0 = q0 + wid*16 + g;
    const int ktmax = 2*qt + 1;

    {
        const uint32_t kv = smb + KVB(0);
        #pragma unroll
        for (int t = 0; t < 4; t++) {
            int s = tid + t * 256;
            int reg = s >> 9, row = (s >> 3) & 63, seg = s & 7;
            CPA(kv + reg * 9216 + row * 144 + seg * 16,
                (reg ? Kl : Kh) + base + (size_t)row * D + seg * 8);
        }
        #pragma unroll
        for (int t = 0; t < 4; t++) {
            int s = tid + t * 256;
            int reg = s >> 9, row = (s >> 3) & 63, seg = s & 7;
            CPA(kv + 18432 + reg * 9216 + row * 144 + seg * 16,
                (reg ? Vl : Vh) + base + (size_t)row * D + seg * 8);
        }
        if (tid < 64) am_s[tid] = amask[b * SEQ + tid];
        CPC();
    }

    for (int kt = 0; kt <= ktmax; kt++) {
        CPW0();
        __syncthreads();
        if (kt + 1 <= ktmax) {
            const uint32_t kv = smb + KVB((kt + 1) & 1);
            const size_t kb = base + (size_t)((kt + 1) * 64) * D;
            #pragma unroll
            for (int t = 0; t < 4; t++) {
                int s = tid + t * 256;
                int reg = s >> 9, row = (s >> 3) & 63, seg = s & 7;
                CPA(kv + reg * 9216 + row * 144 + seg * 16,
                    (reg ? Kl : Kh) + kb + (size_t)row * D + seg * 8);
            }
            #pragma unroll
            for (int t = 0; t < 4; t++) {
                int s = tid + t * 256;
                int reg = s >> 9, row = (s >> 3) & 63, seg = s & 7;
                CPA(kv + 18432 + reg * 9216 + row * 144 + seg * 16,
                    (reg ? Vl : Vh) + kb + (size_t)row * D + seg * 8);
            }
            if (tid < 64) am_s[((kt + 1) & 1) * 64 + tid] = amask[b * SEQ + (kt + 1) * 64 + tid];
            CPC();
        }
        const uint32_t kbuf = smb + KVB(kt & 1);
        const uint32_t vbuf = kbuf + 18432;
        const int* am = am_s + (kt & 1) * 64;

        float sc[8][4];
        #pragma unroll
        for (int i = 0; i < 8; i++)
            #pragma unroll
            for (int j = 0; j < 4; j++) sc[i][j] = 0.f;
        #pragma unroll
        for (int ks = 0; ks < 4; ks++) {
            #pragma unroll
            for (int ng = 0; ng < 4; ng++) {
                uint32_t Bh[4], Bl[4];
                const uint32_t roff = (ng*16 + b_row) * 144 + ks*32 + b_kb;
                ldsm4(Bh, kbuf + roff);
                ldsm4(Bl, kbuf + 9216 + roff);
                #pragma unroll
                for (int hf = 0; hf < 2; hf++) {
                    float* d = sc[ng*2 + hf];
                    mma_bf16(d, qhf[ks], Bh + hf*2);
                    mma_bf16(d, qlf[ks], Bh + hf*2);
                    mma_bf16(d, qhf[ks], Bl + hf*2);
                }
            }
        }
        float mx0 = -1e30f, mx1 = -1e30f;
        #pragma unroll
        for (int nt = 0; nt < 8; nt++) {
            const int c0 = nt*8 + tg*2, c1 = c0 + 1;
            const int col0 = kt*64 + c0, col1 = col0 + 1;
            const int ok0 = am[c0], ok1 = am[c1];
            float s0 = sc[nt][0] * 0.125f, s1 = sc[nt][1] * 0.125f;
            float s2 = sc[nt][2] * 0.125f, s3 = sc[nt][3] * 0.125f;
            if (col0 > row0     || !ok0) s0 = -1e9f;
            if (col1 > row0     || !ok1) s1 = -1e9f;
            if (col0 > row0 + 8 || !ok0) s2 = -1e9f;
            if (col1 > row0 + 8 || !ok1) s3 = -1e9f;
            sc[nt][0] = s0; sc[nt][1] = s1; sc[nt][2] = s2; sc[nt][3] = s3;
            mx0 = fmaxf(mx0, fmaxf(s0, s1));
            mx1 = fmaxf(mx1, fmaxf(s2, s3));
        }
        mx0 = fmaxf(mx0, __shfl_xor_sync(0xffffffffu, mx0, 1));
        mx0 = fmaxf(mx0, __shfl_xor_sync(0xffffffffu, mx0, 2));
        mx1 = fmaxf(mx1, __shfl_xor_sync(0xffffffffu, mx1, 1));
        mx1 = fmaxf(mx1, __shfl_xor_sync(0xffffffffu, mx1, 2));
        const float mn0 = fmaxf(m_i[0], mx0), mn1 = fmaxf(m_i[1], mx1);
        const float al0 = fexp(m_i[0] - mn0), al1 = fexp(m_i[1] - mn1);
        float rs0 = 0.f, rs1 = 0.f;
        #pragma unroll
        for (int nt = 0; nt < 8; nt++) {
            float p0 = fexp(sc[nt][0] - mn0), p1 = fexp(sc[nt][1] - mn0);
            float p2 = fexp(sc[nt][2] - mn1), p3 = fexp(sc[nt][3] - mn1);
            sc[nt][0] = p0; sc[nt][1] = p1; sc[nt][2] = p2; sc[nt][3] = p3;
            rs0 += p0 + p1; rs1 += p2 + p3;
        }
        rs0 += __shfl_xor_sync(0xffffffffu, rs0, 1);
        rs0 += __shfl_xor_sync(0xffffffffu, rs0, 2);
        rs1 += __shfl_xor_sync(0xffffffffu, rs1, 1);
        rs1 += __shfl_xor_sync(0xffffffffu, rs1, 2);
        l_i[0] = l_i[0] * al0 + rs0;  m_i[0] = mn0;
        l_i[1] = l_i[1] * al1 + rs1;  m_i[1] = mn1;
        #pragma unroll
        for (int dt = 0; dt < 8; dt++) {
            o_acc[dt][0] *= al0; o_acc[dt][1] *= al0;
            o_acc[dt][2] *= al1; o_acc[dt][3] *= al1;
        }
        #pragma unroll
        for (int ks = 0; ks < 4; ks++) {
            uint32_t ph[4], pl[4];
            const int n0t = 2*ks, n1t = 2*ks + 1;
            ph[0] = pack_hi(sc[n0t][0], sc[n0t][1]); ph[1] = pack_hi(sc[n0t][2], sc[n0t][3]);
            ph[2] = pack_hi(sc[n1t][0], sc[n1t][1]); ph[3] = pack_hi(sc[n1t][2], sc[n1t][3]);
            pl[0] = pack_lo(sc[n0t][0], sc[n0t][1]); pl[1] = pack_lo(sc[n0t][2], sc[n0t][3]);
            pl[2] = pack_lo(sc[n1t][0], sc[n1t][1]); pl[3] = pack_lo(sc[n1t][2], sc[n1t][3]);
            #pragma unroll
            for (int dg = 0; dg < 4; dg++) {
                uint32_t Vhf[4], Vlf[4];
                const uint32_t voff = (ks*16 + v_row) * 144 + dg*32 + v_byte;
                ldsm4t(Vhf, vbuf + voff);
                ldsm4t(Vlf, vbuf + 9216 + voff);
                #pragma unroll
                for (int hf = 0; hf < 2; hf++) {
                    float* d = o_acc[dg*2 + hf];
                    mma_bf16(d, ph, Vhf + hf*2);
                    mma_bf16(d, pl, Vhf + hf*2);
                    mma_bf16(d, ph, Vlf + hf*2);
                }
            }
        }
    }
    const float inv0 = 1.0f / l_i[0], inv1 = 1.0f / l_i[1];
    #pragma unroll
    for (int dt = 0; dt < 8; dt++) {
        const int col = dt*8 + tg*2;
        const size_t o0 = base + (size_t)row0 * D + col;
        const size_t o1 = base + (size_t)(row0 + 8) * D + col;
        float v0 = o_acc[dt][0]*inv0, v1 = o_acc[dt][1]*inv0;
        float v2 = o_acc[dt][2]*inv1, v3 = o_acc[dt][3]*inv1;
        *(uint32_t*)&Oh[o0] = pack_hi(v0, v1);
        *(uint32_t*)&Oh[o1] = pack_hi(v2, v3);
        *(uint32_t*)&Ol[o0] = pack_lo(v0, v1);
        *(uint32_t*)&Ol[o1] = pack_lo(v2, v3);
    }
}

// -------- fused (residual add + split-K partial add +) LayerNorm --------
__global__ void add_ln_kernel(float* __restrict__ X, const float* __restrict__ R,
                              const float* __restrict__ R2,
                              const float* __restrict__ g, const float* __restrict__ b,
                              __nv_bfloat16* __restrict__ Xh,
                              __nv_bfloat16* __restrict__ Xl)
{
    const int row = blockIdx.x;
    __shared__ float sh[4];
    const int c = threadIdx.x * 4;
    float4 v = *(const float4*)&X[(size_t)row*D + c];
    if (R) {
        float4 r = *(const float4*)&R[(size_t)row*D + c];
        v.x += r.x; v.y += r.y; v.z += r.z; v.w += r.w;
    }
    if (R2) {
        float4 r = *(const float4*)&R2[(size_t)row*D + c];
        v.x += r.x; v.y += r.y; v.z += r.z; v.w += r.w;
    }
    float s = v.x + v.y + v.z + v.w;
    #pragma unroll
    for (int o = 16; o; o >>= 1) s += __shfl_xor_sync(0xffffffffu, s, o);
    if ((threadIdx.x & 31) == 0) sh[threadIdx.x >> 5] = s;
    __syncthreads();
    float mu = (sh[0] + sh[1] + sh[2] + sh[3]) * (1.0f / D);
    float dx = v.x - mu, dy = v.y - mu, dz = v.z - mu, dw = v.w - mu;
    float sq = dx*dx + dy*dy + dz*dz + dw*dw;
    #pragma unroll
    for (int o = 16; o; o >>= 1) sq += __shfl_xor_sync(0xffffffffu, sq, o);
    __syncthreads();
    if ((threadIdx.x & 31) == 0) sh[threadIdx.x >> 5] = sq;
    __syncthreads();
    float var = (sh[0] + sh[1] + sh[2] + sh[3]) * (1.0f / D);
    float inv = rsqrtf(var + 1e-5f);
    float4 gg = *(const float4*)&g[c];
    float4 bb = *(const float4*)&b[c];
    float o0 = dx*inv*gg.x + bb.x, o1 = dy*inv*gg.y + bb.y;
    float o2 = dz*inv*gg.z + bb.z, o3 = dw*inv*gg.w + bb.w;
    const size_t off = (size_t)row*D + c;
    *(float4*)&X[off] = make_float4(o0, o1, o2, o3);
    *(uint32_t*)&Xh[off]     = pack_hi(o0, o1);
    *(uint32_t*)&Xh[off + 2] = pack_hi(o2, o3);
    *(uint32_t*)&Xl[off]     = pack_lo(o0, o1);
    *(uint32_t*)&Xl[off + 2] = pack_lo(o2, o3);
}

// ---------------- host orchestration ----------------
extern "C" void kernel_launch(void* const* d_in, const int* in_sizes, int n_in,
                              void* d_out, int out_size)
{
    const int*   ids  = (const int*)  d_in[0];
    const int*   am   = (const int*)  d_in[1];
    const float* emb  = (const float*)d_in[2];
    const float* wq   = (const float*)d_in[3];  const float* bq = (const float*)d_in[4];
    const float* wk   = (const float*)d_in[5];  const float* bk = (const float*)d_in[6];
    const float* wv   = (const float*)d_in[7];  const float* bv = (const float*)d_in[8];
    const float* wo   = (const float*)d_in[9];  const float* bo = (const float*)d_in[10];
    const float* ln1g = (const float*)d_in[11]; const float* ln1b = (const float*)d_in[12];
    const float* w1   = (const float*)d_in[13]; const float* b1 = (const float*)d_in[14];
    const float* w2   = (const float*)d_in[15]; const float* b2 = (const float*)d_in[16];
    const float* ln2g = (const float*)d_in[17]; const float* ln2b = (const float*)d_in[18];
    const float* lnfg = (const float*)d_in[19]; const float* lnfb = (const float*)d_in[20];
    const float* lmw  = (const float*)d_in[21];
    float* out = (float*)d_out;

    static float *xp = nullptr, *tp, *t2, *bcat;
    static __nv_bfloat16 *xh, *xl, *qh, *ql, *kh, *kl, *vh, *vl, *oh, *ol, *fh, *fl, *wh, *wl;
    if (!xp) {
        cudaGetSymbolAddress((void**)&xp, g_x);
        cudaGetSymbolAddress((void**)&tp, g_t);
        cudaGetSymbolAddress((void**)&t2, g_t2);
        cudaGetSymbolAddress((void**)&bcat, g_bcat);
        cudaGetSymbolAddress((void**)&xh, g_xh);
        cudaGetSymbolAddress((void**)&xl, g_xl);
        cudaGetSymbolAddress((void**)&qh, g_qh);
        cudaGetSymbolAddress((void**)&ql, g_ql);
        cudaGetSymbolAddress((void**)&kh, g_kh);
        cudaGetSymbolAddress((void**)&kl, g_kl);
        cudaGetSymbolAddress((void**)&vh, g_vh);
        cudaGetSymbolAddress((void**)&vl, g_vl);
        cudaGetSymbolAddress((void**)&oh, g_oh);
        cudaGetSymbolAddress((void**)&ol, g_ol);
        cudaGetSymbolAddress((void**)&fh, g_fh);
        cudaGetSymbolAddress((void**)&fl, g_fl);
        cudaGetSymbolAddress((void**)&wh, g_wh);
        cudaGetSymbolAddress((void**)&wl, g_wl);
        cudaFuncSetAttribute(attn_tc, cudaFuncAttributeMaxDynamicSharedMemorySize, ASME);
        cudaFuncSetAttribute(gemm_bf, cudaFuncAttributeMaxDynamicSharedMemorySize, 81920);
    }

    conv_all<<<W_TOTAL/1024, 256>>>(wq, wk, wv, wo, w1, w2, lmw);
    bcat_kernel<<<(NL*3*D + 255)/256, 256>>>(bq, bk, bv);
    detect_ids_kernel<<<1, 256>>>(ids);
    embed_kernel<<<TOK, 128>>>(ids, emb);

    const dim3 gQKV(1536/128, TOK/128);    // (12, 32)
    const dim3 gDs(D/128, TOK/128, 2);     // (4, 32, 2) split-K
    const dim3 gF(FFD/128, TOK/128);       // (16, 32)
    for (int l = 0; l < NL; l++) {
        gemm_bf<<<gQKV, 256, 81920>>>(xh, xl,
            wh + OFF_QKV + (size_t)l*3*DD, wl + OFF_QKV + (size_t)l*3*DD,
            bcat + l*1536, nullptr, nullptr, qh, ql, kh, kl, vh, vl, TOK, 1536, D, 0);
        attn_tc<<<dim3(SEQ/128, BB*NH), 256, ASME>>>(qh, ql, kh, kl, vh, vl, am, oh, ol);
        gemm_bf<<<gDs, 256, 81920>>>(oh, ol,
            wh + OFF_WO + (size_t)l*DD, wl + OFF_WO + (size_t)l*DD,
            bo + l*D, tp, t2, nullptr, nullptr, nullptr, nullptr, nullptr, nullptr,
            TOK, D, D, 0);
        add_ln_kernel<<<TOK, 128>>>(xp, tp, t2, ln1g + l*D, ln1b + l*D, xh, xl);
        gemm_bf<<<gF, 256, 81920>>>(xh, xl,
            wh + OFF_W1 + (size_t)l*FFD*D, wl + OFF_W1 + (size_t)l*FFD*D,
            b1 + l*FFD, nullptr, nullptr, fh, fl, nullptr, nullptr, nullptr, nullptr,
            TOK, FFD, D, 1);
        gemm_bf<<<gDs, 256, 81920>>>(fh, fl,
            wh + OFF_W2 + (size_t)l*D*FFD, wl + OFF_W2 + (size_t)l*D*FFD,
            b2 + l*D, tp, t2, nullptr, nullptr, nullptr, nullptr, nullptr, nullptr,
            TOK, D, FFD, 0);
        add_ln_kernel<<<TOK, 128>>>(xp, tp, t2, ln2g + l*D, ln2b + l*D, xh, xl);
    }
    add_ln_kernel<<<TOK, 128>>>(xp, nullptr, nullptr, lnfg, lnfb, xh, xl);
    // LM head: split-K=2 then combine into out
    gemm_bf<<<gDs, 256, 81920>>>(xh, xl, wh + OFF_LM, wl + OFF_LM,
        nullptr, tp, t2, nullptr, nullptr, nullptr, nullptr, nullptr, nullptr,
        TOK, VOC, D, 0);
    addout_kernel<<<(TOK*VOC)/1024, 256>>>(tp, t2, out);
}

// round 15
// speedup vs baseline: 1.1149x; 1.0238x over previous
#include <cuda_runtime.h>
#include <cuda_bf16.h>
#include <cstdint>

#define D   512
#define SEQ 1024
#define BB  4
#define NH  8
#define NL  6
#define FFD 2048
#define VOC 512
#define TOK (BB*SEQ)   // 4096
#define DD  (D*D)
#define NROW (BB*NH*SEQ)   // 32768 (b,h,s) rows

// weight scratch offsets (element counts into g_wh/g_wl)
#define OFF_QKV 0
#define OFF_WO  (18*DD)
#define OFF_W1  (24*DD)
#define OFF_W2  (OFF_W1 + 6*FFD*D)
#define OFF_LM  (OFF_W2 + 6*D*FFD)
#define W_TOTAL (OFF_LM + VOC*D)

// ---------------- device scratch (no allocations allowed) ----------------
__device__ float g_x[TOK*D];
__device__ float g_t[TOK*D];               // split-K / attn partial 0
__device__ float g_t2[TOK*D];              // split-K / attn partial 1
__device__ float g_pm[2*NROW], g_pl[2*NROW];  // attn partial m/l
__device__ float g_bcat[NL*3*D];
__device__ __nv_bfloat16 g_xh[TOK*D],  g_xl[TOK*D];
__device__ __nv_bfloat16 g_qh[TOK*D],  g_ql[TOK*D];
__device__ __nv_bfloat16 g_kh[TOK*D],  g_kl[TOK*D];
__device__ __nv_bfloat16 g_vh[TOK*D],  g_vl[TOK*D];
__device__ __nv_bfloat16 g_oh[TOK*D],  g_ol[TOK*D];
__device__ __nv_bfloat16 g_fh[TOK*FFD], g_fl[TOK*FFD];
__device__ __nv_bfloat16 g_wh[W_TOTAL], g_wl[W_TOTAL];
__device__ int g_idmode;

// ---------------- helpers ----------------
__device__ __forceinline__ uint32_t smem_u32(const void* p) {
    uint32_t a;
    asm("{ .reg .u64 t; cvta.to.shared.u64 t, %1; cvt.u32.u64 %0, t; }"
        : "=r"(a) : "l"(p));
    return a;
}
__device__ __forceinline__ void ldsm4(uint32_t* r, uint32_t addr) {
    asm volatile("ldmatrix.sync.aligned.m8n8.x4.shared.b16 {%0,%1,%2,%3}, [%4];"
                 : "=r"(r[0]), "=r"(r[1]), "=r"(r[2]), "=r"(r[3]) : "r"(addr));
}
__device__ __forceinline__ void ldsm4t(uint32_t* r, uint32_t addr) {
    asm volatile("ldmatrix.sync.aligned.m8n8.x4.trans.shared.b16 {%0,%1,%2,%3}, [%4];"
                 : "=r"(r[0]), "=r"(r[1]), "=r"(r[2]), "=r"(r[3]) : "r"(addr));
}
__device__ __forceinline__ void mma_bf16(float* d, const uint32_t* a,
                                         const uint32_t* b) {
    asm volatile("mma.sync.aligned.m16n8k16.row.col.f32.bf16.bf16.f32 "
                 "{%0,%1,%2,%3}, {%4,%5,%6,%7}, {%8,%9}, {%0,%1,%2,%3};"
                 : "+f"(d[0]), "+f"(d[1]), "+f"(d[2]), "+f"(d[3])
                 : "r"(a[0]), "r"(a[1]), "r"(a[2]), "r"(a[3]),
                   "r"(b[0]), "r"(b[1]));
}
#define CPA(dst, src) \
    asm volatile("cp.async.ca.shared.global [%0], [%1], 16;" :: "r"(dst), "l"(src))
#define CPC()  asm volatile("cp.async.commit_group;" ::: "memory")
#define CPW0() asm volatile("cp.async.wait_group 0;" ::: "memory")

__device__ __forceinline__ uint32_t pack_hi(float a, float b) {
    return (uint32_t)__bfloat16_as_ushort(__float2bfloat16(a)) |
           ((uint32_t)__bfloat16_as_ushort(__float2bfloat16(b)) << 16);
}
__device__ __forceinline__ uint32_t pack_lo(float a, float b) {
    float ra = a - __bfloat162float(__float2bfloat16(a));
    float rb = b - __bfloat162float(__float2bfloat16(b));
    return (uint32_t)__bfloat16_as_ushort(__float2bfloat16(ra)) |
           ((uint32_t)__bfloat16_as_ushort(__float2bfloat16(rb)) << 16);
}
__device__ __forceinline__ float fexp(float x) {
    x = fmaxf(x, -80.0f);
    float t = x * 1.4426950408889634f;
    float fi = rintf(t);
    float f = t - fi;
    float p =              1.3333558146e-3f;
    p = fmaf(p, f, 9.6180209764e-3f);
    p = fmaf(p, f, 5.5504108664e-2f);
    p = fmaf(p, f, 2.4022650695e-1f);
    p = fmaf(p, f, 6.9314718056e-1f);
    p = fmaf(p, f, 1.0f);
    return __int_as_float(((int)fi + 127) << 23) * p;
}

// ---- single fused weight conversion: all 7 tensors, one launch ----------
__global__ void conv_all(const float* __restrict__ wq, const float* __restrict__ wk,
                         const float* __restrict__ wv, const float* __restrict__ wo,
                         const float* __restrict__ w1, const float* __restrict__ w2,
                         const float* __restrict__ lmw)
{
    long i = ((long)blockIdx.x * 256 + threadIdx.x) * 4;
    const float* src;
    size_t d;
    if (i < 6L*DD) {
        long j = i;  long l = j / DD, r = j - l * DD;
        src = wq + j;  d = (size_t)l * 3 * DD + r;
    } else if (i < 12L*DD) {
        long j = i - 6L*DD;  long l = j / DD, r = j - l * DD;
        src = wk + j;  d = (size_t)l * 3 * DD + DD + r;
    } else if (i < 18L*DD) {
        long j = i - 12L*DD;  long l = j / DD, r = j - l * DD;
        src = wv + j;  d = (size_t)l * 3 * DD + 2 * DD + r;
    } else if (i < 24L*DD) {
        long j = i - 18L*DD;  src = wo + j;  d = OFF_WO + j;
    } else if (i < 24L*DD + 6L*FFD*D) {
        long j = i - 24L*DD;  src = w1 + j;  d = OFF_W1 + j;
    } else if (i < 24L*DD + 12L*FFD*D) {
        long j = i - (24L*DD + 6L*FFD*D);  src = w2 + j;  d = OFF_W2 + j;
    } else {
        long j = i - (24L*DD + 12L*FFD*D);  src = lmw + j;  d = OFF_LM + j;
    }
    float4 v = *(const float4*)src;
    *(uint32_t*)&g_wh[d]     = pack_hi(v.x, v.y);
    *(uint32_t*)&g_wh[d + 2] = pack_hi(v.z, v.w);
    *(uint32_t*)&g_wl[d]     = pack_lo(v.x, v.y);
    *(uint32_t*)&g_wl[d + 2] = pack_lo(v.z, v.w);
}

__global__ void bcat_kernel(const float* __restrict__ bq,
                            const float* __restrict__ bk,
                            const float* __restrict__ bv)
{
    int i = blockIdx.x * 256 + threadIdx.x;
    if (i >= NL * 3 * D) return;
    int l = i / (3 * D), r = i % (3 * D);
    int part = r >> 9, d = r & 511;
    const float* s = part == 0 ? bq : part == 1 ? bk : bv;
    g_bcat[i] = s[l * D + d];
}

__global__ void addout_kernel(const float* __restrict__ a,
                              const float* __restrict__ b,
                              float* __restrict__ o)
{
    int i = (blockIdx.x * 256 + threadIdx.x) * 4;
    float4 x = *(const float4*)&a[i];
    float4 y = *(const float4*)&b[i];
    *(float4*)&o[i] = make_float4(x.x + y.x, x.y + y.y, x.z + y.z, x.w + y.w);
}

__global__ void detect_ids_kernel(const int* __restrict__ p) {
    __shared__ int any;
    if (threadIdx.x == 0) any = 0;
    __syncthreads();
    int loc = 0;
    for (int i = threadIdx.x; i < 2048; i += blockDim.x) loc |= p[2*i + 1];
    if (loc) atomicOr(&any, 1);
    __syncthreads();
    if (threadIdx.x == 0) g_idmode = any ? 1 : 0;
}

__global__ void embed_kernel(const int* __restrict__ ids,
                             const float* __restrict__ emb) {
    int bs = blockIdx.x;
    int s  = bs & (SEQ - 1);
    int id = g_idmode ? ids[bs] : ids[2*bs];
    const float* e = emb + (size_t)id * D;
    const float c = -9.210340371976184f / 512.0f;
    const int d0 = threadIdx.x * 4;
    float v[4];
    #pragma unroll
    for (int j = 0; j < 4; j++) {
        int d = d0 + j;
        float ang = (float)s * expf(c * (float)(d & ~1));
        float pe  = (d & 1) ? cosf(ang) : sinf(ang);
        v[j] = e[d] * 22.627416997969522f + pe;
    }
    const size_t off = (size_t)bs * D + d0;
    *(float4*)&g_x[off] = make_float4(v[0], v[1], v[2], v[3]);
    *(uint32_t*)&g_xh[off]     = pack_hi(v[0], v[1]);
    *(uint32_t*)&g_xh[off + 2] = pack_hi(v[2], v[3]);
    *(uint32_t*)&g_xl[off]     = pack_lo(v[0], v[1]);
    *(uint32_t*)&g_xl[off + 2] = pack_lo(v[2], v[3]);
}

// =====================================================================
// bf16 tensor-core GEMM 128x128, 2-stage cp.async, optional split-K.
// =====================================================================
__device__ __forceinline__ void load_chunk128(
    uint32_t sbuf,
    const __nv_bfloat16* __restrict__ Ah, const __nv_bfloat16* __restrict__ Al,
    const __nv_bfloat16* __restrict__ Wh, const __nv_bfloat16* __restrict__ Wl,
    int m0, int n0, int K, int kc, int tid)
{
    #pragma unroll
    for (int t = 0; t < 4; t++) {
        int s = tid + t * 256;
        int reg = s >> 9;
        int row = (s >> 2) & 127;
        int seg = s & 3;
        uint32_t dst = sbuf + reg * 10240 + row * 80 + seg * 16;
        const __nv_bfloat16* src = (reg ? Al : Ah) + (size_t)(m0 + row) * K + kc + seg * 8;
        CPA(dst, src);
    }
    #pragma unroll
    for (int t = 0; t < 4; t++) {
        int s = tid + t * 256;
        int reg = s >> 9;
        int row = (s >> 2) & 127;
        int seg = s & 3;
        uint32_t dst = sbuf + 20480 + reg * 10240 + row * 80 + seg * 16;
        const __nv_bfloat16* src = (reg ? Wl : Wh) + (size_t)(n0 + row) * K + kc + seg * 8;
        CPA(dst, src);
    }
}

__global__ void __launch_bounds__(256, 2) gemm_bf(
    const __nv_bfloat16* __restrict__ Ah, const __nv_bfloat16* __restrict__ Al,
    const __nv_bfloat16* __restrict__ Wh, const __nv_bfloat16* __restrict__ Wl,
    const float* __restrict__ bias, float* __restrict__ C,
    float* __restrict__ C2,
    __nv_bfloat16* __restrict__ Ch, __nv_bfloat16* __restrict__ Cl,
    __nv_bfloat16* __restrict__ KH, __nv_bfloat16* __restrict__ KL,
    __nv_bfloat16* __restrict__ VH, __nv_bfloat16* __restrict__ VL,
    int M, int N, int K, int relu)
{
    extern __shared__ char sm[];
    const uint32_t smb = smem_u32(sm);
    constexpr int BUFSZ = 40960;
    const int tid = threadIdx.x, wid = tid >> 5, lane = tid & 31;
    const int wm = wid >> 2;
    const int wn = wid & 3;
    const int m0 = blockIdx.y << 7;
    const int n0 = blockIdx.x << 7;
    const int zz = blockIdx.z;
    const int kslice = K / gridDim.z;
    const int kbase0 = zz * kslice;
    const int a_row = lane & 15,  a_kb = lane & 16;
    const int b_row = ((lane >> 4) << 3) + (lane & 7), b_kb = ((lane >> 3) & 1) << 4;

    float acc[4][4][4];
    #pragma unroll
    for (int i = 0; i < 4; i++)
        #pragma unroll
        for (int j = 0; j < 4; j++)
            #pragma unroll
            for (int t = 0; t < 4; t++) acc[i][j][t] = 0.0f;

    const int nch = kslice >> 5;
    load_chunk128(smb, Ah, Al, Wh, Wl, m0, n0, K, kbase0, tid);
    CPC();
    for (int c = 0; c < nch; c++) {
        CPW0();
        __syncthreads();
        if (c + 1 < nch) {
            load_chunk128(smb + ((c + 1) & 1) * BUFSZ, Ah, Al, Wh, Wl,
                          m0, n0, K, kbase0 + ((c + 1) << 5), tid);
            CPC();
        }
        const uint32_t ab = smb + (c & 1) * BUFSZ;
        const uint32_t wb = ab + 20480;
        #pragma unroll
        for (int ks = 0; ks < 2; ks++) {
            const int kbyte = ks * 32;
            uint32_t Bh[2][4], Bl[2][4];
            #pragma unroll
            for (int ng = 0; ng < 2; ng++) {
                const uint32_t roff = (wn*32 + ng*16 + b_row) * 80 + kbyte + b_kb;
                ldsm4(Bh[ng], wb + roff);
                ldsm4(Bl[ng], wb + 10240 + roff);
            }
            #pragma unroll
            for (int mt = 0; mt < 4; mt++) {
                uint32_t Af[4], Alf[4];
                const uint32_t aoff = (wm*64 + mt*16 + a_row) * 80 + kbyte + a_kb;
                ldsm4(Af,  ab + aoff);
                ldsm4(Alf, ab + 10240 + aoff);
                #pragma unroll
                for (int ng = 0; ng < 2; ng++)
                    #pragma unroll
                    for (int hf = 0; hf < 2; hf++) {
                        float* d = acc[mt][ng*2 + hf];
                        mma_bf16(d, Af,  Bh[ng] + hf*2);
                        mma_bf16(d, Alf, Bh[ng] + hf*2);
                        mma_bf16(d, Af,  Bl[ng] + hf*2);
                    }
            }
        }
        __syncthreads();
    }

    __nv_bfloat16 *oh_ = Ch, *ol_ = Cl;
    float* Cout = (zz == 0) ? C : C2;
    const float* bia = (zz == 0) ? bias : nullptr;
    int nst = N, nbase = n0;
    if (KH) {
        const int part = n0 >> 9;
        if (part == 1)      { oh_ = KH; ol_ = KL; }
        else if (part == 2) { oh_ = VH; ol_ = VL; }
        nbase = n0 & 511;
        nst = 512;
    }
    const int g = lane >> 2, tg = lane & 3;
    #pragma unroll
    for (int mt = 0; mt < 4; mt++) {
        #pragma unroll
        for (int nt = 0; nt < 4; nt++) {
            const int row  = m0 + wm*64 + mt*16 + g;
            const int colb = n0 + wn*32 + nt*8 + tg*2;
            const int cols = nbase + wn*32 + nt*8 + tg*2;
            float b0 = bia ? bia[colb]     : 0.0f;
            float b1 = bia ? bia[colb + 1] : 0.0f;
            float v0 = acc[mt][nt][0] + b0, v1 = acc[mt][nt][1] + b1;
            float v2 = acc[mt][nt][2] + b0, v3 = acc[mt][nt][3] + b1;
            if (relu) {
                v0 = fmaxf(v0, 0.f); v1 = fmaxf(v1, 0.f);
                v2 = fmaxf(v2, 0.f); v3 = fmaxf(v3, 0.f);
            }
            const size_t o0 = (size_t)row * nst + cols;
            const size_t o1 = (size_t)(row + 8) * nst + cols;
            if (Cout) {
                *(float2*)&Cout[o0] = make_float2(v0, v1);
                *(float2*)&Cout[o1] = make_float2(v2, v3);
            }
            if (oh_) {
                *(uint32_t*)&oh_[o0] = pack_hi(v0, v1);
                *(uint32_t*)&oh_[o1] = pack_hi(v2, v3);
                *(uint32_t*)&ol_[o0] = pack_lo(v0, v1);
                *(uint32_t*)&ol_[o1] = pack_lo(v2, v3);
            }
        }
    }
}

// =====================================================================
// Split-KV tensor-core flash attention (causal). blockIdx.z halves the
// k-range (each z does qt+1 of the 2qt+2 tiles). Writes UN-normalized
// fp32 O partial + per-row (m,l); attn_combine merges.
// =====================================================================
#define KVB(i) ((i) * 36864)
#define AAM    73728
#define ASME   (AAM + 512)

__global__ void __launch_bounds__(256) attn_split(
    const __nv_bfloat16* __restrict__ Qh, const __nv_bfloat16* __restrict__ Ql,
    const __nv_bfloat16* __restrict__ Kh, const __nv_bfloat16* __restrict__ Kl,
    const __nv_bfloat16* __restrict__ Vh, const __nv_bfloat16* __restrict__ Vl,
    const int* __restrict__ amask,
    float* __restrict__ Op0, float* __restrict__ Op1,
    float* __restrict__ pmA, float* __restrict__ plA)
{
    extern __shared__ char sm[];
    const uint32_t smb = smem_u32(sm);
    int* am_s = (int*)(sm + AAM);              // [2][64]
    const int qt = blockIdx.x, bh = blockIdx.y, zz = blockIdx.z;
    const int b = bh >> 3, h = bh & 7;
    const int tid = threadIdx.x, wid = tid >> 5, lane = tid & 31;
    const int g = lane >> 2, tg = lane & 3;
    const size_t base = (size_t)b * SEQ * D + h * 64;
    const int q0 = qt * 128;
    const int nkt = qt + 1;
    const int kstart = zz * nkt;
    float* Op = zz ? Op1 : Op0;
    float* pm = pmA + zz * NROW;
    float* pl = plA + zz * NROW;
    const int a_row = lane & 15, a_kb = lane & 16;
    const int b_row = ((lane >> 4) << 3) + (lane & 7), b_kb = ((lane >> 3) & 1) << 4;
    const int v_row = (((lane >> 3) & 1) << 3) + (lane & 7), v_byte = (lane >> 4) << 4;

    // Q into buffer 1 region, then to register fragments
    #pragma unroll
    for (int t = 0; t < 8; t++) {
        int s = tid + t * 256;
        int reg = s >> 10, row = (s >> 3) & 127, seg = s & 7;
        uint32_t dst = smb + KVB(1) + reg * 18432 + row * 144 + seg * 16;
        const __nv_bfloat16* src = (reg ? Ql : Qh) + base + (size_t)(q0 + row) * D + seg * 8;
        CPA(dst, src);
    }
    CPC(); CPW0();
    __syncthreads();
    uint32_t qhf[4][4], qlf[4][4];
    #pragma unroll
    for (int ks = 0; ks < 4; ks++) {
        const uint32_t off = (wid*16 + a_row) * 144 + ks*32 + a_kb;
        ldsm4(qhf[ks], smb + KVB(1) + off);
        ldsm4(qlf[ks], smb + KVB(1) + 18432 + off);
    }

    float m_i[2] = {-1e30f, -1e30f}, l_i[2] = {0.f, 0.f};
    float o_acc[8][4];
    #pragma unroll
    for (int i = 0; i < 8; i++)
        #pragma unroll
        for (int j = 0; j < 4; j++) o_acc[i][j] = 0.f;

    const int row0 = q0 + wid*16 + g;

    // prologue: load first tile (kstart) into buffer 0
    {
        const uint32_t kv = smb + KVB(0);
        const size_t kb = base + (size_t)(kstart * 64) * D;
        #pragma unroll
        for (int t = 0; t < 4; t++) {
            int s = tid + t * 256;
            int reg = s >> 9, row = (s >> 3) & 63, seg = s & 7;
            CPA(kv + reg * 9216 + row * 144 + seg * 16,
                (reg ? Kl : Kh) + kb + (size_t)row * D + seg * 8);
        }
        #pragma unroll
        for (int t = 0; t < 4; t++) {
            int s = tid + t * 256;
            int reg = s >> 9, row = (s >> 3) & 63, seg = s & 7;
            CPA(kv + 18432 + reg * 9216 + row * 144 + seg * 16,
                (reg ? Vl : Vh) + kb + (size_t)row * D + seg * 8);
        }
        if (tid < 64) am_s[tid] = amask[b * SEQ + kstart * 64 + tid];
        CPC();
    }

    for (int j = 0; j < nkt; j++) {
        const int kt = kstart + j;
        CPW0();
        __syncthreads();
        if (j + 1 < nkt) {
            const uint32_t kv = smb + KVB((j + 1) & 1);
            const size_t kb = base + (size_t)((kt + 1) * 64) * D;
            #pragma unroll
            for (int t = 0; t < 4; t++) {
                int s = tid + t * 256;
                int reg = s >> 9, row = (s >> 3) & 63, seg = s & 7;
                CPA(kv + reg * 9216 + row * 144 + seg * 16,
                    (reg ? Kl : Kh) + kb + (size_t)row * D + seg * 8);
            }
            #pragma unroll
            for (int t = 0; t < 4; t++) {
                int s = tid + t * 256;
                int reg = s >> 9, row = (s >> 3) & 63, seg = s & 7;
                CPA(kv + 18432 + reg * 9216 + row * 144 + seg * 16,
                    (reg ? Vl : Vh) + kb + (size_t)row * D + seg * 8);
            }
            if (tid < 64) am_s[((j + 1) & 1) * 64 + tid] = amask[b * SEQ + (kt + 1) * 64 + tid];
            CPC();
        }
        const uint32_t kbuf = smb + KVB(j & 1);
        const uint32_t vbuf = kbuf + 18432;
        const int* am = am_s + (j & 1) * 64;

        float sc[8][4];
        #pragma unroll
        for (int i = 0; i < 8; i++)
            #pragma unroll
            for (int jj = 0; jj < 4; jj++) sc[i][jj] = 0.f;
        #pragma unroll
        for (int ks = 0; ks < 4; ks++) {
            #pragma unroll
            for (int ng = 0; ng < 4; ng++) {
                uint32_t Bh[4], Bl[4];
                const uint32_t roff = (ng*16 + b_row) * 144 + ks*32 + b_kb;
                ldsm4(Bh, kbuf + roff);
                ldsm4(Bl, kbuf + 9216 + roff);
                #pragma unroll
                for (int hf = 0; hf < 2; hf++) {
                    float* d = sc[ng*2 + hf];
                    mma_bf16(d, qhf[ks], Bh + hf*2);
                    mma_bf16(d, qlf[ks], Bh + hf*2);
                    mma_bf16(d, qhf[ks], Bl + hf*2);
                }
            }
        }
        float mx0 = -1e30f, mx1 = -1e30f;
        #pragma unroll
        for (int nt = 0; nt < 8; nt++) {
            const int c0 = nt*8 + tg*2, c1 = c0 + 1;
            const int col0 = kt*64 + c0, col1 = col0 + 1;
            const int ok0 = am[c0], ok1 = am[c1];
            float s0 = sc[nt][0] * 0.125f, s1 = sc[nt][1] * 0.125f;
            float s2 = sc[nt][2] * 0.125f, s3 = sc[nt][3] * 0.125f;
            if (col0 > row0     || !ok0) s0 = -1e9f;
            if (col1 > row0     || !ok1) s1 = -1e9f;
            if (col0 > row0 + 8 || !ok0) s2 = -1e9f;
            if (col1 > row0 + 8 || !ok1) s3 = -1e9f;
            sc[nt][0] = s0; sc[nt][1] = s1; sc[nt][2] = s2; sc[nt][3] = s3;
            mx0 = fmaxf(mx0, fmaxf(s0, s1));
            mx1 = fmaxf(mx1, fmaxf(s2, s3));
        }
        mx0 = fmaxf(mx0, __shfl_xor_sync(0xffffffffu, mx0, 1));
        mx0 = fmaxf(mx0, __shfl_xor_sync(0xffffffffu, mx0, 2));
        mx1 = fmaxf(mx1, __shfl_xor_sync(0xffffffffu, mx1, 1));
        mx1 = fmaxf(mx1, __shfl_xor_sync(0xffffffffu, mx1, 2));
        const float mn0 = fmaxf(m_i[0], mx0), mn1 = fmaxf(m_i[1], mx1);
        const float al0 = fexp(m_i[0] - mn0), al1 = fexp(m_i[1] - mn1);
        float rs0 = 0.f, rs1 = 0.f;
        #pragma unroll
        for (int nt = 0; nt < 8; nt++) {
            float p0 = fexp(sc[nt][0] - mn0), p1 = fexp(sc[nt][1] - mn0);
            float p2 = fexp(sc[nt][2] - mn1), p3 = fexp(sc[nt][3] - mn1);
            sc[nt][0] = p0; sc[nt][1] = p1; sc[nt][2] = p2; sc[nt][3] = p3;
            rs0 += p0 + p1; rs1 += p2 + p3;
        }
        rs0 += __shfl_xor_sync(0xffffffffu, rs0, 1);
        rs0 += __shfl_xor_sync(0xffffffffu, rs0, 2);
        rs1 += __shfl_xor_sync(0xffffffffu, rs1, 1);
        rs1 += __shfl_xor_sync(0xffffffffu, rs1, 2);
        l_i[0] = l_i[0] * al0 + rs0;  m_i[0] = mn0;
        l_i[1] = l_i[1] * al1 + rs1;  m_i[1] = mn1;
        #pragma unroll
        for (int dt = 0; dt < 8; dt++) {
            o_acc[dt][0] *= al0; o_acc[dt][1] *= al0;
            o_acc[dt][2] *= al1; o_acc[dt][3] *= al1;
        }
        #pragma unroll
        for (int ks = 0; ks < 4; ks++) {
            uint32_t ph[4], pl_[4];
            const int n0t = 2*ks, n1t = 2*ks + 1;
            ph[0] = pack_hi(sc[n0t][0], sc[n0t][1]); ph[1] = pack_hi(sc[n0t][2], sc[n0t][3]);
            ph[2] = pack_hi(sc[n1t][0], sc[n1t][1]); ph[3] = pack_hi(sc[n1t][2], sc[n1t][3]);
            pl_[0] = pack_lo(sc[n0t][0], sc[n0t][1]); pl_[1] = pack_lo(sc[n0t][2], sc[n0t][3]);
            pl_[2] = pack_lo(sc[n1t][0], sc[n1t][1]); pl_[3] = pack_lo(sc[n1t][2], sc[n1t][3]);
            #pragma unroll
            for (int dg = 0; dg < 4; dg++) {
                uint32_t Vhf[4], Vlf[4];
                const uint32_t voff = (ks*16 + v_row) * 144 + dg*32 + v_byte;
                ldsm4t(Vhf, vbuf + voff);
                ldsm4t(Vlf, vbuf + 9216 + voff);
                #pragma unroll
                for (int hf = 0; hf < 2; hf++) {
                    float* d = o_acc[dg*2 + hf];
                    mma_bf16(d, ph, Vhf + hf*2);
                    mma_bf16(d, pl_, Vhf + hf*2);
                    mma_bf16(d, ph, Vlf + hf*2);
                }
            }
        }
    }
    // epilogue: un-normalized O partial + m/l
    #pragma unroll
    for (int dt = 0; dt < 8; dt++) {
        const int col = dt*8 + tg*2;
        const size_t o0 = base + (size_t)row0 * D + col;
        const size_t o1 = base + (size_t)(row0 + 8) * D + col;
        *(float2*)&Op[o0] = make_float2(o_acc[dt][0], o_acc[dt][1]);
        *(float2*)&Op[o1] = make_float2(o_acc[dt][2], o_acc[dt][3]);
    }
    if (tg == 0) {
        pm[bh * SEQ + row0]     = m_i[0];
        pl[bh * SEQ + row0]     = l_i[0];
        pm[bh * SEQ + row0 + 8] = m_i[1];
        pl[bh * SEQ + row0 + 8] = l_i[1];
    }
}

// merge the two KV-splits: O = (w0 O0 + w1 O1) / (w0 l0 + w1 l1)
__global__ void attn_combine(const float* __restrict__ O0, const float* __restrict__ O1,
                             const float* __restrict__ pm, const float* __restrict__ pl,
                             __nv_bfloat16* __restrict__ Oh, __nv_bfloat16* __restrict__ Ol)
{
    const int t = threadIdx.x;
    const int ridx = blockIdx.x * 8 + (t >> 5);     // 0..NROW-1
    const int cp = (t & 31) * 2;
    const int bh = ridx >> 10, qr = ridx & 1023;
    const int b = bh >> 3, h = bh & 7;
    const size_t off = (size_t)b*SEQ*D + h*64 + (size_t)qr*D + cp;
    float m0 = pm[ridx], m1 = pm[NROW + ridx];
    float l0 = pl[ridx], l1 = pl[NROW + ridx];
    float M = fmaxf(m0, m1);
    float w0 = fexp(m0 - M), w1 = fexp(m1 - M);
    float L = 1.0f / (l0*w0 + l1*w1);
    float2 a = *(const float2*)&O0[off];
    float2 c = *(const float2*)&O1[off];
    float v0 = (w0*a.x + w1*c.x) * L;
    float v1 = (w0*a.y + w1*c.y) * L;
    *(uint32_t*)&Oh[off] = pack_hi(v0, v1);
    *(uint32_t*)&Ol[off] = pack_lo(v0, v1);
}

// -------- fused (residual add + split-K partial add +) LayerNorm --------
__global__ void add_ln_kernel(float* __restrict__ X, const float* __restrict__ R,
                              const float* __restrict__ R2,
                              const float* __restrict__ g, const float* __restrict__ b,
                              __nv_bfloat16* __restrict__ Xh,
                              __nv_bfloat16* __restrict__ Xl)
{
    const int row = blockIdx.x;
    __shared__ float sh[4];
    const int c = threadIdx.x * 4;
    float4 v = *(const float4*)&X[(size_t)row*D + c];
    if (R) {
        float4 r = *(const float4*)&R[(size_t)row*D + c];
        v.x += r.x; v.y += r.y; v.z += r.z; v.w += r.w;
    }
    if (R2) {
        float4 r = *(const float4*)&R2[(size_t)row*D + c];
        v.x += r.x; v.y += r.y; v.z += r.z; v.w += r.w;
    }
    float s = v.x + v.y + v.z + v.w;
    #pragma unroll
    for (int o = 16; o; o >>= 1) s += __shfl_xor_sync(0xffffffffu, s, o);
    if ((threadIdx.x & 31) == 0) sh[threadIdx.x >> 5] = s;
    __syncthreads();
    float mu = (sh[0] + sh[1] + sh[2] + sh[3]) * (1.0f / D);
    float dx = v.x - mu, dy = v.y - mu, dz = v.z - mu, dw = v.w - mu;
    float sq = dx*dx + dy*dy + dz*dz + dw*dw;
    #pragma unroll
    for (int o = 16; o; o >>= 1) sq += __shfl_xor_sync(0xffffffffu, sq, o);
    __syncthreads();
    if ((threadIdx.x & 31) == 0) sh[threadIdx.x >> 5] = sq;
    __syncthreads();
    float var = (sh[0] + sh[1] + sh[2] + sh[3]) * (1.0f / D);
    float inv = rsqrtf(var + 1e-5f);
    float4 gg = *(const float4*)&g[c];
    float4 bb = *(const float4*)&b[c];
    float o0 = dx*inv*gg.x + bb.x, o1 = dy*inv*gg.y + bb.y;
    float o2 = dz*inv*gg.z + bb.z, o3 = dw*inv*gg.w + bb.w;
    const size_t off = (size_t)row*D + c;
    *(float4*)&X[off] = make_float4(o0, o1, o2, o3);
    *(uint32_t*)&Xh[off]     = pack_hi(o0, o1);
    *(uint32_t*)&Xh[off + 2] = pack_hi(o2, o3);
    *(uint32_t*)&Xl[off]     = pack_lo(o0, o1);
    *(uint32_t*)&Xl[off + 2] = pack_lo(o2, o3);
}

// ---------------- host orchestration ----------------
extern "C" void kernel_launch(void* const* d_in, const int* in_sizes, int n_in,
                              void* d_out, int out_size)
{
    const int*   ids  = (const int*)  d_in[0];
    const int*   am   = (const int*)  d_in[1];
    const float* emb  = (const float*)d_in[2];
    const float* wq   = (const float*)d_in[3];  const float* bq = (const float*)d_in[4];
    const float* wk   = (const float*)d_in[5];  const float* bk = (const float*)d_in[6];
    const float* wv   = (const float*)d_in[7];  const float* bv = (const float*)d_in[8];
    const float* wo   = (const float*)d_in[9];  const float* bo = (const float*)d_in[10];
    const float* ln1g = (const float*)d_in[11]; const float* ln1b = (const float*)d_in[12];
    const float* w1   = (const float*)d_in[13]; const float* b1 = (const float*)d_in[14];
    const float* w2   = (const float*)d_in[15]; const float* b2 = (const float*)d_in[16];
    const float* ln2g = (const float*)d_in[17]; const float* ln2b = (const float*)d_in[18];
    const float* lnfg = (const float*)d_in[19]; const float* lnfb = (const float*)d_in[20];
    const float* lmw  = (const float*)d_in[21];
    float* out = (float*)d_out;

    static float *xp = nullptr, *tp, *t2, *pmp, *plp, *bcat;
    static __nv_bfloat16 *xh, *xl, *qh, *ql, *kh, *kl, *vh, *vl, *oh, *ol, *fh, *fl, *wh, *wl;
    if (!xp) {
        cudaGetSymbolAddress((void**)&xp, g_x);
        cudaGetSymbolAddress((void**)&tp, g_t);
        cudaGetSymbolAddress((void**)&t2, g_t2);
        cudaGetSymbolAddress((void**)&pmp, g_pm);
        cudaGetSymbolAddress((void**)&plp, g_pl);
        cudaGetSymbolAddress((void**)&bcat, g_bcat);
        cudaGetSymbolAddress((void**)&xh, g_xh);
        cudaGetSymbolAddress((void**)&xl, g_xl);
        cudaGetSymbolAddress((void**)&qh, g_qh);
        cudaGetSymbolAddress((void**)&ql, g_ql);
        cudaGetSymbolAddress((void**)&kh, g_kh);
        cudaGetSymbolAddress((void**)&kl, g_kl);
        cudaGetSymbolAddress((void**)&vh, g_vh);
        cudaGetSymbolAddress((void**)&vl, g_vl);
        cudaGetSymbolAddress((void**)&oh, g_oh);
        cudaGetSymbolAddress((void**)&ol, g_ol);
        cudaGetSymbolAddress((void**)&fh, g_fh);
        cudaGetSymbolAddress((void**)&fl, g_fl);
        cudaGetSymbolAddress((void**)&wh, g_wh);
        cudaGetSymbolAddress((void**)&wl, g_wl);
        cudaFuncSetAttribute(attn_split, cudaFuncAttributeMaxDynamicSharedMemorySize, ASME);
        cudaFuncSetAttribute(gemm_bf, cudaFuncAttributeMaxDynamicSharedMemorySize, 81920);
    }

    conv_all<<<W_TOTAL/1024, 256>>>(wq, wk, wv, wo, w1, w2, lmw);
    bcat_kernel<<<(NL*3*D + 255)/256, 256>>>(bq, bk, bv);
    detect_ids_kernel<<<1, 256>>>(ids);
    embed_kernel<<<TOK, 128>>>(ids, emb);

    const dim3 gQKV(1536/128, TOK/128);    // (12, 32)
    const dim3 gDs(D/128, TOK/128, 2);     // (4, 32, 2) split-K
    const dim3 gF(FFD/128, TOK/128);       // (16, 32)
    const dim3 gAT(SEQ/128, BB*NH, 2);     // (8, 32, 2) split-KV attention
    for (int l = 0; l < NL; l++) {
        gemm_bf<<<gQKV, 256, 81920>>>(xh, xl,
            wh + OFF_QKV + (size_t)l*3*DD, wl + OFF_QKV + (size_t)l*3*DD,
            bcat + l*1536, nullptr, nullptr, qh, ql, kh, kl, vh, vl, TOK, 1536, D, 0);
        attn_split<<<gAT, 256, ASME>>>(qh, ql, kh, kl, vh, vl, am, tp, t2, pmp, plp);
        attn_combine<<<NROW/8, 256>>>(tp, t2, pmp, plp, oh, ol);
        gemm_bf<<<gDs, 256, 81920>>>(oh, ol,
            wh + OFF_WO + (size_t)l*DD, wl + OFF_WO + (size_t)l*DD,
            bo + l*D, tp, t2, nullptr, nullptr, nullptr, nullptr, nullptr, nullptr,
            TOK, D, D, 0);
        add_ln_kernel<<<TOK, 128>>>(xp, tp, t2, ln1g + l*D, ln1b + l*D, xh, xl);
        gemm_bf<<<gF, 256, 81920>>>(xh, xl,
            wh + OFF_W1 + (size_t)l*FFD*D, wl + OFF_W1 + (size_t)l*FFD*D,
            b1 + l*FFD, nullptr, nullptr, fh, fl, nullptr, nullptr, nullptr, nullptr,
            TOK, FFD, D, 1);
        gemm_bf<<<gDs, 256, 81920>>>(fh, fl,
            wh + OFF_W2 + (size_t)l*D*FFD, wl + OFF_W2 + (size_t)l*D*FFD,
            b2 + l*D, tp, t2, nullptr, nullptr, nullptr, nullptr, nullptr, nullptr,
            TOK, D, FFD, 0);
        add_ln_kernel<<<TOK, 128>>>(xp, tp, t2, ln2g + l*D, ln2b + l*D, xh, xl);
    }
    add_ln_kernel<<<TOK, 128>>>(xp, nullptr, nullptr, lnfg, lnfb, xh, xl);
    gemm_bf<<<gDs, 256, 81920>>>(xh, xl, wh + OFF_LM, wl + OFF_LM,
        nullptr, tp, t2, nullptr, nullptr, nullptr, nullptr, nullptr, nullptr,
        TOK, VOC, D, 0);
    addout_kernel<<<(TOK*VOC)/1024, 256>>>(tp, t2, out);
}

// round 16
// speedup vs baseline: 1.1247x; 1.0087x over previous
#include <cuda_runtime.h>
#include <cuda_bf16.h>
#include <cstdint>

#define D   512
#define SEQ 1024
#define BB  4
#define NH  8
#define NL  6
#define FFD 2048
#define VOC 512
#define TOK (BB*SEQ)   // 4096
#define DD  (D*D)
#define NROW (BB*NH*SEQ)   // 32768 (b,h,s) rows

// weight scratch offsets (element counts into g_wh/g_wl)
#define OFF_QKV 0
#define OFF_WO  (18*DD)
#define OFF_W1  (24*DD)
#define OFF_W2  (OFF_W1 + 6*FFD*D)
#define OFF_LM  (OFF_W2 + 6*D*FFD)
#define W_TOTAL (OFF_LM + VOC*D)
#define BC_TOTAL (NL*3*D)

// ---------------- device scratch (no allocations allowed) ----------------
__device__ float g_t[TOK*D];               // split-K / attn partial 0
__device__ float g_t2[TOK*D];              // split-K / attn partial 1
__device__ float g_pm[2*NROW], g_pl[2*NROW];  // attn partial m/l
__device__ float g_bcat[BC_TOTAL];
__device__ __nv_bfloat16 g_xh[TOK*D],  g_xl[TOK*D];    // residual hi/lo
__device__ __nv_bfloat16 g_qh[TOK*D],  g_ql[TOK*D];
__device__ __nv_bfloat16 g_kh[TOK*D],  g_kl[TOK*D];
__device__ __nv_bfloat16 g_vh[TOK*D],  g_vl[TOK*D];
__device__ __nv_bfloat16 g_oh[TOK*D],  g_ol[TOK*D];
__device__ __nv_bfloat16 g_fh[TOK*FFD], g_fl[TOK*FFD];
__device__ __nv_bfloat16 g_wh[W_TOTAL], g_wl[W_TOTAL];
__device__ int g_idmode;

// ---------------- helpers ----------------
__device__ __forceinline__ uint32_t smem_u32(const void* p) {
    uint32_t a;
    asm("{ .reg .u64 t; cvta.to.shared.u64 t, %1; cvt.u32.u64 %0, t; }"
        : "=r"(a) : "l"(p));
    return a;
}
__device__ __forceinline__ void ldsm4(uint32_t* r, uint32_t addr) {
    asm volatile("ldmatrix.sync.aligned.m8n8.x4.shared.b16 {%0,%1,%2,%3}, [%4];"
                 : "=r"(r[0]), "=r"(r[1]), "=r"(r[2]), "=r"(r[3]) : "r"(addr));
}
__device__ __forceinline__ void ldsm4t(uint32_t* r, uint32_t addr) {
    asm volatile("ldmatrix.sync.aligned.m8n8.x4.trans.shared.b16 {%0,%1,%2,%3}, [%4];"
                 : "=r"(r[0]), "=r"(r[1]), "=r"(r[2]), "=r"(r[3]) : "r"(addr));
}
__device__ __forceinline__ void mma_bf16(float* d, const uint32_t* a,
                                         const uint32_t* b) {
    asm volatile("mma.sync.aligned.m16n8k16.row.col.f32.bf16.bf16.f32 "
                 "{%0,%1,%2,%3}, {%4,%5,%6,%7}, {%8,%9}, {%0,%1,%2,%3};"
                 : "+f"(d[0]), "+f"(d[1]), "+f"(d[2]), "+f"(d[3])
                 : "r"(a[0]), "r"(a[1]), "r"(a[2]), "r"(a[3]),
                   "r"(b[0]), "r"(b[1]));
}
#define CPA(dst, src) \
    asm volatile("cp.async.ca.shared.global [%0], [%1], 16;" :: "r"(dst), "l"(src))
#define CPC()  asm volatile("cp.async.commit_group;" ::: "memory")
#define CPW0() asm volatile("cp.async.wait_group 0;" ::: "memory")

__device__ __forceinline__ uint32_t pack_hi(float a, float b) {
    return (uint32_t)__bfloat16_as_ushort(__float2bfloat16(a)) |
           ((uint32_t)__bfloat16_as_ushort(__float2bfloat16(b)) << 16);
}
__device__ __forceinline__ uint32_t pack_lo(float a, float b) {
    float ra = a - __bfloat162float(__float2bfloat16(a));
    float rb = b - __bfloat162float(__float2bfloat16(b));
    return (uint32_t)__bfloat16_as_ushort(__float2bfloat16(ra)) |
           ((uint32_t)__bfloat16_as_ushort(__float2bfloat16(rb)) << 16);
}
__device__ __forceinline__ float bf_lo16(uint32_t w) {
    return __bfloat162float(__ushort_as_bfloat16((unsigned short)(w & 0xffff)));
}
__device__ __forceinline__ float bf_hi16(uint32_t w) {
    return __bfloat162float(__ushort_as_bfloat16((unsigned short)(w >> 16)));
}
__device__ __forceinline__ float fexp(float x) {
    x = fmaxf(x, -80.0f);
    float t = x * 1.4426950408889634f;
    float fi = rintf(t);
    float f = t - fi;
    float p =              1.3333558146e-3f;
    p = fmaf(p, f, 9.6180209764e-3f);
    p = fmaf(p, f, 5.5504108664e-2f);
    p = fmaf(p, f, 2.4022650695e-1f);
    p = fmaf(p, f, 6.9314718056e-1f);
    p = fmaf(p, f, 1.0f);
    return __int_as_float(((int)fi + 127) << 23) * p;
}

// ---- fused weight conversion + qkv bias concat: one launch -------------
__global__ void conv_all(const float* __restrict__ wq, const float* __restrict__ wk,
                         const float* __restrict__ wv, const float* __restrict__ wo,
                         const float* __restrict__ w1, const float* __restrict__ w2,
                         const float* __restrict__ lmw,
                         const float* __restrict__ bq, const float* __restrict__ bk,
                         const float* __restrict__ bv)
{
    long i = ((long)blockIdx.x * 256 + threadIdx.x) * 4;
    if (i >= W_TOTAL) {                    // tail range: qkv bias concat
        long j = i - W_TOTAL;
        if (j >= BC_TOTAL) return;
        int l = (int)(j / (3 * D)), r = (int)(j % (3 * D));
        int part = r >> 9, d = r & 511;    // groups of 4 never cross parts
        const float* s = part == 0 ? bq : part == 1 ? bk : bv;
        float4 v = *(const float4*)(s + l * D + d);
        *(float4*)&g_bcat[j] = v;
        return;
    }
    const float* src;
    size_t d;
    if (i < 6L*DD) {
        long j = i;  long l = j / DD, r = j - l * DD;
        src = wq + j;  d = (size_t)l * 3 * DD + r;
    } else if (i < 12L*DD) {
        long j = i - 6L*DD;  long l = j / DD, r = j - l * DD;
        src = wk + j;  d = (size_t)l * 3 * DD + DD + r;
    } else if (i < 18L*DD) {
        long j = i - 12L*DD;  long l = j / DD, r = j - l * DD;
        src = wv + j;  d = (size_t)l * 3 * DD + 2 * DD + r;
    } else if (i < 24L*DD) {
        long j = i - 18L*DD;  src = wo + j;  d = OFF_WO + j;
    } else if (i < 24L*DD + 6L*FFD*D) {
        long j = i - 24L*DD;  src = w1 + j;  d = OFF_W1 + j;
    } else if (i < 24L*DD + 12L*FFD*D) {
        long j = i - (24L*DD + 6L*FFD*D);  src = w2 + j;  d = OFF_W2 + j;
    } else {
        long j = i - (24L*DD + 12L*FFD*D);  src = lmw + j;  d = OFF_LM + j;
    }
    float4 v = *(const float4*)src;
    *(uint32_t*)&g_wh[d]     = pack_hi(v.x, v.y);
    *(uint32_t*)&g_wh[d + 2] = pack_hi(v.z, v.w);
    *(uint32_t*)&g_wl[d]     = pack_lo(v.x, v.y);
    *(uint32_t*)&g_wl[d + 2] = pack_lo(v.z, v.w);
}

__global__ void addout_kernel(const float* __restrict__ a,
                              const float* __restrict__ b,
                              float* __restrict__ o)
{
    int i = (blockIdx.x * 256 + threadIdx.x) * 4;
    float4 x = *(const float4*)&a[i];
    float4 y = *(const float4*)&b[i];
    *(float4*)&o[i] = make_float4(x.x + y.x, x.y + y.y, x.z + y.z, x.w + y.w);
}

__global__ void detect_ids_kernel(const int* __restrict__ p) {
    __shared__ int any;
    if (threadIdx.x == 0) any = 0;
    __syncthreads();
    int loc = 0;
    for (int i = threadIdx.x; i < 2048; i += blockDim.x) loc |= p[2*i + 1];
    if (loc) atomicOr(&any, 1);
    __syncthreads();
    if (threadIdx.x == 0) g_idmode = any ? 1 : 0;
}

__global__ void embed_kernel(const int* __restrict__ ids,
                             const float* __restrict__ emb) {
    int bs = blockIdx.x;
    int s  = bs & (SEQ - 1);
    int id = g_idmode ? ids[bs] : ids[2*bs];
    const float* e = emb + (size_t)id * D;
    const float c = -9.210340371976184f / 512.0f;
    const int d0 = threadIdx.x * 4;
    float v[4];
    #pragma unroll
    for (int j = 0; j < 4; j++) {
        int d = d0 + j;
        float ang = (float)s * expf(c * (float)(d & ~1));
        float pe  = (d & 1) ? cosf(ang) : sinf(ang);
        v[j] = e[d] * 22.627416997969522f + pe;
    }
    const size_t off = (size_t)bs * D + d0;
    *(uint32_t*)&g_xh[off]     = pack_hi(v[0], v[1]);
    *(uint32_t*)&g_xh[off + 2] = pack_hi(v[2], v[3]);
    *(uint32_t*)&g_xl[off]     = pack_lo(v[0], v[1]);
    *(uint32_t*)&g_xl[off + 2] = pack_lo(v[2], v[3]);
}

// =====================================================================
// bf16 tensor-core GEMM 128x128, 2-stage cp.async, optional split-K.
// =====================================================================
__device__ __forceinline__ void load_chunk128(
    uint32_t sbuf,
    const __nv_bfloat16* __restrict__ Ah, const __nv_bfloat16* __restrict__ Al,
    const __nv_bfloat16* __restrict__ Wh, const __nv_bfloat16* __restrict__ Wl,
    int m0, int n0, int K, int kc, int tid)
{
    #pragma unroll
    for (int t = 0; t < 4; t++) {
        int s = tid + t * 256;
        int reg = s >> 9;
        int row = (s >> 2) & 127;
        int seg = s & 3;
        uint32_t dst = sbuf + reg * 10240 + row * 80 + seg * 16;
        const __nv_bfloat16* src = (reg ? Al : Ah) + (size_t)(m0 + row) * K + kc + seg * 8;
        CPA(dst, src);
    }
    #pragma unroll
    for (int t = 0; t < 4; t++) {
        int s = tid + t * 256;
        int reg = s >> 9;
        int row = (s >> 2) & 127;
        int seg = s & 3;
        uint32_t dst = sbuf + 20480 + reg * 10240 + row * 80 + seg * 16;
        const __nv_bfloat16* src = (reg ? Wl : Wh) + (size_t)(n0 + row) * K + kc + seg * 8;
        CPA(dst, src);
    }
}

__global__ void __launch_bounds__(256, 2) gemm_bf(
    const __nv_bfloat16* __restrict__ Ah, const __nv_bfloat16* __restrict__ Al,
    const __nv_bfloat16* __restrict__ Wh, const __nv_bfloat16* __restrict__ Wl,
    const float* __restrict__ bias, float* __restrict__ C,
    float* __restrict__ C2,
    __nv_bfloat16* __restrict__ Ch, __nv_bfloat16* __restrict__ Cl,
    __nv_bfloat16* __restrict__ KH, __nv_bfloat16* __restrict__ KL,
    __nv_bfloat16* __restrict__ VH, __nv_bfloat16* __restrict__ VL,
    int M, int N, int K, int relu)
{
    extern __shared__ char sm[];
    const uint32_t smb = smem_u32(sm);
    constexpr int BUFSZ = 40960;
    const int tid = threadIdx.x, wid = tid >> 5, lane = tid & 31;
    const int wm = wid >> 2;
    const int wn = wid & 3;
    const int m0 = blockIdx.y << 7;
    const int n0 = blockIdx.x << 7;
    const int zz = blockIdx.z;
    const int kslice = K / gridDim.z;
    const int kbase0 = zz * kslice;
    const int a_row = lane & 15,  a_kb = lane & 16;
    const int b_row = ((lane >> 4) << 3) + (lane & 7), b_kb = ((lane >> 3) & 1) << 4;

    float acc[4][4][4];
    #pragma unroll
    for (int i = 0; i < 4; i++)
        #pragma unroll
        for (int j = 0; j < 4; j++)
            #pragma unroll
            for (int t = 0; t < 4; t++) acc[i][j][t] = 0.0f;

    const int nch = kslice >> 5;
    load_chunk128(smb, Ah, Al, Wh, Wl, m0, n0, K, kbase0, tid);
    CPC();
    for (int c = 0; c < nch; c++) {
        CPW0();
        __syncthreads();
        if (c + 1 < nch) {
            load_chunk128(smb + ((c + 1) & 1) * BUFSZ, Ah, Al, Wh, Wl,
                          m0, n0, K, kbase0 + ((c + 1) << 5), tid);
            CPC();
        }
        const uint32_t ab = smb + (c & 1) * BUFSZ;
        const uint32_t wb = ab + 20480;
        #pragma unroll
        for (int ks = 0; ks < 2; ks++) {
            const int kbyte = ks * 32;
            uint32_t Bh[2][4], Bl[2][4];
            #pragma unroll
            for (int ng = 0; ng < 2; ng++) {
                const uint32_t roff = (wn*32 + ng*16 + b_row) * 80 + kbyte + b_kb;
                ldsm4(Bh[ng], wb + roff);
                ldsm4(Bl[ng], wb + 10240 + roff);
            }
            #pragma unroll
            for (int mt = 0; mt < 4; mt++) {
                uint32_t Af[4], Alf[4];
                const uint32_t aoff = (wm*64 + mt*16 + a_row) * 80 + kbyte + a_kb;
                ldsm4(Af,  ab + aoff);
                ldsm4(Alf, ab + 10240 + aoff);
                #pragma unroll
                for (int ng = 0; ng < 2; ng++)
                    #pragma unroll
                    for (int hf = 0; hf < 2; hf++) {
                        float* d = acc[mt][ng*2 + hf];
                        mma_bf16(d, Af,  Bh[ng] + hf*2);
                        mma_bf16(d, Alf, Bh[ng] + hf*2);
                        mma_bf16(d, Af,  Bl[ng] + hf*2);
                    }
            }
        }
        __syncthreads();
    }

    __nv_bfloat16 *oh_ = Ch, *ol_ = Cl;
    float* Cout = (zz == 0) ? C : C2;
    const float* bia = (zz == 0) ? bias : nullptr;
    int nst = N, nbase = n0;
    if (KH) {
        const int part = n0 >> 9;
        if (part == 1)      { oh_ = KH; ol_ = KL; }
        else if (part == 2) { oh_ = VH; ol_ = VL; }
        nbase = n0 & 511;
        nst = 512;
    }
    const int g = lane >> 2, tg = lane & 3;
    #pragma unroll
    for (int mt = 0; mt < 4; mt++) {
        #pragma unroll
        for (int nt = 0; nt < 4; nt++) {
            const int row  = m0 + wm*64 + mt*16 + g;
            const int colb = n0 + wn*32 + nt*8 + tg*2;
            const int cols = nbase + wn*32 + nt*8 + tg*2;
            float b0 = bia ? bia[colb]     : 0.0f;
            float b1 = bia ? bia[colb + 1] : 0.0f;
            float v0 = acc[mt][nt][0] + b0, v1 = acc[mt][nt][1] + b1;
            float v2 = acc[mt][nt][2] + b0, v3 = acc[mt][nt][3] + b1;
            if (relu) {
                v0 = fmaxf(v0, 0.f); v1 = fmaxf(v1, 0.f);
                v2 = fmaxf(v2, 0.f); v3 = fmaxf(v3, 0.f);
            }
            const size_t o0 = (size_t)row * nst + cols;
            const size_t o1 = (size_t)(row + 8) * nst + cols;
            if (Cout) {
                *(float2*)&Cout[o0] = make_float2(v0, v1);
                *(float2*)&Cout[o1] = make_float2(v2, v3);
            }
            if (oh_) {
                *(uint32_t*)&oh_[o0] = pack_hi(v0, v1);
                *(uint32_t*)&oh_[o1] = pack_hi(v2, v3);
                *(uint32_t*)&ol_[o0] = pack_lo(v0, v1);
                *(uint32_t*)&ol_[o1] = pack_lo(v2, v3);
            }
        }
    }
}

// =====================================================================
// Split-KV tensor-core flash attention (causal). blockIdx.z halves the
// k-range. Writes UN-normalized fp32 O partial + per-row (m,l).
// =====================================================================
#define KVB(i) ((i) * 36864)
#define AAM    73728
#define ASME   (AAM + 512)

__global__ void __launch_bounds__(256) attn_split(
    const __nv_bfloat16* __restrict__ Qh, const __nv_bfloat16* __restrict__ Ql,
    const __nv_bfloat16* __restrict__ Kh, const __nv_bfloat16* __restrict__ Kl,
    const __nv_bfloat16* __restrict__ Vh, const __nv_bfloat16* __restrict__ Vl,
    const int* __restrict__ amask,
    float* __restrict__ Op0, float* __restrict__ Op1,
    float* __restrict__ pmA, float* __restrict__ plA)
{
    extern __shared__ char sm[];
    const uint32_t smb = smem_u32(sm);
    int* am_s = (int*)(sm + AAM);
    const int qt = blockIdx.x, bh = blockIdx.y, zz = blockIdx.z;
    const int b = bh >> 3, h = bh & 7;
    const int tid = threadIdx.x, wid = tid >> 5, lane = tid & 31;
    const int g = lane >> 2, tg = lane & 3;
    const size_t base = (size_t)b * SEQ * D + h * 64;
    const int q0 = qt * 128;
    const int nkt = qt + 1;
    const int kstart = zz * nkt;
    float* Op = zz ? Op1 : Op0;
    float* pm = pmA + zz * NROW;
    float* pl = plA + zz * NROW;
    const int a_row = lane & 15, a_kb = lane & 16;
    const int b_row = ((lane >> 4) << 3) + (lane & 7), b_kb = ((lane >> 3) & 1) << 4;
    const int v_row = (((lane >> 3) & 1) << 3) + (lane & 7), v_byte = (lane >> 4) << 4;

    #pragma unroll
    for (int t = 0; t < 8; t++) {
        int s = tid + t * 256;
        int reg = s >> 10, row = (s >> 3) & 127, seg = s & 7;
        uint32_t dst = smb + KVB(1) + reg * 18432 + row * 144 + seg * 16;
        const __nv_bfloat16* src = (reg ? Ql : Qh) + base + (size_t)(q0 + row) * D + seg * 8;
        CPA(dst, src);
    }
    CPC(); CPW0();
    __syncthreads();
    uint32_t qhf[4][4], qlf[4][4];
    #pragma unroll
    for (int ks = 0; ks < 4; ks++) {
        const uint32_t off = (wid*16 + a_row) * 144 + ks*32 + a_kb;
        ldsm4(qhf[ks], smb + KVB(1) + off);
        ldsm4(qlf[ks], smb + KVB(1) + 18432 + off);
    }

    float m_i[2] = {-1e30f, -1e30f}, l_i[2] = {0.f, 0.f};
    float o_acc[8][4];
    #pragma unroll
    for (int i = 0; i < 8; i++)
        #pragma unroll
        for (int j = 0; j < 4; j++) o_acc[i][j] = 0.f;

    const int row0 = q0 + wid*16 + g;

    {
        const uint32_t kv = smb + KVB(0);
        const size_t kb = base + (size_t)(kstart * 64) * D;
        #pragma unroll
        for (int t = 0; t < 4; t++) {
            int s = tid + t * 256;
            int reg = s >> 9, row = (s >> 3) & 63, seg = s & 7;
            CPA(kv + reg * 9216 + row * 144 + seg * 16,
                (reg ? Kl : Kh) + kb + (size_t)row * D + seg * 8);
        }
        #pragma unroll
        for (int t = 0; t < 4; t++) {
            int s = tid + t * 256;
            int reg = s >> 9, row = (s >> 3) & 63, seg = s & 7;
            CPA(kv + 18432 + reg * 9216 + row * 144 + seg * 16,
                (reg ? Vl : Vh) + kb + (size_t)row * D + seg * 8);
        }
        if (tid < 64) am_s[tid] = amask[b * SEQ + kstart * 64 + tid];
        CPC();
    }

    for (int j = 0; j < nkt; j++) {
        const int kt = kstart + j;
        CPW0();
        __syncthreads();
        if (j + 1 < nkt) {
            const uint32_t kv = smb + KVB((j + 1) & 1);
            const size_t kb = base + (size_t)((kt + 1) * 64) * D;
            #pragma unroll
            for (int t = 0; t < 4; t++) {
                int s = tid + t * 256;
                int reg = s >> 9, row = (s >> 3) & 63, seg = s & 7;
                CPA(kv + reg * 9216 + row * 144 + seg * 16,
                    (reg ? Kl : Kh) + kb + (size_t)row * D + seg * 8);
            }
            #pragma unroll
            for (int t = 0; t < 4; t++) {
                int s = tid + t * 256;
                int reg = s >> 9, row = (s >> 3) & 63, seg = s & 7;
                CPA(kv + 18432 + reg * 9216 + row * 144 + seg * 16,
                    (reg ? Vl : Vh) + kb + (size_t)row * D + seg * 8);
            }
            if (tid < 64) am_s[((j + 1) & 1) * 64 + tid] = amask[b * SEQ + (kt + 1) * 64 + tid];
            CPC();
        }
        const uint32_t kbuf = smb + KVB(j & 1);
        const uint32_t vbuf = kbuf + 18432;
        const int* am = am_s + (j & 1) * 64;

        float sc[8][4];
        #pragma unroll
        for (int i = 0; i < 8; i++)
            #pragma unroll
            for (int jj = 0; jj < 4; jj++) sc[i][jj] = 0.f;
        #pragma unroll
        for (int ks = 0; ks < 4; ks++) {
            #pragma unroll
            for (int ng = 0; ng < 4; ng++) {
                uint32_t Bh[4], Bl[4];
                const uint32_t roff = (ng*16 + b_row) * 144 + ks*32 + b_kb;
                ldsm4(Bh, kbuf + roff);
                ldsm4(Bl, kbuf + 9216 + roff);
                #pragma unroll
                for (int hf = 0; hf < 2; hf++) {
                    float* d = sc[ng*2 + hf];
                    mma_bf16(d, qhf[ks], Bh + hf*2);
                    mma_bf16(d, qlf[ks], Bh + hf*2);
                    mma_bf16(d, qhf[ks], Bl + hf*2);
                }
            }
        }
        float mx0 = -1e30f, mx1 = -1e30f;
        #pragma unroll
        for (int nt = 0; nt < 8; nt++) {
            const int c0 = nt*8 + tg*2, c1 = c0 + 1;
            const int col0 = kt*64 + c0, col1 = col0 + 1;
            const int ok0 = am[c0], ok1 = am[c1];
            float s0 = sc[nt][0] * 0.125f, s1 = sc[nt][1] * 0.125f;
            float s2 = sc[nt][2] * 0.125f, s3 = sc[nt][3] * 0.125f;
            if (col0 > row0     || !ok0) s0 = -1e9f;
            if (col1 > row0     || !ok1) s1 = -1e9f;
            if (col0 > row0 + 8 || !ok0) s2 = -1e9f;
            if (col1 > row0 + 8 || !ok1) s3 = -1e9f;
            sc[nt][0] = s0; sc[nt][1] = s1; sc[nt][2] = s2; sc[nt][3] = s3;
            mx0 = fmaxf(mx0, fmaxf(s0, s1));
            mx1 = fmaxf(mx1, fmaxf(s2, s3));
        }
        mx0 = fmaxf(mx0, __shfl_xor_sync(0xffffffffu, mx0, 1));
        mx0 = fmaxf(mx0, __shfl_xor_sync(0xffffffffu, mx0, 2));
        mx1 = fmaxf(mx1, __shfl_xor_sync(0xffffffffu, mx1, 1));
        mx1 = fmaxf(mx1, __shfl_xor_sync(0xffffffffu, mx1, 2));
        const float mn0 = fmaxf(m_i[0], mx0), mn1 = fmaxf(m_i[1], mx1);
        const float al0 = fexp(m_i[0] - mn0), al1 = fexp(m_i[1] - mn1);
        float rs0 = 0.f, rs1 = 0.f;
        #pragma unroll
        for (int nt = 0; nt < 8; nt++) {
            float p0 = fexp(sc[nt][0] - mn0), p1 = fexp(sc[nt][1] - mn0);
            float p2 = fexp(sc[nt][2] - mn1), p3 = fexp(sc[nt][3] - mn1);
            sc[nt][0] = p0; sc[nt][1] = p1; sc[nt][2] = p2; sc[nt][3] = p3;
            rs0 += p0 + p1; rs1 += p2 + p3;
        }
        rs0 += __shfl_xor_sync(0xffffffffu, rs0, 1);
        rs0 += __shfl_xor_sync(0xffffffffu, rs0, 2);
        rs1 += __shfl_xor_sync(0xffffffffu, rs1, 1);
        rs1 += __shfl_xor_sync(0xffffffffu, rs1, 2);
        l_i[0] = l_i[0] * al0 + rs0;  m_i[0] = mn0;
        l_i[1] = l_i[1] * al1 + rs1;  m_i[1] = mn1;
        #pragma unroll
        for (int dt = 0; dt < 8; dt++) {
            o_acc[dt][0] *= al0; o_acc[dt][1] *= al0;
            o_acc[dt][2] *= al1; o_acc[dt][3] *= al1;
        }
        #pragma unroll
        for (int ks = 0; ks < 4; ks++) {
            uint32_t ph[4], pl_[4];
            const int n0t = 2*ks, n1t = 2*ks + 1;
            ph[0] = pack_hi(sc[n0t][0], sc[n0t][1]); ph[1] = pack_hi(sc[n0t][2], sc[n0t][3]);
            ph[2] = pack_hi(sc[n1t][0], sc[n1t][1]); ph[3] = pack_hi(sc[n1t][2], sc[n1t][3]);
            pl_[0] = pack_lo(sc[n0t][0], sc[n0t][1]); pl_[1] = pack_lo(sc[n0t][2], sc[n0t][3]);
            pl_[2] = pack_lo(sc[n1t][0], sc[n1t][1]); pl_[3] = pack_lo(sc[n1t][2], sc[n1t][3]);
            #pragma unroll
            for (int dg = 0; dg < 4; dg++) {
                uint32_t Vhf[4], Vlf[4];
                const uint32_t voff = (ks*16 + v_row) * 144 + dg*32 + v_byte;
                ldsm4t(Vhf, vbuf + voff);
                ldsm4t(Vlf, vbuf + 9216 + voff);
                #pragma unroll
                for (int hf = 0; hf < 2; hf++) {
                    float* d = o_acc[dg*2 + hf];
                    mma_bf16(d, ph, Vhf + hf*2);
                    mma_bf16(d, pl_, Vhf + hf*2);
                    mma_bf16(d, ph, Vlf + hf*2);
                }
            }
        }
    }
    #pragma unroll
    for (int dt = 0; dt < 8; dt++) {
        const int col = dt*8 + tg*2;
        const size_t o0 = base + (size_t)row0 * D + col;
        const size_t o1 = base + (size_t)(row0 + 8) * D + col;
        *(float2*)&Op[o0] = make_float2(o_acc[dt][0], o_acc[dt][1]);
        *(float2*)&Op[o1] = make_float2(o_acc[dt][2], o_acc[dt][3]);
    }
    if (tg == 0) {
        pm[bh * SEQ + row0]     = m_i[0];
        pl[bh * SEQ + row0]     = l_i[0];
        pm[bh * SEQ + row0 + 8] = m_i[1];
        pl[bh * SEQ + row0 + 8] = l_i[1];
    }
}

__global__ void attn_combine(const float* __restrict__ O0, const float* __restrict__ O1,
                             const float* __restrict__ pm, const float* __restrict__ pl,
                             __nv_bfloat16* __restrict__ Oh, __nv_bfloat16* __restrict__ Ol)
{
    const int t = threadIdx.x;
    const int ridx = blockIdx.x * 8 + (t >> 5);
    const int cp = (t & 31) * 2;
    const int bh = ridx >> 10, qr = ridx & 1023;
    const int b = bh >> 3, h = bh & 7;
    const size_t off = (size_t)b*SEQ*D + h*64 + (size_t)qr*D + cp;
    float m0 = pm[ridx], m1 = pm[NROW + ridx];
    float l0 = pl[ridx], l1 = pl[NROW + ridx];
    float M = fmaxf(m0, m1);
    float w0 = fexp(m0 - M), w1 = fexp(m1 - M);
    float L = 1.0f / (l0*w0 + l1*w1);
    float2 a = *(const float2*)&O0[off];
    float2 c = *(const float2*)&O1[off];
    float v0 = (w0*a.x + w1*c.x) * L;
    float v1 = (w0*a.y + w1*c.y) * L;
    *(uint32_t*)&Oh[off] = pack_hi(v0, v1);
    *(uint32_t*)&Ol[off] = pack_lo(v0, v1);
}

// -------- fused (residual add + split-K partial add +) LayerNorm --------
// residual carried as bf16 hi/lo pair (reconstruct x = hi + lo)
__global__ void add_ln_kernel(const float* __restrict__ R,
                              const float* __restrict__ R2,
                              const float* __restrict__ g, const float* __restrict__ b,
                              __nv_bfloat16* __restrict__ Xh,
                              __nv_bfloat16* __restrict__ Xl)
{
    const int row = blockIdx.x;
    __shared__ float sh[4];
    const int c = threadIdx.x * 4;
    const size_t off = (size_t)row*D + c;
    uint32_t h01 = *(uint32_t*)&Xh[off], h23 = *(uint32_t*)&Xh[off + 2];
    uint32_t l01 = *(uint32_t*)&Xl[off], l23 = *(uint32_t*)&Xl[off + 2];
    float4 v;
    v.x = bf_lo16(h01) + bf_lo16(l01);
    v.y = bf_hi16(h01) + bf_hi16(l01);
    v.z = bf_lo16(h23) + bf_lo16(l23);
    v.w = bf_hi16(h23) + bf_hi16(l23);
    if (R) {
        float4 r = *(const float4*)&R[off];
        v.x += r.x; v.y += r.y; v.z += r.z; v.w += r.w;
    }
    if (R2) {
        float4 r = *(const float4*)&R2[off];
        v.x += r.x; v.y += r.y; v.z += r.z; v.w += r.w;
    }
    float s = v.x + v.y + v.z + v.w;
    #pragma unroll
    for (int o = 16; o; o >>= 1) s += __shfl_xor_sync(0xffffffffu, s, o);
    if ((threadIdx.x & 31) == 0) sh[threadIdx.x >> 5] = s;
    __syncthreads();
    float mu = (sh[0] + sh[1] + sh[2] + sh[3]) * (1.0f / D);
    float dx = v.x - mu, dy = v.y - mu, dz = v.z - mu, dw = v.w - mu;
    float sq = dx*dx + dy*dy + dz*dz + dw*dw;
    #pragma unroll
    for (int o = 16; o; o >>= 1) sq += __shfl_xor_sync(0xffffffffu, sq, o);
    __syncthreads();
    if ((threadIdx.x & 31) == 0) sh[threadIdx.x >> 5] = sq;
    __syncthreads();
    float var = (sh[0] + sh[1] + sh[2] + sh[3]) * (1.0f / D);
    float inv = rsqrtf(var + 1e-5f);
    float4 gg = *(const float4*)&g[c];
    float4 bb = *(const float4*)&b[c];
    float o0 = dx*inv*gg.x + bb.x, o1 = dy*inv*gg.y + bb.y;
    float o2 = dz*inv*gg.z + bb.z, o3 = dw*inv*gg.w + bb.w;
    *(uint32_t*)&Xh[off]     = pack_hi(o0, o1);
    *(uint32_t*)&Xh[off + 2] = pack_hi(o2, o3);
    *(uint32_t*)&Xl[off]     = pack_lo(o0, o1);
    *(uint32_t*)&Xl[off + 2] = pack_lo(o2, o3);
}

// ---------------- host orchestration ----------------
extern "C" void kernel_launch(void* const* d_in, const int* in_sizes, int n_in,
                              void* d_out, int out_size)
{
    const int*   ids  = (const int*)  d_in[0];
    const int*   am   = (const int*)  d_in[1];
    const float* emb  = (const float*)d_in[2];
    const float* wq   = (const float*)d_in[3];  const float* bq = (const float*)d_in[4];
    const float* wk   = (const float*)d_in[5];  const float* bk = (const float*)d_in[6];
    const float* wv   = (const float*)d_in[7];  const float* bv = (const float*)d_in[8];
    const float* wo   = (const float*)d_in[9];  const float* bo = (const float*)d_in[10];
    const float* ln1g = (const float*)d_in[11]; const float* ln1b = (const float*)d_in[12];
    const float* w1   = (const float*)d_in[13]; const float* b1 = (const float*)d_in[14];
    const float* w2   = (const float*)d_in[15]; const float* b2 = (const float*)d_in[16];
    const float* ln2g = (const float*)d_in[17]; const float* ln2b = (const float*)d_in[18];
    const float* lnfg = (const float*)d_in[19]; const float* lnfb = (const float*)d_in[20];
    const float* lmw  = (const float*)d_in[21];
    float* out = (float*)d_out;

    static float *tp = nullptr, *t2, *pmp, *plp, *bcat;
    static __nv_bfloat16 *xh, *xl, *qh, *ql, *kh, *kl, *vh, *vl, *oh, *ol, *fh, *fl, *wh, *wl;
    if (!tp) {
        cudaGetSymbolAddress((void**)&tp, g_t);
        cudaGetSymbolAddress((void**)&t2, g_t2);
        cudaGetSymbolAddress((void**)&pmp, g_pm);
        cudaGetSymbolAddress((void**)&plp, g_pl);
        cudaGetSymbolAddress((void**)&bcat, g_bcat);
        cudaGetSymbolAddress((void**)&xh, g_xh);
        cudaGetSymbolAddress((void**)&xl, g_xl);
        cudaGetSymbolAddress((void**)&qh, g_qh);
        cudaGetSymbolAddress((void**)&ql, g_ql);
        cudaGetSymbolAddress((void**)&kh, g_kh);
        cudaGetSymbolAddress((void**)&kl, g_kl);
        cudaGetSymbolAddress((void**)&vh, g_vh);
        cudaGetSymbolAddress((void**)&vl, g_vl);
        cudaGetSymbolAddress((void**)&oh, g_oh);
        cudaGetSymbolAddress((void**)&ol, g_ol);
        cudaGetSymbolAddress((void**)&fh, g_fh);
        cudaGetSymbolAddress((void**)&fl, g_fl);
        cudaGetSymbolAddress((void**)&wh, g_wh);
        cudaGetSymbolAddress((void**)&wl, g_wl);
        cudaFuncSetAttribute(attn_split, cudaFuncAttributeMaxDynamicSharedMemorySize, ASME);
        cudaFuncSetAttribute(gemm_bf, cudaFuncAttributeMaxDynamicSharedMemorySize, 81920);
    }

    conv_all<<<(W_TOTAL + BC_TOTAL)/1024, 256>>>(wq, wk, wv, wo, w1, w2, lmw, bq, bk, bv);
    detect_ids_kernel<<<1, 256>>>(ids);
    embed_kernel<<<TOK, 128>>>(ids, emb);

    const dim3 gQKV(1536/128, TOK/128);    // (12, 32)
    const dim3 gDs(D/128, TOK/128, 2);     // (4, 32, 2) split-K
    const dim3 gF(FFD/128, TOK/128);       // (16, 32)
    const dim3 gAT(SEQ/128, BB*NH, 2);     // (8, 32, 2) split-KV attention
    for (int l = 0; l < NL; l++) {
        gemm_bf<<<gQKV, 256, 81920>>>(xh, xl,
            wh + OFF_QKV + (size_t)l*3*DD, wl + OFF_QKV + (size_t)l*3*DD,
            bcat + l*1536, nullptr, nullptr, qh, ql, kh, kl, vh, vl, TOK, 1536, D, 0);
        attn_split<<<gAT, 256, ASME>>>(qh, ql, kh, kl, vh, vl, am, tp, t2, pmp, plp);
        attn_combine<<<NROW/8, 256>>>(tp, t2, pmp, plp, oh, ol);
        gemm_bf<<<gDs, 256, 81920>>>(oh, ol,
            wh + OFF_WO + (size_t)l*DD, wl + OFF_WO + (size_t)l*DD,
            bo + l*D, tp, t2, nullptr, nullptr, nullptr, nullptr, nullptr, nullptr,
            TOK, D, D, 0);
        add_ln_kernel<<<TOK, 128>>>(tp, t2, ln1g + l*D, ln1b + l*D, xh, xl);
        gemm_bf<<<gF, 256, 81920>>>(xh, xl,
            wh + OFF_W1 + (size_t)l*FFD*D, wl + OFF_W1 + (size_t)l*FFD*D,
            b1 + l*FFD, nullptr, nullptr, fh, fl, nullptr, nullptr, nullptr, nullptr,
            TOK, FFD, D, 1);
        gemm_bf<<<gDs, 256, 81920>>>(fh, fl,
            wh + OFF_W2 + (size_t)l*D*FFD, wl + OFF_W2 + (size_t)l*D*FFD,
            b2 + l*D, tp, t2, nullptr, nullptr, nullptr, nullptr, nullptr, nullptr,
            TOK, D, FFD, 0);
        add_ln_kernel<<<TOK, 128>>>(tp, t2, ln2g + l*D, ln2b + l*D, xh, xl);
    }
    add_ln_kernel<<<TOK, 128>>>(nullptr, nullptr, lnfg, lnfb, xh, xl);
    gemm_bf<<<gDs, 256, 81920>>>(xh, xl, wh + OFF_LM, wl + OFF_LM,
        nullptr, tp, t2, nullptr, nullptr, nullptr, nullptr, nullptr, nullptr,
        TOK, VOC, D, 0);
    addout_kernel<<<(TOK*VOC)/1024, 256>>>(tp, t2, out);
}

// round 17
// speedup vs baseline: 1.1277x; 1.0027x over previous
#include <cuda_runtime.h>
#include <cuda_bf16.h>
#include <cstdint>

#define D   512
#define SEQ 1024
#define BB  4
#define NH  8
#define NL  6
#define FFD 2048
#define VOC 512
#define TOK (BB*SEQ)   // 4096
#define DD  (D*D)
#define NROW (BB*NH*SEQ)   // 32768 (b,h,s) rows

// weight scratch offsets (element counts into g_wh/g_wl)
#define OFF_QKV 0
#define OFF_WO  (18*DD)
#define OFF_W1  (24*DD)
#define OFF_W2  (OFF_W1 + 6*FFD*D)
#define OFF_LM  (OFF_W2 + 6*D*FFD)
#define W_TOTAL (OFF_LM + VOC*D)
#define BC_TOTAL (NL*3*D)

// ---------------- device scratch (no allocations allowed) ----------------
__device__ float g_t[TOK*D];               // split-K / attn partial 0
__device__ float g_t2[TOK*D];              // split-K / attn partial 1
__device__ float g_pm[2*NROW], g_pl[2*NROW];  // attn partial m/l
__device__ float g_bcat[BC_TOTAL];
__device__ __nv_bfloat16 g_xh[TOK*D],  g_xl[TOK*D];    // residual hi/lo
__device__ __nv_bfloat16 g_qh[TOK*D],  g_ql[TOK*D];
__device__ __nv_bfloat16 g_kh[TOK*D],  g_kl[TOK*D];
__device__ __nv_bfloat16 g_vh[TOK*D],  g_vl[TOK*D];
__device__ __nv_bfloat16 g_oh[TOK*D],  g_ol[TOK*D];
__device__ __nv_bfloat16 g_fh[TOK*FFD], g_fl[TOK*FFD];
__device__ __nv_bfloat16 g_wh[W_TOTAL], g_wl[W_TOTAL];
__device__ int g_idmode;

// ---------------- helpers ----------------
__device__ __forceinline__ uint32_t smem_u32(const void* p) {
    uint32_t a;
    asm("{ .reg .u64 t; cvta.to.shared.u64 t, %1; cvt.u32.u64 %0, t; }"
        : "=r"(a) : "l"(p));
    return a;
}
__device__ __forceinline__ void ldsm4(uint32_t* r, uint32_t addr) {
    asm volatile("ldmatrix.sync.aligned.m8n8.x4.shared.b16 {%0,%1,%2,%3}, [%4];"
                 : "=r"(r[0]), "=r"(r[1]), "=r"(r[2]), "=r"(r[3]) : "r"(addr));
}
__device__ __forceinline__ void ldsm4t(uint32_t* r, uint32_t addr) {
    asm volatile("ldmatrix.sync.aligned.m8n8.x4.trans.shared.b16 {%0,%1,%2,%3}, [%4];"
                 : "=r"(r[0]), "=r"(r[1]), "=r"(r[2]), "=r"(r[3]) : "r"(addr));
}
__device__ __forceinline__ void mma_bf16(float* d, const uint32_t* a,
                                         const uint32_t* b) {
    asm volatile("mma.sync.aligned.m16n8k16.row.col.f32.bf16.bf16.f32 "
                 "{%0,%1,%2,%3}, {%4,%5,%6,%7}, {%8,%9}, {%0,%1,%2,%3};"
                 : "+f"(d[0]), "+f"(d[1]), "+f"(d[2]), "+f"(d[3])
                 : "r"(a[0]), "r"(a[1]), "r"(a[2]), "r"(a[3]),
                   "r"(b[0]), "r"(b[1]));
}
#define CPA(dst, src) \
    asm volatile("cp.async.ca.shared.global [%0], [%1], 16;" :: "r"(dst), "l"(src))
#define CPC()  asm volatile("cp.async.commit_group;" ::: "memory")
#define CPW0() asm volatile("cp.async.wait_group 0;" ::: "memory")

__device__ __forceinline__ uint32_t pack_hi(float a, float b) {
    return (uint32_t)__bfloat16_as_ushort(__float2bfloat16(a)) |
           ((uint32_t)__bfloat16_as_ushort(__float2bfloat16(b)) << 16);
}
__device__ __forceinline__ uint32_t pack_lo(float a, float b) {
    float ra = a - __bfloat162float(__float2bfloat16(a));
    float rb = b - __bfloat162float(__float2bfloat16(b));
    return (uint32_t)__bfloat16_as_ushort(__float2bfloat16(ra)) |
           ((uint32_t)__bfloat16_as_ushort(__float2bfloat16(rb)) << 16);
}
__device__ __forceinline__ float bf_lo16(uint32_t w) {
    return __bfloat162float(__ushort_as_bfloat16((unsigned short)(w & 0xffff)));
}
__device__ __forceinline__ float bf_hi16(uint32_t w) {
    return __bfloat162float(__ushort_as_bfloat16((unsigned short)(w >> 16)));
}
__device__ __forceinline__ float fexp(float x) {
    x = fmaxf(x, -80.0f);
    float t = x * 1.4426950408889634f;
    float fi = rintf(t);
    float f = t - fi;
    float p =              1.3333558146e-3f;
    p = fmaf(p, f, 9.6180209764e-3f);
    p = fmaf(p, f, 5.5504108664e-2f);
    p = fmaf(p, f, 2.4022650695e-1f);
    p = fmaf(p, f, 6.9314718056e-1f);
    p = fmaf(p, f, 1.0f);
    return __int_as_float(((int)fi + 127) << 23) * p;
}

// ---- fused weight conversion + qkv bias concat: one launch -------------
__global__ void conv_all(const float* __restrict__ wq, const float* __restrict__ wk,
                         const float* __restrict__ wv, const float* __restrict__ wo,
                         const float* __restrict__ w1, const float* __restrict__ w2,
                         const float* __restrict__ lmw,
                         const float* __restrict__ bq, const float* __restrict__ bk,
                         const float* __restrict__ bv)
{
    long i = ((long)blockIdx.x * 256 + threadIdx.x) * 4;
    if (i >= W_TOTAL) {                    // tail range: qkv bias concat
        long j = i - W_TOTAL;
        if (j >= BC_TOTAL) return;
        int l = (int)(j / (3 * D)), r = (int)(j % (3 * D));
        int part = r >> 9, d = r & 511;
        const float* s = part == 0 ? bq : part == 1 ? bk : bv;
        float4 v = *(const float4*)(s + l * D + d);
        *(float4*)&g_bcat[j] = v;
        return;
    }
    const float* src;
    size_t d;
    if (i < 6L*DD) {
        long j = i;  long l = j / DD, r = j - l * DD;
        src = wq + j;  d = (size_t)l * 3 * DD + r;
    } else if (i < 12L*DD) {
        long j = i - 6L*DD;  long l = j / DD, r = j - l * DD;
        src = wk + j;  d = (size_t)l * 3 * DD + DD + r;
    } else if (i < 18L*DD) {
        long j = i - 12L*DD;  long l = j / DD, r = j - l * DD;
        src = wv + j;  d = (size_t)l * 3 * DD + 2 * DD + r;
    } else if (i < 24L*DD) {
        long j = i - 18L*DD;  src = wo + j;  d = OFF_WO + j;
    } else if (i < 24L*DD + 6L*FFD*D) {
        long j = i - 24L*DD;  src = w1 + j;  d = OFF_W1 + j;
    } else if (i < 24L*DD + 12L*FFD*D) {
        long j = i - (24L*DD + 6L*FFD*D);  src = w2 + j;  d = OFF_W2 + j;
    } else {
        long j = i - (24L*DD + 12L*FFD*D);  src = lmw + j;  d = OFF_LM + j;
    }
    float4 v = *(const float4*)src;
    *(uint32_t*)&g_wh[d]     = pack_hi(v.x, v.y);
    *(uint32_t*)&g_wh[d + 2] = pack_hi(v.z, v.w);
    *(uint32_t*)&g_wl[d]     = pack_lo(v.x, v.y);
    *(uint32_t*)&g_wl[d + 2] = pack_lo(v.z, v.w);
}

__global__ void addout_kernel(const float* __restrict__ a,
                              const float* __restrict__ b,
                              float* __restrict__ o)
{
    int i = (blockIdx.x * 256 + threadIdx.x) * 4;
    float4 x = *(const float4*)&a[i];
    float4 y = *(const float4*)&b[i];
    *(float4*)&o[i] = make_float4(x.x + y.x, x.y + y.y, x.z + y.z, x.w + y.w);
}

__global__ void detect_ids_kernel(const int* __restrict__ p) {
    __shared__ int any;
    if (threadIdx.x == 0) any = 0;
    __syncthreads();
    int loc = 0;
    for (int i = threadIdx.x; i < 2048; i += blockDim.x) loc |= p[2*i + 1];
    if (loc) atomicOr(&any, 1);
    __syncthreads();
    if (threadIdx.x == 0) g_idmode = any ? 1 : 0;
}

__global__ void embed_kernel(const int* __restrict__ ids,
                             const float* __restrict__ emb) {
    int bs = blockIdx.x;
    int s  = bs & (SEQ - 1);
    int id = g_idmode ? ids[bs] : ids[2*bs];
    const float* e = emb + (size_t)id * D;
    const float c = -9.210340371976184f / 512.0f;
    const int d0 = threadIdx.x * 4;
    float v[4];
    #pragma unroll
    for (int j = 0; j < 4; j++) {
        int d = d0 + j;
        float ang = (float)s * expf(c * (float)(d & ~1));
        float pe  = (d & 1) ? cosf(ang) : sinf(ang);
        v[j] = e[d] * 22.627416997969522f + pe;
    }
    const size_t off = (size_t)bs * D + d0;
    *(uint32_t*)&g_xh[off]     = pack_hi(v[0], v[1]);
    *(uint32_t*)&g_xh[off + 2] = pack_hi(v[2], v[3]);
    *(uint32_t*)&g_xl[off]     = pack_lo(v[0], v[1]);
    *(uint32_t*)&g_xl[off + 2] = pack_lo(v[2], v[3]);
}

// =====================================================================
// bf16 tensor-core GEMM 128x128, 2-stage cp.async, optional split-K.
// MMA issue is TERM-MAJOR within each mt: accumulator reuse distance 4
// (was 1) -> hides tensor-op latency; per-d accumulation order unchanged.
// =====================================================================
__device__ __forceinline__ void load_chunk128(
    uint32_t sbuf,
    const __nv_bfloat16* __restrict__ Ah, const __nv_bfloat16* __restrict__ Al,
    const __nv_bfloat16* __restrict__ Wh, const __nv_bfloat16* __restrict__ Wl,
    int m0, int n0, int K, int kc, int tid)
{
    #pragma unroll
    for (int t = 0; t < 4; t++) {
        int s = tid + t * 256;
        int reg = s >> 9;
        int row = (s >> 2) & 127;
        int seg = s & 3;
        uint32_t dst = sbuf + reg * 10240 + row * 80 + seg * 16;
        const __nv_bfloat16* src = (reg ? Al : Ah) + (size_t)(m0 + row) * K + kc + seg * 8;
        CPA(dst, src);
    }
    #pragma unroll
    for (int t = 0; t < 4; t++) {
        int s = tid + t * 256;
        int reg = s >> 9;
        int row = (s >> 2) & 127;
        int seg = s & 3;
        uint32_t dst = sbuf + 20480 + reg * 10240 + row * 80 + seg * 16;
        const __nv_bfloat16* src = (reg ? Wl : Wh) + (size_t)(n0 + row) * K + kc + seg * 8;
        CPA(dst, src);
    }
}

__global__ void __launch_bounds__(256, 2) gemm_bf(
    const __nv_bfloat16* __restrict__ Ah, const __nv_bfloat16* __restrict__ Al,
    const __nv_bfloat16* __restrict__ Wh, const __nv_bfloat16* __restrict__ Wl,
    const float* __restrict__ bias, float* __restrict__ C,
    float* __restrict__ C2,
    __nv_bfloat16* __restrict__ Ch, __nv_bfloat16* __restrict__ Cl,
    __nv_bfloat16* __restrict__ KH, __nv_bfloat16* __restrict__ KL,
    __nv_bfloat16* __restrict__ VH, __nv_bfloat16* __restrict__ VL,
    int M, int N, int K, int relu)
{
    extern __shared__ char sm[];
    const uint32_t smb = smem_u32(sm);
    constexpr int BUFSZ = 40960;
    const int tid = threadIdx.x, wid = tid >> 5, lane = tid & 31;
    const int wm = wid >> 2;
    const int wn = wid & 3;
    const int m0 = blockIdx.y << 7;
    const int n0 = blockIdx.x << 7;
    const int zz = blockIdx.z;
    const int kslice = K / gridDim.z;
    const int kbase0 = zz * kslice;
    const int a_row = lane & 15,  a_kb = lane & 16;
    const int b_row = ((lane >> 4) << 3) + (lane & 7), b_kb = ((lane >> 3) & 1) << 4;

    float acc[4][4][4];
    #pragma unroll
    for (int i = 0; i < 4; i++)
        #pragma unroll
        for (int j = 0; j < 4; j++)
            #pragma unroll
            for (int t = 0; t < 4; t++) acc[i][j][t] = 0.0f;

    const int nch = kslice >> 5;
    load_chunk128(smb, Ah, Al, Wh, Wl, m0, n0, K, kbase0, tid);
    CPC();
    for (int c = 0; c < nch; c++) {
        CPW0();
        __syncthreads();
        if (c + 1 < nch) {
            load_chunk128(smb + ((c + 1) & 1) * BUFSZ, Ah, Al, Wh, Wl,
                          m0, n0, K, kbase0 + ((c + 1) << 5), tid);
            CPC();
        }
        const uint32_t ab = smb + (c & 1) * BUFSZ;
        const uint32_t wb = ab + 20480;
        #pragma unroll
        for (int ks = 0; ks < 2; ks++) {
            const int kbyte = ks * 32;
            uint32_t Bh[2][4], Bl[2][4];
            #pragma unroll
            for (int ng = 0; ng < 2; ng++) {
                const uint32_t roff = (wn*32 + ng*16 + b_row) * 80 + kbyte + b_kb;
                ldsm4(Bh[ng], wb + roff);
                ldsm4(Bl[ng], wb + 10240 + roff);
            }
            #pragma unroll
            for (int mt = 0; mt < 4; mt++) {
                uint32_t Af[4], Alf[4];
                const uint32_t aoff = (wm*64 + mt*16 + a_row) * 80 + kbyte + a_kb;
                ldsm4(Af,  ab + aoff);
                ldsm4(Alf, ab + 10240 + aoff);
                // term-major issue: reuse distance per accumulator = 4
                #pragma unroll
                for (int ng = 0; ng < 2; ng++)
                    #pragma unroll
                    for (int hf = 0; hf < 2; hf++)
                        mma_bf16(acc[mt][ng*2 + hf], Af,  Bh[ng] + hf*2);
                #pragma unroll
                for (int ng = 0; ng < 2; ng++)
                    #pragma unroll
                    for (int hf = 0; hf < 2; hf++)
                        mma_bf16(acc[mt][ng*2 + hf], Alf, Bh[ng] + hf*2);
                #pragma unroll
                for (int ng = 0; ng < 2; ng++)
                    #pragma unroll
                    for (int hf = 0; hf < 2; hf++)
                        mma_bf16(acc[mt][ng*2 + hf], Af,  Bl[ng] + hf*2);
            }
        }
        __syncthreads();
    }

    __nv_bfloat16 *oh_ = Ch, *ol_ = Cl;
    float* Cout = (zz == 0) ? C : C2;
    const float* bia = (zz == 0) ? bias : nullptr;
    int nst = N, nbase = n0;
    if (KH) {
        const int part = n0 >> 9;
        if (part == 1)      { oh_ = KH; ol_ = KL; }
        else if (part == 2) { oh_ = VH; ol_ = VL; }
        nbase = n0 & 511;
        nst = 512;
    }
    const int g = lane >> 2, tg = lane & 3;
    #pragma unroll
    for (int mt = 0; mt < 4; mt++) {
        #pragma unroll
        for (int nt = 0; nt < 4; nt++) {
            const int row  = m0 + wm*64 + mt*16 + g;
            const int colb = n0 + wn*32 + nt*8 + tg*2;
            const int cols = nbase + wn*32 + nt*8 + tg*2;
            float b0 = bia ? bia[colb]     : 0.0f;
            float b1 = bia ? bia[colb + 1] : 0.0f;
            float v0 = acc[mt][nt][0] + b0, v1 = acc[mt][nt][1] + b1;
            float v2 = acc[mt][nt][2] + b0, v3 = acc[mt][nt][3] + b1;
            if (relu) {
                v0 = fmaxf(v0, 0.f); v1 = fmaxf(v1, 0.f);
                v2 = fmaxf(v2, 0.f); v3 = fmaxf(v3, 0.f);
            }
            const size_t o0 = (size_t)row * nst + cols;
            const size_t o1 = (size_t)(row + 8) * nst + cols;
            if (Cout) {
                *(float2*)&Cout[o0] = make_float2(v0, v1);
                *(float2*)&Cout[o1] = make_float2(v2, v3);
            }
            if (oh_) {
                *(uint32_t*)&oh_[o0] = pack_hi(v0, v1);
                *(uint32_t*)&oh_[o1] = pack_hi(v2, v3);
                *(uint32_t*)&ol_[o0] = pack_lo(v0, v1);
                *(uint32_t*)&ol_[o1] = pack_lo(v2, v3);
            }
        }
    }
}

// =====================================================================
// Split-KV tensor-core flash attention (causal). blockIdx.z halves the
// k-range. Writes UN-normalized fp32 O partial + per-row (m,l).
// MMA inner loops term-major (reuse distance 2).
// =====================================================================
#define KVB(i) ((i) * 36864)
#define AAM    73728
#define ASME   (AAM + 512)

__global__ void __launch_bounds__(256) attn_split(
    const __nv_bfloat16* __restrict__ Qh, const __nv_bfloat16* __restrict__ Ql,
    const __nv_bfloat16* __restrict__ Kh, const __nv_bfloat16* __restrict__ Kl,
    const __nv_bfloat16* __restrict__ Vh, const __nv_bfloat16* __restrict__ Vl,
    const int* __restrict__ amask,
    float* __restrict__ Op0, float* __restrict__ Op1,
    float* __restrict__ pmA, float* __restrict__ plA)
{
    extern __shared__ char sm[];
    const uint32_t smb = smem_u32(sm);
    int* am_s = (int*)(sm + AAM);
    const int qt = blockIdx.x, bh = blockIdx.y, zz = blockIdx.z;
    const int b = bh >> 3, h = bh & 7;
    const int tid = threadIdx.x, wid = tid >> 5, lane = tid & 31;
    const int g = lane >> 2, tg = lane & 3;
    const size_t base = (size_t)b * SEQ * D + h * 64;
    const int q0 = qt * 128;
    const int nkt = qt + 1;
    const int kstart = zz * nkt;
    float* Op = zz ? Op1 : Op0;
    float* pm = pmA + zz * NROW;
    float* pl = plA + zz * NROW;
    const int a_row = lane & 15, a_kb = lane & 16;
    const int b_row = ((lane >> 4) << 3) + (lane & 7), b_kb = ((lane >> 3) & 1) << 4;
    const int v_row = (((lane >> 3) & 1) << 3) + (lane & 7), v_byte = (lane >> 4) << 4;

    #pragma unroll
    for (int t = 0; t < 8; t++) {
        int s = tid + t * 256;
        int reg = s >> 10, row = (s >> 3) & 127, seg = s & 7;
        uint32_t dst = smb + KVB(1) + reg * 18432 + row * 144 + seg * 16;
        const __nv_bfloat16* src = (reg ? Ql : Qh) + base + (size_t)(q0 + row) * D + seg * 8;
        CPA(dst, src);
    }
    CPC(); CPW0();
    __syncthreads();
    uint32_t qhf[4][4], qlf[4][4];
    #pragma unroll
    for (int ks = 0; ks < 4; ks++) {
        const uint32_t off = (wid*16 + a_row) * 144 + ks*32 + a_kb;
        ldsm4(qhf[ks], smb + KVB(1) + off);
        ldsm4(qlf[ks], smb + KVB(1) + 18432 + off);
    }

    float m_i[2] = {-1e30f, -1e30f}, l_i[2] = {0.f, 0.f};
    float o_acc[8][4];
    #pragma unroll
    for (int i = 0; i < 8; i++)
        #pragma unroll
        for (int j = 0; j < 4; j++) o_acc[i][j] = 0.f;

    const int row0 = q0 + wid*16 + g;

    {
        const uint32_t kv = smb + KVB(0);
        const size_t kb = base + (size_t)(kstart * 64) * D;
        #pragma unroll
        for (int t = 0; t < 4; t++) {
            int s = tid + t * 256;
            int reg = s >> 9, row = (s >> 3) & 63, seg = s & 7;
            CPA(kv + reg * 9216 + row * 144 + seg * 16,
                (reg ? Kl : Kh) + kb + (size_t)row * D + seg * 8);
        }
        #pragma unroll
        for (int t = 0; t < 4; t++) {
            int s = tid + t * 256;
            int reg = s >> 9, row = (s >> 3) & 63, seg = s & 7;
            CPA(kv + 18432 + reg * 9216 + row * 144 + seg * 16,
                (reg ? Vl : Vh) + kb + (size_t)row * D + seg * 8);
        }
        if (tid < 64) am_s[tid] = amask[b * SEQ + kstart * 64 + tid];
        CPC();
    }

    for (int j = 0; j < nkt; j++) {
        const int kt = kstart + j;
        CPW0();
        __syncthreads();
        if (j + 1 < nkt) {
            const uint32_t kv = smb + KVB((j + 1) & 1);
            const size_t kb = base + (size_t)((kt + 1) * 64) * D;
            #pragma unroll
            for (int t = 0; t < 4; t++) {
                int s = tid + t * 256;
                int reg = s >> 9, row = (s >> 3) & 63, seg = s & 7;
                CPA(kv + reg * 9216 + row * 144 + seg * 16,
                    (reg ? Kl : Kh) + kb + (size_t)row * D + seg * 8);
            }
            #pragma unroll
            for (int t = 0; t < 4; t++) {
                int s = tid + t * 256;
                int reg = s >> 9, row = (s >> 3) & 63, seg = s & 7;
                CPA(kv + 18432 + reg * 9216 + row * 144 + seg * 16,
                    (reg ? Vl : Vh) + kb + (size_t)row * D + seg * 8);
            }
            if (tid < 64) am_s[((j + 1) & 1) * 64 + tid] = amask[b * SEQ + (kt + 1) * 64 + tid];
            CPC();
        }
        const uint32_t kbuf = smb + KVB(j & 1);
        const uint32_t vbuf = kbuf + 18432;
        const int* am = am_s + (j & 1) * 64;

        float sc[8][4];
        #pragma unroll
        for (int i = 0; i < 8; i++)
            #pragma unroll
            for (int jj = 0; jj < 4; jj++) sc[i][jj] = 0.f;
        #pragma unroll
        for (int ks = 0; ks < 4; ks++) {
            #pragma unroll
            for (int ng = 0; ng < 4; ng++) {
                uint32_t Bh[4], Bl[4];
                const uint32_t roff = (ng*16 + b_row) * 144 + ks*32 + b_kb;
                ldsm4(Bh, kbuf + roff);
                ldsm4(Bl, kbuf + 9216 + roff);
                // term-major: reuse distance 2
                #pragma unroll
                for (int hf = 0; hf < 2; hf++)
                    mma_bf16(sc[ng*2 + hf], qhf[ks], Bh + hf*2);
                #pragma unroll
                for (int hf = 0; hf < 2; hf++)
                    mma_bf16(sc[ng*2 + hf], qlf[ks], Bh + hf*2);
                #pragma unroll
                for (int hf = 0; hf < 2; hf++)
                    mma_bf16(sc[ng*2 + hf], qhf[ks], Bl + hf*2);
            }
        }
        float mx0 = -1e30f, mx1 = -1e30f;
        #pragma unroll
        for (int nt = 0; nt < 8; nt++) {
            const int c0 = nt*8 + tg*2, c1 = c0 + 1;
            const int col0 = kt*64 + c0, col1 = col0 + 1;
            const int ok0 = am[c0], ok1 = am[c1];
            float s0 = sc[nt][0] * 0.125f, s1 = sc[nt][1] * 0.125f;
            float s2 = sc[nt][2] * 0.125f, s3 = sc[nt][3] * 0.125f;
            if (col0 > row0     || !ok0) s0 = -1e9f;
            if (col1 > row0     || !ok1) s1 = -1e9f;
            if (col0 > row0 + 8 || !ok0) s2 = -1e9f;
            if (col1 > row0 + 8 || !ok1) s3 = -1e9f;
            sc[nt][0] = s0; sc[nt][1] = s1; sc[nt][2] = s2; sc[nt][3] = s3;
            mx0 = fmaxf(mx0, fmaxf(s0, s1));
            mx1 = fmaxf(mx1, fmaxf(s2, s3));
        }
        mx0 = fmaxf(mx0, __shfl_xor_sync(0xffffffffu, mx0, 1));
        mx0 = fmaxf(mx0, __shfl_xor_sync(0xffffffffu, mx0, 2));
        mx1 = fmaxf(mx1, __shfl_xor_sync(0xffffffffu, mx1, 1));
        mx1 = fmaxf(mx1, __shfl_xor_sync(0xffffffffu, mx1, 2));
        const float mn0 = fmaxf(m_i[0], mx0), mn1 = fmaxf(m_i[1], mx1);
        const float al0 = fexp(m_i[0] - mn0), al1 = fexp(m_i[1] - mn1);
        float rs0 = 0.f, rs1 = 0.f;
        #pragma unroll
        for (int nt = 0; nt < 8; nt++) {
            float p0 = fexp(sc[nt][0] - mn0), p1 = fexp(sc[nt][1] - mn0);
            float p2 = fexp(sc[nt][2] - mn1), p3 = fexp(sc[nt][3] - mn1);
            sc[nt][0] = p0; sc[nt][1] = p1; sc[nt][2] = p2; sc[nt][3] = p3;
            rs0 += p0 + p1; rs1 += p2 + p3;
        }
        rs0 += __shfl_xor_sync(0xffffffffu, rs0, 1);
        rs0 += __shfl_xor_sync(0xffffffffu, rs0, 2);
        rs1 += __shfl_xor_sync(0xffffffffu, rs1, 1);
        rs1 += __shfl_xor_sync(0xffffffffu, rs1, 2);
        l_i[0] = l_i[0] * al0 + rs0;  m_i[0] = mn0;
        l_i[1] = l_i[1] * al1 + rs1;  m_i[1] = mn1;
        #pragma unroll
        for (int dt = 0; dt < 8; dt++) {
            o_acc[dt][0] *= al0; o_acc[dt][1] *= al0;
            o_acc[dt][2] *= al1; o_acc[dt][3] *= al1;
        }
        #pragma unroll
        for (int ks = 0; ks < 4; ks++) {
            uint32_t ph[4], pl_[4];
            const int n0t = 2*ks, n1t = 2*ks + 1;
            ph[0] = pack_hi(sc[n0t][0], sc[n0t][1]); ph[1] = pack_hi(sc[n0t][2], sc[n0t][3]);
            ph[2] = pack_hi(sc[n1t][0], sc[n1t][1]); ph[3] = pack_hi(sc[n1t][2], sc[n1t][3]);
            pl_[0] = pack_lo(sc[n0t][0], sc[n0t][1]); pl_[1] = pack_lo(sc[n0t][2], sc[n0t][3]);
            pl_[2] = pack_lo(sc[n1t][0], sc[n1t][1]); pl_[3] = pack_lo(sc[n1t][2], sc[n1t][3]);
            #pragma unroll
            for (int dg = 0; dg < 4; dg++) {
                uint32_t Vhf[4], Vlf[4];
                const uint32_t voff = (ks*16 + v_row) * 144 + dg*32 + v_byte;
                ldsm4t(Vhf, vbuf + voff);
                ldsm4t(Vlf, vbuf + 9216 + voff);
                // term-major: reuse distance 2
                #pragma unroll
                for (int hf = 0; hf < 2; hf++)
                    mma_bf16(o_acc[dg*2 + hf], ph,  Vhf + hf*2);
                #pragma unroll
                for (int hf = 0; hf < 2; hf++)
                    mma_bf16(o_acc[dg*2 + hf], pl_, Vhf + hf*2);
                #pragma unroll
                for (int hf = 0; hf < 2; hf++)
                    mma_bf16(o_acc[dg*2 + hf], ph,  Vlf + hf*2);
            }
        }
    }
    #pragma unroll
    for (int dt = 0; dt < 8; dt++) {
        const int col = dt*8 + tg*2;
        const size_t o0 = base + (size_t)row0 * D + col;
        const size_t o1 = base + (size_t)(row0 + 8) * D + col;
        *(float2*)&Op[o0] = make_float2(o_acc[dt][0], o_acc[dt][1]);
        *(float2*)&Op[o1] = make_float2(o_acc[dt][2], o_acc[dt][3]);
    }
    if (tg == 0) {
        pm[bh * SEQ + row0]     = m_i[0];
        pl[bh * SEQ + row0]     = l_i[0];
        pm[bh * SEQ + row0 + 8] = m_i[1];
        pl[bh * SEQ + row0 + 8] = l_i[1];
    }
}

__global__ void attn_combine(const float* __restrict__ O0, const float* __restrict__ O1,
                             const float* __restrict__ pm, const float* __restrict__ pl,
                             __nv_bfloat16* __restrict__ Oh, __nv_bfloat16* __restrict__ Ol)
{
    const int t = threadIdx.x;
    const int ridx = blockIdx.x * 8 + (t >> 5);
    const int cp = (t & 31) * 2;
    const int bh = ridx >> 10, qr = ridx & 1023;
    const int b = bh >> 3, h = bh & 7;
    const size_t off = (size_t)b*SEQ*D + h*64 + (size_t)qr*D + cp;
    float m0 = pm[ridx], m1 = pm[NROW + ridx];
    float l0 = pl[ridx], l1 = pl[NROW + ridx];
    float M = fmaxf(m0, m1);
    float w0 = fexp(m0 - M), w1 = fexp(m1 - M);
    float L = 1.0f / (l0*w0 + l1*w1);
    float2 a = *(const float2*)&O0[off];
    float2 c = *(const float2*)&O1[off];
    float v0 = (w0*a.x + w1*c.x) * L;
    float v1 = (w0*a.y + w1*c.y) * L;
    *(uint32_t*)&Oh[off] = pack_hi(v0, v1);
    *(uint32_t*)&Ol[off] = pack_lo(v0, v1);
}

// -------- fused (residual add + split-K partial add +) LayerNorm --------
__global__ void add_ln_kernel(const float* __restrict__ R,
                              const float* __restrict__ R2,
                              const float* __restrict__ g, const float* __restrict__ b,
                              __nv_bfloat16* __restrict__ Xh,
                              __nv_bfloat16* __restrict__ Xl)
{
    const int row = blockIdx.x;
    __shared__ float sh[4];
    const int c = threadIdx.x * 4;
    const size_t off = (size_t)row*D + c;
    uint32_t h01 = *(uint32_t*)&Xh[off], h23 = *(uint32_t*)&Xh[off + 2];
    uint32_t l01 = *(uint32_t*)&Xl[off], l23 = *(uint32_t*)&Xl[off + 2];
    float4 v;
    v.x = bf_lo16(h01) + bf_lo16(l01);
    v.y = bf_hi16(h01) + bf_hi16(l01);
    v.z = bf_lo16(h23) + bf_lo16(l23);
    v.w = bf_hi16(h23) + bf_hi16(l23);
    if (R) {
        float4 r = *(const float4*)&R[off];
        v.x += r.x; v.y += r.y; v.z += r.z; v.w += r.w;
    }
    if (R2) {
        float4 r = *(const float4*)&R2[off];
        v.x += r.x; v.y += r.y; v.z += r.z; v.w += r.w;
    }
    float s = v.x + v.y + v.z + v.w;
    #pragma unroll
    for (int o = 16; o; o >>= 1) s += __shfl_xor_sync(0xffffffffu, s, o);
    if ((threadIdx.x & 31) == 0) sh[threadIdx.x >> 5] = s;
    __syncthreads();
    float mu = (sh[0] + sh[1] + sh[2] + sh[3]) * (1.0f / D);
    float dx = v.x - mu, dy = v.y - mu, dz = v.z - mu, dw = v.w - mu;
    float sq = dx*dx + dy*dy + dz*dz + dw*dw;
    #pragma unroll
    for (int o = 16; o; o >>= 1) sq += __shfl_xor_sync(0xffffffffu, sq, o);
    __syncthreads();
    if ((threadIdx.x & 31) == 0) sh[threadIdx.x >> 5] = sq;
    __syncthreads();
    float var = (sh[0] + sh[1] + sh[2] + sh[3]) * (1.0f / D);
    float inv = rsqrtf(var + 1e-5f);
    float4 gg = *(const float4*)&g[c];
    float4 bb = *(const float4*)&b[c];
    float o0 = dx*inv*gg.x + bb.x, o1 = dy*inv*gg.y + bb.y;
    float o2 = dz*inv*gg.z + bb.z, o3 = dw*inv*gg.w + bb.w;
    *(uint32_t*)&Xh[off]     = pack_hi(o0, o1);
    *(uint32_t*)&Xh[off + 2] = pack_hi(o2, o3);
    *(uint32_t*)&Xl[off]     = pack_lo(o0, o1);
    *(uint32_t*)&Xl[off + 2] = pack_lo(o2, o3);
}

// ---------------- host orchestration ----------------
extern "C" void kernel_launch(void* const* d_in, const int* in_sizes, int n_in,
                              void* d_out, int out_size)
{
    const int*   ids  = (const int*)  d_in[0];
    const int*   am   = (const int*)  d_in[1];
    const float* emb  = (const float*)d_in[2];
    const float* wq   = (const float*)d_in[3];  const float* bq = (const float*)d_in[4];
    const float* wk   = (const float*)d_in[5];  const float* bk = (const float*)d_in[6];
    const float* wv   = (const float*)d_in[7];  const float* bv = (const float*)d_in[8];
    const float* wo   = (const float*)d_in[9];  const float* bo = (const float*)d_in[10];
    const float* ln1g = (const float*)d_in[11]; const float* ln1b = (const float*)d_in[12];
    const float* w1   = (const float*)d_in[13]; const float* b1 = (const float*)d_in[14];
    const float* w2   = (const float*)d_in[15]; const float* b2 = (const float*)d_in[16];
    const float* ln2g = (const float*)d_in[17]; const float* ln2b = (const float*)d_in[18];
    const float* lnfg = (const float*)d_in[19]; const float* lnfb = (const float*)d_in[20];
    const float* lmw  = (const float*)d_in[21];
    float* out = (float*)d_out;

    static float *tp = nullptr, *t2, *pmp, *plp, *bcat;
    static __nv_bfloat16 *xh, *xl, *qh, *ql, *kh, *kl, *vh, *vl, *oh, *ol, *fh, *fl, *wh, *wl;
    if (!tp) {
        cudaGetSymbolAddress((void**)&tp, g_t);
        cudaGetSymbolAddress((void**)&t2, g_t2);
        cudaGetSymbolAddress((void**)&pmp, g_pm);
        cudaGetSymbolAddress((void**)&plp, g_pl);
        cudaGetSymbolAddress((void**)&bcat, g_bcat);
        cudaGetSymbolAddress((void**)&xh, g_xh);
        cudaGetSymbolAddress((void**)&xl, g_xl);
        cudaGetSymbolAddress((void**)&qh, g_qh);
        cudaGetSymbolAddress((void**)&ql, g_ql);
        cudaGetSymbolAddress((void**)&kh, g_kh);
        cudaGetSymbolAddress((void**)&kl, g_kl);
        cudaGetSymbolAddress((void**)&vh, g_vh);
        cudaGetSymbolAddress((void**)&vl, g_vl);
        cudaGetSymbolAddress((void**)&oh, g_oh);
        cudaGetSymbolAddress((void**)&ol, g_ol);
        cudaGetSymbolAddress((void**)&fh, g_fh);
        cudaGetSymbolAddress((void**)&fl, g_fl);
        cudaGetSymbolAddress((void**)&wh, g_wh);
        cudaGetSymbolAddress((void**)&wl, g_wl);
        cudaFuncSetAttribute(attn_split, cudaFuncAttributeMaxDynamicSharedMemorySize, ASME);
        cudaFuncSetAttribute(gemm_bf, cudaFuncAttributeMaxDynamicSharedMemorySize, 81920);
    }

    conv_all<<<(W_TOTAL + BC_TOTAL)/1024, 256>>>(wq, wk, wv, wo, w1, w2, lmw, bq, bk, bv);
    detect_ids_kernel<<<1, 256>>>(ids);
    embed_kernel<<<TOK, 128>>>(ids, emb);

    const dim3 gQKV(1536/128, TOK/128);    // (12, 32)
    const dim3 gDs(D/128, TOK/128, 2);     // (4, 32, 2) split-K
    const dim3 gF(FFD/128, TOK/128);       // (16, 32)
    const dim3 gAT(SEQ/128, BB*NH, 2);     // (8, 32, 2) split-KV attention
    for (int l = 0; l < NL; l++) {
        gemm_bf<<<gQKV, 256, 81920>>>(xh, xl,
            wh + OFF_QKV + (size_t)l*3*DD, wl + OFF_QKV + (size_t)l*3*DD,
            bcat + l*1536, nullptr, nullptr, qh, ql, kh, kl, vh, vl, TOK, 1536, D, 0);
        attn_split<<<gAT, 256, ASME>>>(qh, ql, kh, kl, vh, vl, am, tp, t2, pmp, plp);
        attn_combine<<<NROW/8, 256>>>(tp, t2, pmp, plp, oh, ol);
        gemm_bf<<<gDs, 256, 81920>>>(oh, ol,
            wh + OFF_WO + (size_t)l*DD, wl + OFF_WO + (size_t)l*DD,
            bo + l*D, tp, t2, nullptr, nullptr, nullptr, nullptr, nullptr, nullptr,
            TOK, D, D, 0);
        add_ln_kernel<<<TOK, 128>>>(tp, t2, ln1g + l*D, ln1b + l*D, xh, xl);
        gemm_bf<<<gF, 256, 81920>>>(xh, xl,
            wh + OFF_W1 + (size_t)l*FFD*D, wl + OFF_W1 + (size_t)l*FFD*D,
            b1 + l*FFD, nullptr, nullptr, fh, fl, nullptr, nullptr, nullptr, nullptr,
            TOK, FFD, D, 1);
        gemm_bf<<<gDs, 256, 81920>>>(fh, fl,
            wh + OFF_W2 + (size_t)l*D*FFD, wl + OFF_W2 + (size_t)l*D*FFD,
            b2 + l*D, tp, t2, nullptr, nullptr, nullptr, nullptr, nullptr, nullptr,
            TOK, D, FFD, 0);
        add_ln_kernel<<<TOK, 128>>>(tp, t2, ln2g + l*D, ln2b + l*D, xh, xl);
    }
    add_ln_kernel<<<TOK, 128>>>(nullptr, nullptr, lnfg, lnfb, xh, xl);
    gemm_bf<<<gDs, 256, 81920>>>(xh, xl, wh + OFF_LM, wl + OFF_LM,
        nullptr, tp, t2, nullptr, nullptr, nullptr, nullptr, nullptr, nullptr,
        TOK, VOC, D, 0);
    addout_kernel<<<(TOK*VOC)/1024, 256>>>(tp, t2, out);
}